// round 3
// baseline (speedup 1.0000x reference)
#include <cuda_runtime.h>
#include <cstdint>

// ---------------------------------------------------------------------------
// Problem constants (fixed shapes: x [8,16,512,512] f32)
// ---------------------------------------------------------------------------
#define HH 512
#define WW 512
#define NU 257          // rfft width = W/2+1
#define SU 260          // padded u-stride (float2)
#define NCH 16
#define NBATCH 8
#define IMGS (NBATCH*NCH)   // 128
#define GSTR 578            // per-FFT-group smem stride (float2); 578 % 16 == 2

// Scratch spectra: [img][h][u] as float2, padded stride SU.
__device__ float2 g_X[(size_t)IMGS * HH * SU];
__device__ float2 g_Y[(size_t)IMGS * HH * SU];

__device__ __forceinline__ float2 cmul(float2 a, float2 b) {
    return make_float2(a.x*b.x - a.y*b.y, a.x*b.y + a.y*b.x);
}
__device__ __forceinline__ float2 cadd(float2 a, float2 b) { return make_float2(a.x+b.x, a.y+b.y); }
__device__ __forceinline__ float2 csub(float2 a, float2 b) { return make_float2(a.x-b.x, a.y-b.y); }

// ---------------------------------------------------------------------------
// Radix-8 butterfly in registers. S = -1 forward, +1 inverse.
// Computes y[k] = sum_j a[j] * exp(S*2*pi*i*j*k/8), output in natural order.
// ---------------------------------------------------------------------------
template<int S>
__device__ __forceinline__ void fft8(float2 a[8]) {
    const float r = 0.7071067811865476f;
    const float sf = (float)S;
    float2 d, u;
    // stage 1: (j, j+4), twiddle W8^j on the difference
    u=a[0]; d=csub(u,a[4]); a[0]=cadd(u,a[4]); a[4]=d;
    u=a[1]; d=csub(u,a[5]); a[1]=cadd(u,a[5]); a[5]=make_float2(r*(d.x - sf*d.y), r*(sf*d.x + d.y));
    u=a[2]; d=csub(u,a[6]); a[2]=cadd(u,a[6]); a[6]=make_float2(-sf*d.y, sf*d.x);
    u=a[3]; d=csub(u,a[7]); a[3]=cadd(u,a[7]); a[7]=make_float2(r*(-d.x - sf*d.y), r*(sf*d.x - d.y));
    // stage 2: (j, j+2) within each 4-group, twiddle W4^1 = (0, S)
    u=a[0]; d=csub(u,a[2]); a[0]=cadd(u,a[2]); a[2]=d;
    u=a[1]; d=csub(u,a[3]); a[1]=cadd(u,a[3]); a[3]=make_float2(-sf*d.y, sf*d.x);
    u=a[4]; d=csub(u,a[6]); a[4]=cadd(u,a[6]); a[6]=d;
    u=a[5]; d=csub(u,a[7]); a[5]=cadd(u,a[7]); a[7]=make_float2(-sf*d.y, sf*d.x);
    // stage 3: adjacent pairs, no twiddle
    u=a[0]; a[0]=cadd(u,a[1]); a[1]=csub(u,a[1]);
    u=a[2]; a[2]=cadd(u,a[3]); a[3]=csub(u,a[3]);
    u=a[4]; a[4]=cadd(u,a[5]); a[5]=csub(u,a[5]);
    u=a[6]; a[6]=cadd(u,a[7]); a[7]=csub(u,a[7]);
    // bit-reverse rename to natural order: swap 1<->4, 3<->6
    d=a[1]; a[1]=a[4]; a[4]=d;
    d=a[3]; a[3]=a[6]; a[6]=d;
}

// ---------------------------------------------------------------------------
// 512-pt FFT: 64 threads (t in [0,64)), 8 float2 regs per thread.
// Input:  a[m] = x[t + 64*m]
// Output: a[m] = X[t + 64*m]
// s: per-group shared buffer, >= 576 float2. 3 block-wide __syncthreads inside
// (every thread of the block must call this with identical control flow).
// ---------------------------------------------------------------------------
template<int S>
__device__ __forceinline__ void fft512_regs(float2 a[8], int t, float2* s) {
    const float TWO_PI = 6.283185307179586f;
    const int n2 = t & 7;
    const int n1 = t >> 3;

    fft8<S>(a);  // regs now indexed by k0
    // twiddle W_64^{n1*k0}
    const float c1 = (float)S * TWO_PI / 64.0f * (float)n1;
    #pragma unroll
    for (int k0 = 1; k0 < 8; ++k0) {
        float sn, cs; __sincosf(c1 * (float)k0, &sn, &cs);
        a[k0] = cmul(a[k0], make_float2(cs, sn));
    }
    // exchange 1: write [ (n2+8*n1) + 72*k0 ], read regs over n1
    #pragma unroll
    for (int k0 = 0; k0 < 8; ++k0) s[t + 72*k0] = a[k0];
    __syncthreads();
    const int k0r = t >> 3;   // new role: (n2, k0)
    #pragma unroll
    for (int j = 0; j < 8; ++j) a[j] = s[n2 + 8*j + 72*k0r];
    __syncthreads();          // buffer reuse barrier

    fft8<S>(a);  // regs now indexed by k1
    // twiddle W_512^{n2*(k0 + 8*k1)}
    const float c2 = (float)S * TWO_PI / 512.0f * (float)n2;
    #pragma unroll
    for (int k1 = 0; k1 < 8; ++k1) {
        float sn, cs; __sincosf(c2 * (float)(k0r + 8*k1), &sn, &cs);
        a[k1] = cmul(a[k1], make_float2(cs, sn));
    }
    // exchange 2: XOR-swizzled [ 72*k1 + 8*k0 + (n2^k0) ]
    #pragma unroll
    for (int k1 = 0; k1 < 8; ++k1) s[72*k1 + 8*k0r + (n2 ^ k0r)] = a[k1];
    __syncthreads();
    const int k0b = t & 7, k1r = t >> 3;  // new role: (k0, k1), tid = k0 + 8*k1
    #pragma unroll
    for (int j = 0; j < 8; ++j) a[j] = s[72*k1r + 8*k0b + (j ^ k0b)];

    fft8<S>(a);  // regs now indexed by k2 ; X[t + 64*k2] = a[k2]
}

// ---------------------------------------------------------------------------
// Kernel A: row rfft. 512 threads = 8 FFT groups = 16 rows per block.
// Two real rows packed into one complex 512-pt FFT, then Hermitian unpack.
// grid = 128 imgs * 32 = 4096 blocks.
// ---------------------------------------------------------------------------
__global__ __launch_bounds__(512) void kA_rfft_rows(const float* __restrict__ x) {
    __shared__ float2 s[8 * GSTR];
    const int t = threadIdx.x & 63;
    const int g = threadIdx.x >> 6;
    const int img = blockIdx.x >> 5;
    const int seg = blockIdx.x & 31;
    const int pr = seg * 8 + g;           // row-pair 0..255

    const float* r0 = x + ((size_t)img * HH + 2 * pr) * WW;
    const float* r1 = r0 + WW;

    float2 a[8];
    #pragma unroll
    for (int m = 0; m < 8; ++m)
        a[m] = make_float2(r0[t + 64*m], r1[t + 64*m]);

    float2* z = s + g * GSTR;
    fft512_regs<-1>(a, t, z);

    __syncthreads();                       // exchange reads done everywhere
    #pragma unroll
    for (int m = 0; m < 8; ++m) z[t + 64*m] = a[m];
    __syncthreads();

    float2* X0 = g_X + ((size_t)img * HH + 2 * pr) * SU;
    float2* X1 = X0 + SU;
    #pragma unroll
    for (int m = 0; m < 5; ++m) {
        const int u = t + 64*m;
        if (u < NU) {
            const float2 zk = z[u];
            const float2 zm = z[(512 - u) & 511];
            X0[u] = make_float2(0.5f*(zk.x + zm.x),  0.5f*(zk.y - zm.y));
            X1[u] = make_float2(0.5f*(zk.y + zm.y), -0.5f*(zk.x - zm.x));
        }
    }
}

// ---------------------------------------------------------------------------
// Kernel B/D: column FFT along h. 512 threads = 8 u-columns per block
// (u is the FAST thread index for coalescing). grid = (33, 128).
// ---------------------------------------------------------------------------
template<int S>
__global__ __launch_bounds__(512) void kBD_fft_cols(int useY, float scale) {
    __shared__ float2 s[8 * GSTR];
    const int g = threadIdx.x & 7;        // u offset within block
    const int t = threadIdx.x >> 3;       // position in FFT (0..63)
    const int img = blockIdx.y;
    const int u = blockIdx.x * 8 + g;
    const bool ok = (u < NU);

    float2* data = useY ? g_Y : g_X;
    float2* base = data + (size_t)img * HH * SU + u;

    float2 a[8];
    #pragma unroll
    for (int m = 0; m < 8; ++m)
        a[m] = ok ? base[(size_t)(t + 64*m) * SU] : make_float2(0.f, 0.f);

    fft512_regs<S>(a, t, s + g * GSTR);

    if (ok) {
        #pragma unroll
        for (int m = 0; m < 8; ++m)
            base[(size_t)(t + 64*m) * SU] = make_float2(a[m].x * scale, a[m].y * scale);
    }
}

// ---------------------------------------------------------------------------
// Kernel C: 3x3 complex conv with 16->16 channel mixing on the spectrum.
// Y[n,o,h,u] = sum_{i,a,b} w[i,o,a,b] * X[n,i,h+1-a,u+1-b] + bias (zero pad).
// ---------------------------------------------------------------------------
#define TH 16
#define TU 32
#define SXW 35
#define SX_ELEMS (NCH * (TH + 2) * SXW)
#define W_ELEMS (NCH * NCH * 9)

__global__ __launch_bounds__(256, 2) void kC_conv(
    const float* __restrict__ w_real, const float* __restrict__ w_imag,
    const float* __restrict__ b_real, const float* __restrict__ b_imag)
{
    extern __shared__ float smemC[];
    float2* sX  = (float2*)smemC;
    float*  swr = (float*)(sX + SX_ELEMS);
    float*  swi = swr + W_ELEMS;

    const int t = threadIdx.x;
    const int u0 = blockIdx.x * TU;
    const int h0 = blockIdx.y * TH;
    const int n  = blockIdx.z;

    for (int idx = t; idx < W_ELEMS; idx += 256) {
        const int i = idx / 144;
        const int q = idx - i * 144;
        const int tap = q >> 4;
        const int o = q & 15;
        const int src = (i * 16 + o) * 9 + tap;
        swr[idx] = w_real[src];
        swi[idx] = w_imag[src];
    }

    for (int e = t; e < NCH * (TH + 2) * (TU + 2); e += 256) {
        const int i = e / ((TH + 2) * (TU + 2));
        const int q = e - i * ((TH + 2) * (TU + 2));
        const int rr = q / (TU + 2);
        const int cc = q - rr * (TU + 2);
        const int gh = h0 - 1 + rr;
        const int gu = u0 - 1 + cc;
        float2 v = make_float2(0.f, 0.f);
        if (gh >= 0 && gh < HH && gu >= 0 && gu < NU)
            v = g_X[(((size_t)n * NCH + i) * HH + gh) * SU + gu];
        sX[(i * (TH + 2) + rr) * SXW + cc] = v;
    }
    __syncthreads();

    const int oh = t >> 7;
    const int ps = t & 127;
    const int lh0 = ps >> 5;
    const int lu  = ps & 31;

    float accr[4][8], acci[4][8];
    #pragma unroll
    for (int r = 0; r < 4; ++r)
        #pragma unroll
        for (int o = 0; o < 8; ++o) { accr[r][o] = 0.f; acci[r][o] = 0.f; }

    for (int i = 0; i < NCH; ++i) {
        #pragma unroll
        for (int a = 0; a < 3; ++a) {
            #pragma unroll
            for (int b = 0; b < 3; ++b) {
                float2 xv[4];
                #pragma unroll
                for (int r = 0; r < 4; ++r)
                    xv[r] = sX[(i * (TH + 2) + (lh0 + 4 * r + 2 - a)) * SXW + (lu + 2 - b)];
                const int wbase = (i * 9 + a * 3 + b) * 16 + oh * 8;
                #pragma unroll
                for (int o = 0; o < 8; ++o) {
                    const float wr_ = swr[wbase + o];
                    const float wi_ = swi[wbase + o];
                    #pragma unroll
                    for (int r = 0; r < 4; ++r) {
                        accr[r][o] += xv[r].x * wr_ - xv[r].y * wi_;
                        acci[r][o] += xv[r].x * wi_ + xv[r].y * wr_;
                    }
                }
            }
        }
    }

    const int u = u0 + lu;
    if (u < NU) {
        #pragma unroll
        for (int o = 0; o < 8; ++o) {
            const int og = oh * 8 + o;
            const float br_ = b_real[og];
            const float bi_ = b_imag[og];
            #pragma unroll
            for (int r = 0; r < 4; ++r) {
                const int h = h0 + lh0 + 4 * r;
                g_Y[(((size_t)n * NCH + og) * HH + h) * SU + u] =
                    make_float2(accr[r][o] + br_, acci[r][o] + bi_);
            }
        }
    }
}

// ---------------------------------------------------------------------------
// Kernel E: row irfft. 512 threads = 8 groups = 16 rows per block.
// Hermitian pack (Im at u in {0,256} zeroed -> exact), inverse 512-pt FFT.
// ---------------------------------------------------------------------------
__global__ __launch_bounds__(512) void kE_irfft_rows(float* __restrict__ out) {
    __shared__ float2 s[8 * GSTR];
    const int t = threadIdx.x & 63;
    const int g = threadIdx.x >> 6;
    const int img = blockIdx.x >> 5;
    const int seg = blockIdx.x & 31;
    const int pr = seg * 8 + g;

    const float2* G0 = g_Y + ((size_t)img * HH + 2 * pr) * SU;
    const float2* G1 = G0 + SU;

    float2* z = s + g * GSTR;
    #pragma unroll
    for (int m = 0; m < 5; ++m) {
        const int u = t + 64*m;
        if (u < NU) {
            float2 A = G0[u];
            float2 B = G1[u];
            if (u == 0 || u == 256) { A.y = 0.f; B.y = 0.f; }
            z[u] = make_float2(A.x - B.y, A.y + B.x);            // A + i*B
            if (u >= 1 && u <= 255)
                z[512 - u] = make_float2(A.x + B.y, B.x - A.y);  // conj ext
        }
    }
    __syncthreads();

    float2 a[8];
    #pragma unroll
    for (int m = 0; m < 8; ++m) a[m] = z[t + 64*m];
    __syncthreads();       // all reads done before fft writes into z

    fft512_regs<+1>(a, t, z);

    float* o0 = out + ((size_t)img * HH + 2 * pr) * WW;
    float* o1 = o0 + WW;
    #pragma unroll
    for (int m = 0; m < 8; ++m) {
        o0[t + 64*m] = a[m].x;
        o1[t + 64*m] = a[m].y;
    }
}

// ---------------------------------------------------------------------------
// Launch
// ---------------------------------------------------------------------------
extern "C" void kernel_launch(void* const* d_in, const int* in_sizes, int n_in,
                              void* d_out, int out_size) {
    const float* x      = (const float*)d_in[0];
    const float* w_real = (const float*)d_in[1];
    const float* w_imag = (const float*)d_in[2];
    const float* b_real = (const float*)d_in[3];
    const float* b_imag = (const float*)d_in[4];
    float* out = (float*)d_out;

    const int smemC_bytes = SX_ELEMS * (int)sizeof(float2) + 2 * W_ELEMS * (int)sizeof(float);
    cudaFuncSetAttribute(kC_conv, cudaFuncAttributeMaxDynamicSharedMemorySize, smemC_bytes);

    // 1) row rfft
    kA_rfft_rows<<<IMGS * 32, 512>>>(x);

    // 2) forward column FFT over h
    dim3 gB((NU + 7) / 8, IMGS);
    kBD_fft_cols<-1><<<gB, 512>>>(0, 1.0f);

    // 3) 3x3 complex conv + bias in frequency domain
    dim3 gC((NU + TU - 1) / TU, HH / TH, NBATCH);
    kC_conv<<<gC, 256, smemC_bytes>>>(w_real, w_imag, b_real, b_imag);

    // 4) inverse column FFT over h, folding the backward norm 1/(512*512)
    kBD_fft_cols<+1><<<gB, 512>>>(1, 1.0f / (512.0f * 512.0f));

    // 5) row irfft -> real output
    kE_irfft_rows<<<IMGS * 32, 512>>>(out);
}

// round 4
// speedup vs baseline: 1.1238x; 1.1238x over previous
#include <cuda_runtime.h>
#include <cstdint>

#define HH 512
#define WW 512
#define NU 257
#define SU 260
#define NCH 16
#define NBATCH 8
#define IMGS (NBATCH*NCH)
#define GSTR 578

__device__ float2 g_X[(size_t)IMGS * HH * SU];
__device__ float2 g_Y[(size_t)IMGS * HH * SU];

__device__ __forceinline__ float2 cmul(float2 a, float2 b) {
    return make_float2(a.x*b.x - a.y*b.y, a.x*b.y + a.y*b.x);
}
__device__ __forceinline__ float2 cadd(float2 a, float2 b) { return make_float2(a.x+b.x, a.y+b.y); }
__device__ __forceinline__ float2 csub(float2 a, float2 b) { return make_float2(a.x-b.x, a.y-b.y); }

#define PACK2(d, lo, hi) asm("mov.b64 %0, {%1, %2};" : "=l"(d) : "f"(lo), "f"(hi))
#define UNPACK2(lo, hi, s) asm("mov.b64 {%0, %1}, %2;" : "=f"(lo), "=f"(hi) : "l"(s))
#define FMA2(d, a, b, c) asm("fma.rn.f32x2 %0, %1, %2, %3;" : "=l"(d) : "l"(a), "l"(b), "l"(c))

// ---------------- radix-8 register FFT (as round 2) ----------------
template<int S>
__device__ __forceinline__ void fft8(float2 a[8]) {
    const float r = 0.7071067811865476f;
    const float sf = (float)S;
    float2 d, u;
    u=a[0]; d=csub(u,a[4]); a[0]=cadd(u,a[4]); a[4]=d;
    u=a[1]; d=csub(u,a[5]); a[1]=cadd(u,a[5]); a[5]=make_float2(r*(d.x - sf*d.y), r*(sf*d.x + d.y));
    u=a[2]; d=csub(u,a[6]); a[2]=cadd(u,a[6]); a[6]=make_float2(-sf*d.y, sf*d.x);
    u=a[3]; d=csub(u,a[7]); a[3]=cadd(u,a[7]); a[7]=make_float2(r*(-d.x - sf*d.y), r*(sf*d.x - d.y));
    u=a[0]; d=csub(u,a[2]); a[0]=cadd(u,a[2]); a[2]=d;
    u=a[1]; d=csub(u,a[3]); a[1]=cadd(u,a[3]); a[3]=make_float2(-sf*d.y, sf*d.x);
    u=a[4]; d=csub(u,a[6]); a[4]=cadd(u,a[6]); a[6]=d;
    u=a[5]; d=csub(u,a[7]); a[5]=cadd(u,a[7]); a[7]=make_float2(-sf*d.y, sf*d.x);
    u=a[0]; a[0]=cadd(u,a[1]); a[1]=csub(u,a[1]);
    u=a[2]; a[2]=cadd(u,a[3]); a[3]=csub(u,a[3]);
    u=a[4]; a[4]=cadd(u,a[5]); a[5]=csub(u,a[5]);
    u=a[6]; a[6]=cadd(u,a[7]); a[7]=csub(u,a[7]);
    d=a[1]; a[1]=a[4]; a[4]=d;
    d=a[3]; a[3]=a[6]; a[6]=d;
}

template<int S>
__device__ __forceinline__ void fft512_regs(float2 a[8], int t, float2* s) {
    const float TWO_PI = 6.283185307179586f;
    const int n2 = t & 7;
    const int n1 = t >> 3;

    fft8<S>(a);
    const float c1 = (float)S * TWO_PI / 64.0f * (float)n1;
    #pragma unroll
    for (int k0 = 1; k0 < 8; ++k0) {
        float sn, cs; __sincosf(c1 * (float)k0, &sn, &cs);
        a[k0] = cmul(a[k0], make_float2(cs, sn));
    }
    #pragma unroll
    for (int k0 = 0; k0 < 8; ++k0) s[t + 72*k0] = a[k0];
    __syncthreads();
    const int k0r = t >> 3;
    #pragma unroll
    for (int j = 0; j < 8; ++j) a[j] = s[n2 + 8*j + 72*k0r];
    __syncthreads();

    fft8<S>(a);
    const float c2 = (float)S * TWO_PI / 512.0f * (float)n2;
    #pragma unroll
    for (int k1 = 0; k1 < 8; ++k1) {
        float sn, cs; __sincosf(c2 * (float)(k0r + 8*k1), &sn, &cs);
        a[k1] = cmul(a[k1], make_float2(cs, sn));
    }
    #pragma unroll
    for (int k1 = 0; k1 < 8; ++k1) s[72*k1 + 8*k0r + (n2 ^ k0r)] = a[k1];
    __syncthreads();
    const int k0b = t & 7, k1r = t >> 3;
    #pragma unroll
    for (int j = 0; j < 8; ++j) a[j] = s[72*k1r + 8*k0b + (j ^ k0b)];

    fft8<S>(a);
}

// ---------------- kA: row rfft ----------------
__global__ __launch_bounds__(512) void kA_rfft_rows(const float* __restrict__ x) {
    __shared__ float2 s[8 * GSTR];
    const int t = threadIdx.x & 63;
    const int g = threadIdx.x >> 6;
    const int img = blockIdx.x >> 5;
    const int seg = blockIdx.x & 31;
    const int pr = seg * 8 + g;

    const float* r0 = x + ((size_t)img * HH + 2 * pr) * WW;
    const float* r1 = r0 + WW;

    float2 a[8];
    #pragma unroll
    for (int m = 0; m < 8; ++m)
        a[m] = make_float2(r0[t + 64*m], r1[t + 64*m]);

    float2* z = s + g * GSTR;
    fft512_regs<-1>(a, t, z);

    __syncthreads();
    #pragma unroll
    for (int m = 0; m < 8; ++m) z[t + 64*m] = a[m];
    __syncthreads();

    float2* X0 = g_X + ((size_t)img * HH + 2 * pr) * SU;
    float2* X1 = X0 + SU;
    #pragma unroll
    for (int m = 0; m < 5; ++m) {
        const int u = t + 64*m;
        if (u < NU) {
            const float2 zk = z[u];
            const float2 zm = z[(512 - u) & 511];
            X0[u] = make_float2(0.5f*(zk.x + zm.x),  0.5f*(zk.y - zm.y));
            X1[u] = make_float2(0.5f*(zk.y + zm.y), -0.5f*(zk.x - zm.x));
        }
    }
}

// ---------------- kB/kD: column FFT ----------------
template<int S>
__global__ __launch_bounds__(512) void kBD_fft_cols(int useY, float scale) {
    __shared__ float2 s[8 * GSTR];
    const int g = threadIdx.x & 7;
    const int t = threadIdx.x >> 3;
    const int img = blockIdx.y;
    const int u = blockIdx.x * 8 + g;
    const bool ok = (u < NU);

    float2* data = useY ? g_Y : g_X;
    float2* base = data + (size_t)img * HH * SU + u;

    float2 a[8];
    #pragma unroll
    for (int m = 0; m < 8; ++m)
        a[m] = ok ? base[(size_t)(t + 64*m) * SU] : make_float2(0.f, 0.f);

    fft512_regs<S>(a, t, s + g * GSTR);

    if (ok) {
        #pragma unroll
        for (int m = 0; m < 8; ++m)
            base[(size_t)(t + 64*m) * SU] = make_float2(a[m].x * scale, a[m].y * scale);
    }
}

// ---------------- kC: spectral 3x3 complex conv, packed f32x2 FMA ----------------
#define TH 16
#define TU 32
#define SXW 35
#define SX_ELEMS (NCH * (TH + 2) * SXW)
#define W_ELEMS (NCH * NCH * 9)

__global__ __launch_bounds__(256, 1) void kC_conv(
    const float* __restrict__ w_real, const float* __restrict__ w_imag,
    const float* __restrict__ b_real, const float* __restrict__ b_imag)
{
    extern __shared__ float smemC[];
    float2* sX  = (float2*)smemC;                    // [16][18][35]
    float2* sw1 = (float2*)(sX + SX_ELEMS);          // (wr, wi)
    float2* sw2 = sw1 + W_ELEMS;                     // (-wi, wr)

    const int t = threadIdx.x;
    const int u0 = blockIdx.x * TU;
    const int h0 = blockIdx.y * TH;
    const int n  = blockIdx.z;

    for (int idx = t; idx < W_ELEMS; idx += 256) {
        const int i = idx / 144;
        const int q = idx - i * 144;
        const int tap = q >> 4;
        const int o = q & 15;
        const int src = (i * 16 + o) * 9 + tap;
        const float wr = w_real[src];
        const float wi = w_imag[src];
        sw1[idx] = make_float2(wr, wi);
        sw2[idx] = make_float2(-wi, wr);
    }

    for (int e = t; e < NCH * (TH + 2) * (TU + 2); e += 256) {
        const int i = e / ((TH + 2) * (TU + 2));
        const int q = e - i * ((TH + 2) * (TU + 2));
        const int rr = q / (TU + 2);
        const int cc = q - rr * (TU + 2);
        const int gh = h0 - 1 + rr;
        const int gu = u0 - 1 + cc;
        float2 v = make_float2(0.f, 0.f);
        if (gh >= 0 && gh < HH && gu >= 0 && gu < NU)
            v = g_X[(((size_t)n * NCH + i) * HH + gh) * SU + gu];
        sX[(i * (TH + 2) + rr) * SXW + cc] = v;
    }
    __syncthreads();

    const int oh = t >> 7;
    const int ps = t & 127;
    const int lh0 = ps >> 5;
    const int lu  = ps & 31;

    unsigned long long acc[4][8];
    #pragma unroll
    for (int r = 0; r < 4; ++r)
        #pragma unroll
        for (int o = 0; o < 8; ++o) acc[r][o] = 0ull;

    for (int i = 0; i < NCH; ++i) {
        #pragma unroll
        for (int a = 0; a < 3; ++a) {
            #pragma unroll
            for (int b = 0; b < 3; ++b) {
                unsigned long long xr2[4], xi2[4];
                #pragma unroll
                for (int r = 0; r < 4; ++r) {
                    const float2 xv = sX[(i * (TH + 2) + (lh0 + 4 * r + 2 - a)) * SXW + (lu + 2 - b)];
                    PACK2(xr2[r], xv.x, xv.x);
                    PACK2(xi2[r], xv.y, xv.y);
                }
                const int wbase = (i * 9 + a * 3 + b) * 16 + oh * 8;
                #pragma unroll
                for (int o = 0; o < 8; ++o) {
                    unsigned long long w1 = *(const unsigned long long*)(sw1 + wbase + o);
                    unsigned long long w2 = *(const unsigned long long*)(sw2 + wbase + o);
                    #pragma unroll
                    for (int r = 0; r < 4; ++r) {
                        FMA2(acc[r][o], xr2[r], w1, acc[r][o]);
                        FMA2(acc[r][o], xi2[r], w2, acc[r][o]);
                    }
                }
            }
        }
    }

    const int u = u0 + lu;
    if (u < NU) {
        #pragma unroll
        for (int o = 0; o < 8; ++o) {
            const int og = oh * 8 + o;
            const float br_ = b_real[og];
            const float bi_ = b_imag[og];
            #pragma unroll
            for (int r = 0; r < 4; ++r) {
                const int h = h0 + lh0 + 4 * r;
                float zr, zi;
                UNPACK2(zr, zi, acc[r][o]);
                g_Y[(((size_t)n * NCH + og) * HH + h) * SU + u] =
                    make_float2(zr + br_, zi + bi_);
            }
        }
    }
}

// ---------------- kE: row irfft ----------------
__global__ __launch_bounds__(512) void kE_irfft_rows(float* __restrict__ out) {
    __shared__ float2 s[8 * GSTR];
    const int t = threadIdx.x & 63;
    const int g = threadIdx.x >> 6;
    const int img = blockIdx.x >> 5;
    const int seg = blockIdx.x & 31;
    const int pr = seg * 8 + g;

    const float2* G0 = g_Y + ((size_t)img * HH + 2 * pr) * SU;
    const float2* G1 = G0 + SU;

    float2* z = s + g * GSTR;
    #pragma unroll
    for (int m = 0; m < 5; ++m) {
        const int u = t + 64*m;
        if (u < NU) {
            float2 A = G0[u];
            float2 B = G1[u];
            if (u == 0 || u == 256) { A.y = 0.f; B.y = 0.f; }
            z[u] = make_float2(A.x - B.y, A.y + B.x);
            if (u >= 1 && u <= 255)
                z[512 - u] = make_float2(A.x + B.y, B.x - A.y);
        }
    }
    __syncthreads();

    float2 a[8];
    #pragma unroll
    for (int m = 0; m < 8; ++m) a[m] = z[t + 64*m];
    __syncthreads();

    fft512_regs<+1>(a, t, z);

    float* o0 = out + ((size_t)img * HH + 2 * pr) * WW;
    float* o1 = o0 + WW;
    #pragma unroll
    for (int m = 0; m < 8; ++m) {
        o0[t + 64*m] = a[m].x;
        o1[t + 64*m] = a[m].y;
    }
}

// ---------------- launch ----------------
extern "C" void kernel_launch(void* const* d_in, const int* in_sizes, int n_in,
                              void* d_out, int out_size) {
    const float* x      = (const float*)d_in[0];
    const float* w_real = (const float*)d_in[1];
    const float* w_imag = (const float*)d_in[2];
    const float* b_real = (const float*)d_in[3];
    const float* b_imag = (const float*)d_in[4];
    float* out = (float*)d_out;

    const int smemC_bytes = SX_ELEMS * (int)sizeof(float2) + 2 * W_ELEMS * (int)sizeof(float2);
    cudaFuncSetAttribute(kC_conv, cudaFuncAttributeMaxDynamicSharedMemorySize, smemC_bytes);

    kA_rfft_rows<<<IMGS * 32, 512>>>(x);

    dim3 gB((NU + 7) / 8, IMGS);
    kBD_fft_cols<-1><<<gB, 512>>>(0, 1.0f);

    dim3 gC((NU + TU - 1) / TU, HH / TH, NBATCH);
    kC_conv<<<gC, 256, smemC_bytes>>>(w_real, w_imag, b_real, b_imag);

    kBD_fft_cols<+1><<<gB, 512>>>(1, 1.0f / (512.0f * 512.0f));

    kE_irfft_rows<<<IMGS * 32, 512>>>(out);
}

// round 6
// speedup vs baseline: 1.3142x; 1.1694x over previous
#include <cuda_runtime.h>
#include <cuda_bf16.h>
#include <cstdint>

#define HH 512
#define WW 512
#define NU 257
#define SU 260
#define NCH 16
#define NBATCH 8
#define IMGS (NBATCH*NCH)
#define GSTR 578

__device__ float2 g_X[(size_t)IMGS * HH * SU];
__device__ float2 g_Y[(size_t)IMGS * HH * SU];

__device__ __forceinline__ float2 cmul(float2 a, float2 b) {
    return make_float2(a.x*b.x - a.y*b.y, a.x*b.y + a.y*b.x);
}
__device__ __forceinline__ float2 cadd(float2 a, float2 b) { return make_float2(a.x+b.x, a.y+b.y); }
__device__ __forceinline__ float2 csub(float2 a, float2 b) { return make_float2(a.x-b.x, a.y-b.y); }

// ---------------- radix-8 register FFT ----------------
template<int S>
__device__ __forceinline__ void fft8(float2 a[8]) {
    const float r = 0.7071067811865476f;
    const float sf = (float)S;
    float2 d, u;
    u=a[0]; d=csub(u,a[4]); a[0]=cadd(u,a[4]); a[4]=d;
    u=a[1]; d=csub(u,a[5]); a[1]=cadd(u,a[5]); a[5]=make_float2(r*(d.x - sf*d.y), r*(sf*d.x + d.y));
    u=a[2]; d=csub(u,a[6]); a[2]=cadd(u,a[6]); a[6]=make_float2(-sf*d.y, sf*d.x);
    u=a[3]; d=csub(u,a[7]); a[3]=cadd(u,a[7]); a[7]=make_float2(r*(-d.x - sf*d.y), r*(sf*d.x - d.y));
    u=a[0]; d=csub(u,a[2]); a[0]=cadd(u,a[2]); a[2]=d;
    u=a[1]; d=csub(u,a[3]); a[1]=cadd(u,a[3]); a[3]=make_float2(-sf*d.y, sf*d.x);
    u=a[4]; d=csub(u,a[6]); a[4]=cadd(u,a[6]); a[6]=d;
    u=a[5]; d=csub(u,a[7]); a[5]=cadd(u,a[7]); a[7]=make_float2(-sf*d.y, sf*d.x);
    u=a[0]; a[0]=cadd(u,a[1]); a[1]=csub(u,a[1]);
    u=a[2]; a[2]=cadd(u,a[3]); a[3]=csub(u,a[3]);
    u=a[4]; a[4]=cadd(u,a[5]); a[5]=csub(u,a[5]);
    u=a[6]; a[6]=cadd(u,a[7]); a[7]=csub(u,a[7]);
    d=a[1]; a[1]=a[4]; a[4]=d;
    d=a[3]; a[3]=a[6]; a[6]=d;
}

template<int S>
__device__ __forceinline__ void fft512_regs(float2 a[8], int t, float2* s) {
    const float TWO_PI = 6.283185307179586f;
    const int n2 = t & 7;
    const int n1 = t >> 3;
    fft8<S>(a);
    const float c1 = (float)S * TWO_PI / 64.0f * (float)n1;
    #pragma unroll
    for (int k0 = 1; k0 < 8; ++k0) {
        float sn, cs; __sincosf(c1 * (float)k0, &sn, &cs);
        a[k0] = cmul(a[k0], make_float2(cs, sn));
    }
    #pragma unroll
    for (int k0 = 0; k0 < 8; ++k0) s[t + 72*k0] = a[k0];
    __syncthreads();
    const int k0r = t >> 3;
    #pragma unroll
    for (int j = 0; j < 8; ++j) a[j] = s[n2 + 8*j + 72*k0r];
    __syncthreads();
    fft8<S>(a);
    const float c2 = (float)S * TWO_PI / 512.0f * (float)n2;
    #pragma unroll
    for (int k1 = 0; k1 < 8; ++k1) {
        float sn, cs; __sincosf(c2 * (float)(k0r + 8*k1), &sn, &cs);
        a[k1] = cmul(a[k1], make_float2(cs, sn));
    }
    #pragma unroll
    for (int k1 = 0; k1 < 8; ++k1) s[72*k1 + 8*k0r + (n2 ^ k0r)] = a[k1];
    __syncthreads();
    const int k0b = t & 7, k1r = t >> 3;
    #pragma unroll
    for (int j = 0; j < 8; ++j) a[j] = s[72*k1r + 8*k0b + (j ^ k0b)];
    fft8<S>(a);
}

__global__ __launch_bounds__(512) void kA_rfft_rows(const float* __restrict__ x) {
    __shared__ float2 s[8 * GSTR];
    const int t = threadIdx.x & 63;
    const int g = threadIdx.x >> 6;
    const int img = blockIdx.x >> 5;
    const int pr = (blockIdx.x & 31) * 8 + g;
    const float* r0 = x + ((size_t)img * HH + 2 * pr) * WW;
    const float* r1 = r0 + WW;
    float2 a[8];
    #pragma unroll
    for (int m = 0; m < 8; ++m) a[m] = make_float2(r0[t + 64*m], r1[t + 64*m]);
    float2* z = s + g * GSTR;
    fft512_regs<-1>(a, t, z);
    __syncthreads();
    #pragma unroll
    for (int m = 0; m < 8; ++m) z[t + 64*m] = a[m];
    __syncthreads();
    float2* X0 = g_X + ((size_t)img * HH + 2 * pr) * SU;
    float2* X1 = X0 + SU;
    #pragma unroll
    for (int m = 0; m < 5; ++m) {
        const int u = t + 64*m;
        if (u < NU) {
            const float2 zk = z[u];
            const float2 zm = z[(512 - u) & 511];
            X0[u] = make_float2(0.5f*(zk.x + zm.x),  0.5f*(zk.y - zm.y));
            X1[u] = make_float2(0.5f*(zk.y + zm.y), -0.5f*(zk.x - zm.x));
        }
    }
}

template<int S>
__global__ __launch_bounds__(512) void kBD_fft_cols(int useY, float scale) {
    __shared__ float2 s[8 * GSTR];
    const int g = threadIdx.x & 7;
    const int t = threadIdx.x >> 3;
    const int img = blockIdx.y;
    const int u = blockIdx.x * 8 + g;
    const bool ok = (u < NU);
    float2* data = useY ? g_Y : g_X;
    float2* base = data + (size_t)img * HH * SU + u;
    float2 a[8];
    #pragma unroll
    for (int m = 0; m < 8; ++m)
        a[m] = ok ? base[(size_t)(t + 64*m) * SU] : make_float2(0.f, 0.f);
    fft512_regs<S>(a, t, s + g * GSTR);
    if (ok) {
        #pragma unroll
        for (int m = 0; m < 8; ++m)
            base[(size_t)(t + 64*m) * SU] = make_float2(a[m].x * scale, a[m].y * scale);
    }
}

// ===================== kC: mma.sync bf16 implicit spectral conv =====================
// Block: 512 thr = 16 warps. Payload: 16 h-lines x 32 u. Halo: 18 x 34 points.
// Per point K = 96 bf16 (as 48 u32): [A_hi(16 u32) | A_lo(16) | A_hi(16)].
// B per tap: [W_hi | W_hi | W_lo] over K=96, N=32 (16 outch x {re,im}).
#define APITCH 52                      // u32 per point (48 used + 4 pad)
#define HALO_PTS (18 * 34)             // 612
#define A_U32 (HALO_PTS * APITCH)      // 31824
#define B_U32 (9 * 6 * 4 * 2 * 32)     // 13824
#define KC_SMEM ((A_U32 + B_U32) * 4)  // 182592 B

__device__ __forceinline__ uint32_t packbf(float x, float y) {
    __nv_bfloat162 h;
    h.x = __float2bfloat16_rn(x);
    h.y = __float2bfloat16_rn(y);
    uint32_t r;
    *(__nv_bfloat162*)&r = h;
    return r;
}

__device__ __forceinline__ void mma16816(float* d, uint32_t a0, uint32_t a1,
                                         uint32_t a2, uint32_t a3,
                                         uint32_t b0, uint32_t b1) {
    asm volatile(
        "mma.sync.aligned.m16n8k16.row.col.f32.bf16.bf16.f32 "
        "{%0,%1,%2,%3}, {%4,%5,%6,%7}, {%8,%9}, {%0,%1,%2,%3};"
        : "+f"(d[0]), "+f"(d[1]), "+f"(d[2]), "+f"(d[3])
        : "r"(a0), "r"(a1), "r"(a2), "r"(a3), "r"(b0), "r"(b1));
}

__global__ __launch_bounds__(512, 1) void kC_conv_mma(
    const float* __restrict__ w_real, const float* __restrict__ w_imag,
    const float* __restrict__ b_real, const float* __restrict__ b_imag)
{
    extern __shared__ uint32_t smc[];
    uint32_t* sA = smc;
    uint32_t* sB = smc + A_U32;

    const int t = threadIdx.x;
    const int w = t >> 5;
    const int lane = t & 31;
    const int g = lane >> 2;       // group id (0..7)
    const int th = lane & 3;       // thread-in-group
    const int ubase = blockIdx.x * 32;
    const int h0 = blockIdx.y * 16;
    const int n = blockIdx.z;

    // ---- B fill: fragment order [tap][ks][nt][rr][lane] ----
    for (int e = t; e < B_U32; e += 512) {
        const int ln = e & 31;
        const int rr = (e >> 5) & 1;
        const int nt = (e >> 6) & 3;
        const int rem = e >> 8;
        const int ks = rem % 6;
        const int tap = rem / 6;
        const int a = tap / 3, b = tap % 3;
        const int gg = ln >> 2, tt = ln & 3;
        const int n_idx = nt * 8 + gg;
        const int o = n_idx >> 1, cout = n_idx & 1;
        float vals[2];
        #pragma unroll
        for (int q = 0; q < 2; ++q) {
            const int k = ks * 16 + tt * 2 + rr * 8 + q;
            const int half = k >> 5;           // 0,1: W_hi ; 2: W_lo
            const int i = (k & 31) >> 1;
            const int cin = k & 1;
            const float wr_ = w_real[(i * 16 + o) * 9 + a * 3 + b];
            const float wi_ = w_imag[(i * 16 + o) * 9 + a * 3 + b];
            const float coef = cout ? (cin ? wr_ : wi_) : (cin ? -wi_ : wr_);
            const float chi = __bfloat162float(__float2bfloat16_rn(coef));
            vals[q] = (half < 2) ? chi : (coef - chi);
        }
        sB[e] = packbf(vals[0], vals[1]);
    }

    // ---- A halo fill: 612 points x 16 ch ----
    for (int e = t; e < HALO_PTS * NCH; e += 512) {
        const int i = e / HALO_PTS;
        const int p = e - i * HALO_PTS;
        const int hr = p / 34;
        const int c = p - hr * 34;
        const int h = h0 - 1 + hr;
        const int u = ubase - 1 + c;
        float2 v = make_float2(0.f, 0.f);
        if (h >= 0 && h < HH && u >= 0 && u < NU)
            v = g_X[(((size_t)n * NCH + i) * HH + h) * SU + u];
        const float hr_ = __bfloat162float(__float2bfloat16_rn(v.x));
        const float hi_ = __bfloat162float(__float2bfloat16_rn(v.y));
        const uint32_t hp = packbf(v.x, v.y);
        const uint32_t lp = packbf(v.x - hr_, v.y - hi_);
        const int base = p * APITCH;
        sA[base + i] = hp;
        sA[base + 16 + i] = lp;
        sA[base + 32 + i] = hp;
    }
    __syncthreads();

    // ---- main loop ----
    float acc[2][4][4];
    #pragma unroll
    for (int mt = 0; mt < 2; ++mt)
        #pragma unroll
        for (int nt = 0; nt < 4; ++nt)
            #pragma unroll
            for (int q = 0; q < 4; ++q) acc[mt][nt][q] = 0.f;

    for (int tap = 0; tap < 9; ++tap) {
        const int a = tap / 3, b = tap % 3;
        const int prow = (w + 2 - a) * 34 + (2 - b);   // halo point index base
        #pragma unroll
        for (int ks = 0; ks < 6; ++ks) {
            uint32_t bf[4][2];
            const int bbase = (tap * 6 + ks) * 256 + lane;
            #pragma unroll
            for (int nt = 0; nt < 4; ++nt) {
                bf[nt][0] = sB[bbase + nt * 64];
                bf[nt][1] = sB[bbase + nt * 64 + 32];
            }
            #pragma unroll
            for (int mt = 0; mt < 2; ++mt) {
                const int p0 = (prow + mt * 16 + g) * APITCH + ks * 8 + th;
                const int p1 = p0 + 8 * APITCH;
                const uint32_t a0 = sA[p0];
                const uint32_t a1 = sA[p1];
                const uint32_t a2 = sA[p0 + 4];
                const uint32_t a3 = sA[p1 + 4];
                #pragma unroll
                for (int nt = 0; nt < 4; ++nt)
                    mma16816(acc[mt][nt], a0, a1, a2, a3, bf[nt][0], bf[nt][1]);
            }
        }
    }

    // ---- epilogue: lane owns (re,im) of outch o = nt*4+th at 2x2 points ----
    const int h = h0 + w;
    #pragma unroll
    for (int nt = 0; nt < 4; ++nt) {
        const int o = nt * 4 + th;
        const float br_ = __ldg(b_real + o);
        const float bi_ = __ldg(b_imag + o);
        float2* Yrow = g_Y + (((size_t)n * NCH + o) * HH + h) * SU;
        #pragma unroll
        for (int mt = 0; mt < 2; ++mt) {
            const int u0 = ubase + mt * 16 + g;
            const int u1 = u0 + 8;
            if (u0 < NU)
                Yrow[u0] = make_float2(acc[mt][nt][0] + br_, acc[mt][nt][1] + bi_);
            if (u1 < NU)
                Yrow[u1] = make_float2(acc[mt][nt][2] + br_, acc[mt][nt][3] + bi_);
        }
    }
}

__global__ __launch_bounds__(512) void kE_irfft_rows(float* __restrict__ out) {
    __shared__ float2 s[8 * GSTR];
    const int t = threadIdx.x & 63;
    const int g = threadIdx.x >> 6;
    const int img = blockIdx.x >> 5;
    const int pr = (blockIdx.x & 31) * 8 + g;
    const float2* G0 = g_Y + ((size_t)img * HH + 2 * pr) * SU;
    const float2* G1 = G0 + SU;
    float2* z = s + g * GSTR;
    #pragma unroll
    for (int m = 0; m < 5; ++m) {
        const int u = t + 64*m;
        if (u < NU) {
            float2 A = G0[u];
            float2 B = G1[u];
            if (u == 0 || u == 256) { A.y = 0.f; B.y = 0.f; }
            z[u] = make_float2(A.x - B.y, A.y + B.x);
            if (u >= 1 && u <= 255)
                z[512 - u] = make_float2(A.x + B.y, B.x - A.y);
        }
    }
    __syncthreads();
    float2 a[8];
    #pragma unroll
    for (int m = 0; m < 8; ++m) a[m] = z[t + 64*m];
    __syncthreads();
    fft512_regs<+1>(a, t, z);
    float* o0 = out + ((size_t)img * HH + 2 * pr) * WW;
    float* o1 = o0 + WW;
    #pragma unroll
    for (int m = 0; m < 8; ++m) {
        o0[t + 64*m] = a[m].x;
        o1[t + 64*m] = a[m].y;
    }
}

extern "C" void kernel_launch(void* const* d_in, const int* in_sizes, int n_in,
                              void* d_out, int out_size) {
    const float* x      = (const float*)d_in[0];
    const float* w_real = (const float*)d_in[1];
    const float* w_imag = (const float*)d_in[2];
    const float* b_real = (const float*)d_in[3];
    const float* b_imag = (const float*)d_in[4];
    float* out = (float*)d_out;

    cudaFuncSetAttribute(kC_conv_mma, cudaFuncAttributeMaxDynamicSharedMemorySize, KC_SMEM);

    kA_rfft_rows<<<IMGS * 32, 512>>>(x);

    dim3 gB((NU + 7) / 8, IMGS);
    kBD_fft_cols<-1><<<gB, 512>>>(0, 1.0f);

    dim3 gC(9, HH / 16, NBATCH);
    kC_conv_mma<<<gC, 512, KC_SMEM>>>(w_real, w_imag, b_real, b_imag);

    kBD_fft_cols<+1><<<gB, 512>>>(1, 1.0f / (512.0f * 512.0f));

    kE_irfft_rows<<<IMGS * 32, 512>>>(out);
}

// round 7
// speedup vs baseline: 1.3587x; 1.0339x over previous
#include <cuda_runtime.h>
#include <cuda_bf16.h>
#include <cstdint>

#define HH 512
#define WW 512
#define NU 257
#define SU 260
#define NCH 16
#define NBATCH 8
#define IMGS (NBATCH*NCH)
#define GSTR 578

__device__ float2 g_X[(size_t)IMGS * HH * SU];
__device__ float2 g_Y[(size_t)IMGS * HH * SU];

__device__ __forceinline__ float2 cmul(float2 a, float2 b) {
    return make_float2(a.x*b.x - a.y*b.y, a.x*b.y + a.y*b.x);
}
__device__ __forceinline__ float2 cadd(float2 a, float2 b) { return make_float2(a.x+b.x, a.y+b.y); }
__device__ __forceinline__ float2 csub(float2 a, float2 b) { return make_float2(a.x-b.x, a.y-b.y); }

// ---------------- radix-8 register FFT ----------------
template<int S>
__device__ __forceinline__ void fft8(float2 a[8]) {
    const float r = 0.7071067811865476f;
    const float sf = (float)S;
    float2 d, u;
    u=a[0]; d=csub(u,a[4]); a[0]=cadd(u,a[4]); a[4]=d;
    u=a[1]; d=csub(u,a[5]); a[1]=cadd(u,a[5]); a[5]=make_float2(r*(d.x - sf*d.y), r*(sf*d.x + d.y));
    u=a[2]; d=csub(u,a[6]); a[2]=cadd(u,a[6]); a[6]=make_float2(-sf*d.y, sf*d.x);
    u=a[3]; d=csub(u,a[7]); a[3]=cadd(u,a[7]); a[7]=make_float2(r*(-d.x - sf*d.y), r*(sf*d.x - d.y));
    u=a[0]; d=csub(u,a[2]); a[0]=cadd(u,a[2]); a[2]=d;
    u=a[1]; d=csub(u,a[3]); a[1]=cadd(u,a[3]); a[3]=make_float2(-sf*d.y, sf*d.x);
    u=a[4]; d=csub(u,a[6]); a[4]=cadd(u,a[6]); a[6]=d;
    u=a[5]; d=csub(u,a[7]); a[5]=cadd(u,a[7]); a[7]=make_float2(-sf*d.y, sf*d.x);
    u=a[0]; a[0]=cadd(u,a[1]); a[1]=csub(u,a[1]);
    u=a[2]; a[2]=cadd(u,a[3]); a[3]=csub(u,a[3]);
    u=a[4]; a[4]=cadd(u,a[5]); a[5]=csub(u,a[5]);
    u=a[6]; a[6]=cadd(u,a[7]); a[7]=csub(u,a[7]);
    d=a[1]; a[1]=a[4]; a[4]=d;
    d=a[3]; a[3]=a[6]; a[6]=d;
}

template<int S>
__device__ __forceinline__ void fft512_regs(float2 a[8], int t, float2* s) {
    const float TWO_PI = 6.283185307179586f;
    const int n2 = t & 7;
    const int n1 = t >> 3;
    fft8<S>(a);
    const float c1 = (float)S * TWO_PI / 64.0f * (float)n1;
    #pragma unroll
    for (int k0 = 1; k0 < 8; ++k0) {
        float sn, cs; __sincosf(c1 * (float)k0, &sn, &cs);
        a[k0] = cmul(a[k0], make_float2(cs, sn));
    }
    #pragma unroll
    for (int k0 = 0; k0 < 8; ++k0) s[t + 72*k0] = a[k0];
    __syncthreads();
    const int k0r = t >> 3;
    #pragma unroll
    for (int j = 0; j < 8; ++j) a[j] = s[n2 + 8*j + 72*k0r];
    __syncthreads();
    fft8<S>(a);
    const float c2 = (float)S * TWO_PI / 512.0f * (float)n2;
    #pragma unroll
    for (int k1 = 0; k1 < 8; ++k1) {
        float sn, cs; __sincosf(c2 * (float)(k0r + 8*k1), &sn, &cs);
        a[k1] = cmul(a[k1], make_float2(cs, sn));
    }
    #pragma unroll
    for (int k1 = 0; k1 < 8; ++k1) s[72*k1 + 8*k0r + (n2 ^ k0r)] = a[k1];
    __syncthreads();
    const int k0b = t & 7, k1r = t >> 3;
    #pragma unroll
    for (int j = 0; j < 8; ++j) a[j] = s[72*k1r + 8*k0b + (j ^ k0b)];
    fft8<S>(a);
}

__global__ __launch_bounds__(512) void kA_rfft_rows(const float* __restrict__ x) {
    __shared__ float2 s[8 * GSTR];
    const int t = threadIdx.x & 63;
    const int g = threadIdx.x >> 6;
    const int img = blockIdx.x >> 5;
    const int pr = (blockIdx.x & 31) * 8 + g;
    const float* r0 = x + ((size_t)img * HH + 2 * pr) * WW;
    const float* r1 = r0 + WW;
    float2 a[8];
    #pragma unroll
    for (int m = 0; m < 8; ++m) a[m] = make_float2(r0[t + 64*m], r1[t + 64*m]);
    float2* z = s + g * GSTR;
    fft512_regs<-1>(a, t, z);
    __syncthreads();
    #pragma unroll
    for (int m = 0; m < 8; ++m) z[t + 64*m] = a[m];
    __syncthreads();
    float2* X0 = g_X + ((size_t)img * HH + 2 * pr) * SU;
    float2* X1 = X0 + SU;
    #pragma unroll
    for (int m = 0; m < 5; ++m) {
        const int u = t + 64*m;
        if (u < NU) {
            const float2 zk = z[u];
            const float2 zm = z[(512 - u) & 511];
            X0[u] = make_float2(0.5f*(zk.x + zm.x),  0.5f*(zk.y - zm.y));
            X1[u] = make_float2(0.5f*(zk.y + zm.y), -0.5f*(zk.x - zm.x));
        }
    }
}

template<int S>
__global__ __launch_bounds__(512) void kBD_fft_cols(int useY, float scale) {
    __shared__ float2 s[8 * GSTR];
    const int g = threadIdx.x & 7;
    const int t = threadIdx.x >> 3;
    const int img = blockIdx.y;
    const int u = blockIdx.x * 8 + g;
    const bool ok = (u < NU);
    float2* data = useY ? g_Y : g_X;
    float2* base = data + (size_t)img * HH * SU + u;
    float2 a[8];
    #pragma unroll
    for (int m = 0; m < 8; ++m)
        a[m] = ok ? base[(size_t)(t + 64*m) * SU] : make_float2(0.f, 0.f);
    fft512_regs<S>(a, t, s + g * GSTR);
    if (ok) {
        #pragma unroll
        for (int m = 0; m < 8; ++m)
            base[(size_t)(t + 64*m) * SU] = make_float2(a[m].x * scale, a[m].y * scale);
    }
}

// ===================== kC: mma.sync bf16 + ldmatrix =====================
#define APITCH 52                      // u32 per point (48 used + 4 pad)
#define HALO_PTS (18 * 34)             // 612
#define A_U32 (HALO_PTS * APITCH)      // 31824
#define B_U32 (9 * 6 * 4 * 2 * 32)     // 13824
#define KC_SMEM ((A_U32 + B_U32) * 4)  // 182592 B

__device__ __forceinline__ uint32_t packbf(float x, float y) {
    __nv_bfloat162 h;
    h.x = __float2bfloat16_rn(x);
    h.y = __float2bfloat16_rn(y);
    uint32_t r;
    *(__nv_bfloat162*)&r = h;
    return r;
}

__device__ __forceinline__ uint32_t smem_u32(const void* p) {
    uint32_t a;
    asm("{ .reg .u64 t; cvta.to.shared.u64 t, %1; cvt.u32.u64 %0, t; }" : "=r"(a) : "l"(p));
    return a;
}

__device__ __forceinline__ void ldmA(uint32_t addr, uint32_t& a0, uint32_t& a1,
                                     uint32_t& a2, uint32_t& a3) {
    asm volatile("ldmatrix.sync.aligned.m8n8.x4.shared.b16 {%0,%1,%2,%3}, [%4];"
                 : "=r"(a0), "=r"(a1), "=r"(a2), "=r"(a3) : "r"(addr));
}

__device__ __forceinline__ void mma16816(float* d, uint32_t a0, uint32_t a1,
                                         uint32_t a2, uint32_t a3,
                                         uint32_t b0, uint32_t b1) {
    asm volatile(
        "mma.sync.aligned.m16n8k16.row.col.f32.bf16.bf16.f32 "
        "{%0,%1,%2,%3}, {%4,%5,%6,%7}, {%8,%9}, {%0,%1,%2,%3};"
        : "+f"(d[0]), "+f"(d[1]), "+f"(d[2]), "+f"(d[3])
        : "r"(a0), "r"(a1), "r"(a2), "r"(a3), "r"(b0), "r"(b1));
}

__global__ __launch_bounds__(512, 1) void kC_conv_mma(
    const float* __restrict__ w_real, const float* __restrict__ w_imag,
    const float* __restrict__ b_real, const float* __restrict__ b_imag)
{
    extern __shared__ uint32_t smc[];
    uint32_t* sA = smc;
    uint32_t* sB = smc + A_U32;

    const int t = threadIdx.x;
    const int w = t >> 5;
    const int lane = t & 31;
    const int g = lane >> 2;
    const int th = lane & 3;
    const int ubase = blockIdx.x * 32;
    const int h0 = blockIdx.y * 16;
    const int n = blockIdx.z;

    // ---- B fill: [tap][ks] chunk of 256 u32; pairs (b0,b1) adjacent per lane ----
    for (int e = t; e < B_U32; e += 512) {
        const int ln = e & 31;
        const int rr = (e >> 5) & 1;
        const int nt = (e >> 6) & 3;
        const int rem = e >> 8;
        const int ks = rem % 6;
        const int tap = rem / 6;
        const int a = tap / 3, b = tap % 3;
        const int gg = ln >> 2, tt = ln & 3;
        const int n_idx = nt * 8 + gg;
        const int o = n_idx >> 1, cout = n_idx & 1;
        float vals[2];
        #pragma unroll
        for (int q = 0; q < 2; ++q) {
            const int k = ks * 16 + tt * 2 + rr * 8 + q;
            const int half = k >> 5;
            const int i = (k & 31) >> 1;
            const int cin = k & 1;
            const float wr_ = w_real[(i * 16 + o) * 9 + a * 3 + b];
            const float wi_ = w_imag[(i * 16 + o) * 9 + a * 3 + b];
            const float coef = cout ? (cin ? wr_ : wi_) : (cin ? -wi_ : wr_);
            const float chi = __bfloat162float(__float2bfloat16_rn(coef));
            vals[q] = (half < 2) ? chi : (coef - chi);
        }
        sB[(tap * 6 + ks) * 256 + nt * 64 + ln * 2 + rr] = packbf(vals[0], vals[1]);
    }

    // ---- A halo fill ----
    for (int e = t; e < HALO_PTS * NCH; e += 512) {
        const int i = e / HALO_PTS;
        const int p = e - i * HALO_PTS;
        const int hr = p / 34;
        const int c = p - hr * 34;
        const int h = h0 - 1 + hr;
        const int u = ubase - 1 + c;
        float2 v = make_float2(0.f, 0.f);
        if (h >= 0 && h < HH && u >= 0 && u < NU)
            v = g_X[(((size_t)n * NCH + i) * HH + h) * SU + u];
        const float hr_ = __bfloat162float(__float2bfloat16_rn(v.x));
        const float hi_ = __bfloat162float(__float2bfloat16_rn(v.y));
        const uint32_t hp = packbf(v.x, v.y);
        const uint32_t lp = packbf(v.x - hr_, v.y - hi_);
        const int base = p * APITCH;
        sA[base + i] = hp;
        sA[base + 16 + i] = lp;
        sA[base + 32 + i] = hp;
    }
    __syncthreads();

    const uint32_t sAb = smem_u32(sA);

    float acc[2][4][4];
    #pragma unroll
    for (int mt = 0; mt < 2; ++mt)
        #pragma unroll
        for (int nt = 0; nt < 4; ++nt)
            #pragma unroll
            for (int q = 0; q < 4; ++q) acc[mt][nt][q] = 0.f;

    // lane's row-part for ldmatrix (fixed per tap): rows 0-7 lanes 0-7 & 16-23,
    // rows 8-15 lanes 8-15 & 24-31; k-halves by lane>>4.
    const int lrow = (lane & 7) + ((lane >> 3) & 1) * 8;
    const int lkof = (lane >> 4) * 4;

    for (int tap = 0; tap < 9; ++tap) {
        const int a = tap / 3, b = tap % 3;
        const int prow = (w + 2 - a) * 34 + (2 - b);
        const uint32_t abase = sAb + (uint32_t)(((prow + lrow) * APITCH) + lkof) * 4u;
        #pragma unroll
        for (int ks = 0; ks < 6; ++ks) {
            uint2 bb[4];
            const int bbase = (tap * 6 + ks) * 256 + lane * 2;
            #pragma unroll
            for (int nt = 0; nt < 4; ++nt)
                bb[nt] = *(const uint2*)(sB + bbase + nt * 64);
            #pragma unroll
            for (int mt = 0; mt < 2; ++mt) {
                uint32_t a0, a1, a2, a3;
                ldmA(abase + (uint32_t)(mt * 16 * APITCH * 4 + ks * 32), a0, a1, a2, a3);
                #pragma unroll
                for (int nt = 0; nt < 4; ++nt)
                    mma16816(acc[mt][nt], a0, a1, a2, a3, bb[nt].x, bb[nt].y);
            }
        }
    }

    // ---- epilogue ----
    const int h = h0 + w;
    #pragma unroll
    for (int nt = 0; nt < 4; ++nt) {
        const int o = nt * 4 + th;
        const float br_ = __ldg(b_real + o);
        const float bi_ = __ldg(b_imag + o);
        float2* Yrow = g_Y + (((size_t)n * NCH + o) * HH + h) * SU;
        #pragma unroll
        for (int mt = 0; mt < 2; ++mt) {
            const int u0 = ubase + mt * 16 + g;
            const int u1 = u0 + 8;
            if (u0 < NU)
                Yrow[u0] = make_float2(acc[mt][nt][0] + br_, acc[mt][nt][1] + bi_);
            if (u1 < NU)
                Yrow[u1] = make_float2(acc[mt][nt][2] + br_, acc[mt][nt][3] + bi_);
        }
    }
}

__global__ __launch_bounds__(512) void kE_irfft_rows(float* __restrict__ out) {
    __shared__ float2 s[8 * GSTR];
    const int t = threadIdx.x & 63;
    const int g = threadIdx.x >> 6;
    const int img = blockIdx.x >> 5;
    const int pr = (blockIdx.x & 31) * 8 + g;
    const float2* G0 = g_Y + ((size_t)img * HH + 2 * pr) * SU;
    const float2* G1 = G0 + SU;
    float2* z = s + g * GSTR;
    #pragma unroll
    for (int m = 0; m < 5; ++m) {
        const int u = t + 64*m;
        if (u < NU) {
            float2 A = G0[u];
            float2 B = G1[u];
            if (u == 0 || u == 256) { A.y = 0.f; B.y = 0.f; }
            z[u] = make_float2(A.x - B.y, A.y + B.x);
            if (u >= 1 && u <= 255)
                z[512 - u] = make_float2(A.x + B.y, B.x - A.y);
        }
    }
    __syncthreads();
    float2 a[8];
    #pragma unroll
    for (int m = 0; m < 8; ++m) a[m] = z[t + 64*m];
    __syncthreads();
    fft512_regs<+1>(a, t, z);
    float* o0 = out + ((size_t)img * HH + 2 * pr) * WW;
    float* o1 = o0 + WW;
    #pragma unroll
    for (int m = 0; m < 8; ++m) {
        o0[t + 64*m] = a[m].x;
        o1[t + 64*m] = a[m].y;
    }
}

extern "C" void kernel_launch(void* const* d_in, const int* in_sizes, int n_in,
                              void* d_out, int out_size) {
    const float* x      = (const float*)d_in[0];
    const float* w_real = (const float*)d_in[1];
    const float* w_imag = (const float*)d_in[2];
    const float* b_real = (const float*)d_in[3];
    const float* b_imag = (const float*)d_in[4];
    float* out = (float*)d_out;

    cudaFuncSetAttribute(kC_conv_mma, cudaFuncAttributeMaxDynamicSharedMemorySize, KC_SMEM);

    kA_rfft_rows<<<IMGS * 32, 512>>>(x);

    dim3 gB((NU + 7) / 8, IMGS);
    kBD_fft_cols<-1><<<gB, 512>>>(0, 1.0f);

    dim3 gC(9, HH / 16, NBATCH);
    kC_conv_mma<<<gC, 512, KC_SMEM>>>(w_real, w_imag, b_real, b_imag);

    kBD_fft_cols<+1><<<gB, 512>>>(1, 1.0f / (512.0f * 512.0f));

    kE_irfft_rows<<<IMGS * 32, 512>>>(out);
}

// round 8
// speedup vs baseline: 1.5376x; 1.1317x over previous
#include <cuda_runtime.h>
#include <cuda_bf16.h>
#include <cstdint>

#define HH 512
#define WW 512
#define NU 257
#define SU 260
#define NCH 16
#define NBATCH 8
#define IMGS (NBATCH*NCH)
#define GSTR 578

__device__ float2 g_X[(size_t)IMGS * HH * SU];
__device__ float2 g_Y[(size_t)IMGS * HH * SU];

// Precomputed B fragments (weight matrices in mma fragment order)
#define B_U32 (9 * 6 * 4 * 2 * 32)     // 13824
__device__ uint32_t g_Bfrag[B_U32];

__device__ __forceinline__ float2 cmul(float2 a, float2 b) {
    return make_float2(a.x*b.x - a.y*b.y, a.x*b.y + a.y*b.x);
}
__device__ __forceinline__ float2 cadd(float2 a, float2 b) { return make_float2(a.x+b.x, a.y+b.y); }
__device__ __forceinline__ float2 csub(float2 a, float2 b) { return make_float2(a.x-b.x, a.y-b.y); }

// ---------------- radix-8 register FFT ----------------
template<int S>
__device__ __forceinline__ void fft8(float2 a[8]) {
    const float r = 0.7071067811865476f;
    const float sf = (float)S;
    float2 d, u;
    u=a[0]; d=csub(u,a[4]); a[0]=cadd(u,a[4]); a[4]=d;
    u=a[1]; d=csub(u,a[5]); a[1]=cadd(u,a[5]); a[5]=make_float2(r*(d.x - sf*d.y), r*(sf*d.x + d.y));
    u=a[2]; d=csub(u,a[6]); a[2]=cadd(u,a[6]); a[6]=make_float2(-sf*d.y, sf*d.x);
    u=a[3]; d=csub(u,a[7]); a[3]=cadd(u,a[7]); a[7]=make_float2(r*(-d.x - sf*d.y), r*(sf*d.x - d.y));
    u=a[0]; d=csub(u,a[2]); a[0]=cadd(u,a[2]); a[2]=d;
    u=a[1]; d=csub(u,a[3]); a[1]=cadd(u,a[3]); a[3]=make_float2(-sf*d.y, sf*d.x);
    u=a[4]; d=csub(u,a[6]); a[4]=cadd(u,a[6]); a[6]=d;
    u=a[5]; d=csub(u,a[7]); a[5]=cadd(u,a[7]); a[7]=make_float2(-sf*d.y, sf*d.x);
    u=a[0]; a[0]=cadd(u,a[1]); a[1]=csub(u,a[1]);
    u=a[2]; a[2]=cadd(u,a[3]); a[3]=csub(u,a[3]);
    u=a[4]; a[4]=cadd(u,a[5]); a[5]=csub(u,a[5]);
    u=a[6]; a[6]=cadd(u,a[7]); a[7]=csub(u,a[7]);
    d=a[1]; a[1]=a[4]; a[4]=d;
    d=a[3]; a[3]=a[6]; a[6]=d;
}

template<int S>
__device__ __forceinline__ void fft512_regs(float2 a[8], int t, float2* s) {
    const float TWO_PI = 6.283185307179586f;
    const int n2 = t & 7;
    const int n1 = t >> 3;
    fft8<S>(a);
    const float c1 = (float)S * TWO_PI / 64.0f * (float)n1;
    #pragma unroll
    for (int k0 = 1; k0 < 8; ++k0) {
        float sn, cs; __sincosf(c1 * (float)k0, &sn, &cs);
        a[k0] = cmul(a[k0], make_float2(cs, sn));
    }
    #pragma unroll
    for (int k0 = 0; k0 < 8; ++k0) s[t + 72*k0] = a[k0];
    __syncthreads();
    const int k0r = t >> 3;
    #pragma unroll
    for (int j = 0; j < 8; ++j) a[j] = s[n2 + 8*j + 72*k0r];
    __syncthreads();
    fft8<S>(a);
    const float c2 = (float)S * TWO_PI / 512.0f * (float)n2;
    #pragma unroll
    for (int k1 = 0; k1 < 8; ++k1) {
        float sn, cs; __sincosf(c2 * (float)(k0r + 8*k1), &sn, &cs);
        a[k1] = cmul(a[k1], make_float2(cs, sn));
    }
    #pragma unroll
    for (int k1 = 0; k1 < 8; ++k1) s[72*k1 + 8*k0r + (n2 ^ k0r)] = a[k1];
    __syncthreads();
    const int k0b = t & 7, k1r = t >> 3;
    #pragma unroll
    for (int j = 0; j < 8; ++j) a[j] = s[72*k1r + 8*k0b + (j ^ k0b)];
    fft8<S>(a);
}

__global__ __launch_bounds__(512) void kA_rfft_rows(const float* __restrict__ x) {
    __shared__ float2 s[8 * GSTR];
    const int t = threadIdx.x & 63;
    const int g = threadIdx.x >> 6;
    const int img = blockIdx.x >> 5;
    const int pr = (blockIdx.x & 31) * 8 + g;
    const float* r0 = x + ((size_t)img * HH + 2 * pr) * WW;
    const float* r1 = r0 + WW;
    float2 a[8];
    #pragma unroll
    for (int m = 0; m < 8; ++m) a[m] = make_float2(r0[t + 64*m], r1[t + 64*m]);
    float2* z = s + g * GSTR;
    fft512_regs<-1>(a, t, z);
    __syncthreads();
    #pragma unroll
    for (int m = 0; m < 8; ++m) z[t + 64*m] = a[m];
    __syncthreads();
    float2* X0 = g_X + ((size_t)img * HH + 2 * pr) * SU;
    float2* X1 = X0 + SU;
    #pragma unroll
    for (int m = 0; m < 5; ++m) {
        const int u = t + 64*m;
        if (u < NU) {
            const float2 zk = z[u];
            const float2 zm = z[(512 - u) & 511];
            X0[u] = make_float2(0.5f*(zk.x + zm.x),  0.5f*(zk.y - zm.y));
            X1[u] = make_float2(0.5f*(zk.y + zm.y), -0.5f*(zk.x - zm.x));
        }
    }
}

template<int S>
__global__ __launch_bounds__(512) void kBD_fft_cols(int useY, float scale) {
    __shared__ float2 s[8 * GSTR];
    const int g = threadIdx.x & 7;
    const int t = threadIdx.x >> 3;
    const int img = blockIdx.y;
    const int u = blockIdx.x * 8 + g;
    const bool ok = (u < NU);
    float2* data = useY ? g_Y : g_X;
    float2* base = data + (size_t)img * HH * SU + u;
    float2 a[8];
    #pragma unroll
    for (int m = 0; m < 8; ++m)
        a[m] = ok ? base[(size_t)(t + 64*m) * SU] : make_float2(0.f, 0.f);
    fft512_regs<S>(a, t, s + g * GSTR);
    if (ok) {
        #pragma unroll
        for (int m = 0; m < 8; ++m)
            base[(size_t)(t + 64*m) * SU] = make_float2(a[m].x * scale, a[m].y * scale);
    }
}

// ===================== kC machinery =====================
#define APITCH 52
#define HALO_PTS (18 * 34)
#define A_U32 (HALO_PTS * APITCH)
#define KC_SMEM ((A_U32 + B_U32) * 4)

__device__ __forceinline__ uint32_t packbf(float x, float y) {
    __nv_bfloat162 h;
    h.x = __float2bfloat16_rn(x);
    h.y = __float2bfloat16_rn(y);
    uint32_t r;
    *(__nv_bfloat162*)&r = h;
    return r;
}

__device__ __forceinline__ uint32_t smem_u32(const void* p) {
    uint32_t a;
    asm("{ .reg .u64 t; cvta.to.shared.u64 t, %1; cvt.u32.u64 %0, t; }" : "=r"(a) : "l"(p));
    return a;
}

__device__ __forceinline__ void ldmA(uint32_t addr, uint32_t& a0, uint32_t& a1,
                                     uint32_t& a2, uint32_t& a3) {
    asm volatile("ldmatrix.sync.aligned.m8n8.x4.shared.b16 {%0,%1,%2,%3}, [%4];"
                 : "=r"(a0), "=r"(a1), "=r"(a2), "=r"(a3) : "r"(addr));
}

__device__ __forceinline__ void mma16816(float* d, uint32_t a0, uint32_t a1,
                                         uint32_t a2, uint32_t a3,
                                         uint32_t b0, uint32_t b1) {
    asm volatile(
        "mma.sync.aligned.m16n8k16.row.col.f32.bf16.bf16.f32 "
        "{%0,%1,%2,%3}, {%4,%5,%6,%7}, {%8,%9}, {%0,%1,%2,%3};"
        : "+f"(d[0]), "+f"(d[1]), "+f"(d[2]), "+f"(d[3])
        : "r"(a0), "r"(a1), "r"(a2), "r"(a3), "r"(b0), "r"(b1));
}

// ---- one-shot: build B fragments into g_Bfrag ----
__global__ __launch_bounds__(512) void kW_buildB(
    const float* __restrict__ w_real, const float* __restrict__ w_imag)
{
    const int e = blockIdx.x * 512 + threadIdx.x;
    if (e >= B_U32) return;
    const int ln = e & 31;
    const int rr = (e >> 5) & 1;
    const int nt = (e >> 6) & 3;
    const int rem = e >> 8;
    const int ks = rem % 6;
    const int tap = rem / 6;
    const int a = tap / 3, b = tap % 3;
    const int gg = ln >> 2, tt = ln & 3;
    const int n_idx = nt * 8 + gg;
    const int o = n_idx >> 1, cout = n_idx & 1;
    float vals[2];
    #pragma unroll
    for (int q = 0; q < 2; ++q) {
        const int k = ks * 16 + tt * 2 + rr * 8 + q;
        const int half = k >> 5;
        const int i = (k & 31) >> 1;
        const int cin = k & 1;
        const float wr_ = w_real[(i * 16 + o) * 9 + a * 3 + b];
        const float wi_ = w_imag[(i * 16 + o) * 9 + a * 3 + b];
        const float coef = cout ? (cin ? wr_ : wi_) : (cin ? -wi_ : wr_);
        const float chi = __bfloat162float(__float2bfloat16_rn(coef));
        vals[q] = (half < 2) ? chi : (coef - chi);
    }
    g_Bfrag[(tap * 6 + ks) * 256 + nt * 64 + ln * 2 + rr] = packbf(vals[0], vals[1]);
}

__global__ __launch_bounds__(512, 1) void kC_conv_mma(
    const float* __restrict__ b_real, const float* __restrict__ b_imag)
{
    extern __shared__ uint32_t smc[];
    uint32_t* sA = smc;
    uint32_t* sB = smc + A_U32;

    const int t = threadIdx.x;
    const int w = t >> 5;
    const int lane = t & 31;
    const int g = lane >> 2;
    const int th = lane & 3;
    const int ubase = blockIdx.x * 32;
    const int h0 = blockIdx.y * 16;
    const int n = blockIdx.z;

    // ---- B stage: coalesced uint4 copy from precomputed table ----
    {
        const uint4* src = (const uint4*)g_Bfrag;
        uint4* dst = (uint4*)sB;
        #pragma unroll
        for (int e = t; e < B_U32 / 4; e += 512) dst[e] = src[e];
    }

    // ---- A halo fill ----
    for (int e = t; e < HALO_PTS * NCH; e += 512) {
        const int i = e / HALO_PTS;
        const int p = e - i * HALO_PTS;
        const int hr = p / 34;
        const int c = p - hr * 34;
        const int h = h0 - 1 + hr;
        const int u = ubase - 1 + c;
        float2 v = make_float2(0.f, 0.f);
        if (h >= 0 && h < HH && u >= 0 && u < NU)
            v = g_X[(((size_t)n * NCH + i) * HH + h) * SU + u];
        const float hr_ = __bfloat162float(__float2bfloat16_rn(v.x));
        const float hi_ = __bfloat162float(__float2bfloat16_rn(v.y));
        const uint32_t hp = packbf(v.x, v.y);
        const uint32_t lp = packbf(v.x - hr_, v.y - hi_);
        const int base = p * APITCH;
        sA[base + i] = hp;
        sA[base + 16 + i] = lp;
        sA[base + 32 + i] = hp;
    }
    __syncthreads();

    const uint32_t sAb = smem_u32(sA);

    float acc[2][4][4];
    #pragma unroll
    for (int mt = 0; mt < 2; ++mt)
        #pragma unroll
        for (int nt = 0; nt < 4; ++nt)
            #pragma unroll
            for (int q = 0; q < 4; ++q) acc[mt][nt][q] = 0.f;

    const int lrow = (lane & 7) + ((lane >> 3) & 1) * 8;
    const int lkof = (lane >> 4) * 4;

    for (int tap = 0; tap < 9; ++tap) {
        const int a = tap / 3, b = tap % 3;
        const int prow = (w + 2 - a) * 34 + (2 - b);
        const uint32_t abase = sAb + (uint32_t)(((prow + lrow) * APITCH) + lkof) * 4u;
        #pragma unroll
        for (int ks = 0; ks < 6; ++ks) {
            uint2 bb[4];
            const int bbase = (tap * 6 + ks) * 256 + lane * 2;
            #pragma unroll
            for (int nt = 0; nt < 4; ++nt)
                bb[nt] = *(const uint2*)(sB + bbase + nt * 64);
            #pragma unroll
            for (int mt = 0; mt < 2; ++mt) {
                uint32_t a0, a1, a2, a3;
                ldmA(abase + (uint32_t)(mt * 16 * APITCH * 4 + ks * 32), a0, a1, a2, a3);
                #pragma unroll
                for (int nt = 0; nt < 4; ++nt)
                    mma16816(acc[mt][nt], a0, a1, a2, a3, bb[nt].x, bb[nt].y);
            }
        }
    }

    // ---- epilogue ----
    const int h = h0 + w;
    #pragma unroll
    for (int nt = 0; nt < 4; ++nt) {
        const int o = nt * 4 + th;
        const float br_ = __ldg(b_real + o);
        const float bi_ = __ldg(b_imag + o);
        float2* Yrow = g_Y + (((size_t)n * NCH + o) * HH + h) * SU;
        #pragma unroll
        for (int mt = 0; mt < 2; ++mt) {
            const int u0 = ubase + mt * 16 + g;
            const int u1 = u0 + 8;
            if (u0 < NU)
                Yrow[u0] = make_float2(acc[mt][nt][0] + br_, acc[mt][nt][1] + bi_);
            if (u1 < NU)
                Yrow[u1] = make_float2(acc[mt][nt][2] + br_, acc[mt][nt][3] + bi_);
        }
    }
}

__global__ __launch_bounds__(512) void kE_irfft_rows(float* __restrict__ out) {
    __shared__ float2 s[8 * GSTR];
    const int t = threadIdx.x & 63;
    const int g = threadIdx.x >> 6;
    const int img = blockIdx.x >> 5;
    const int pr = (blockIdx.x & 31) * 8 + g;
    const float2* G0 = g_Y + ((size_t)img * HH + 2 * pr) * SU;
    const float2* G1 = G0 + SU;
    float2* z = s + g * GSTR;
    #pragma unroll
    for (int m = 0; m < 5; ++m) {
        const int u = t + 64*m;
        if (u < NU) {
            float2 A = G0[u];
            float2 B = G1[u];
            if (u == 0 || u == 256) { A.y = 0.f; B.y = 0.f; }
            z[u] = make_float2(A.x - B.y, A.y + B.x);
            if (u >= 1 && u <= 255)
                z[512 - u] = make_float2(A.x + B.y, B.x - A.y);
        }
    }
    __syncthreads();
    float2 a[8];
    #pragma unroll
    for (int m = 0; m < 8; ++m) a[m] = z[t + 64*m];
    __syncthreads();
    fft512_regs<+1>(a, t, z);
    float* o0 = out + ((size_t)img * HH + 2 * pr) * WW;
    float* o1 = o0 + WW;
    #pragma unroll
    for (int m = 0; m < 8; ++m) {
        o0[t + 64*m] = a[m].x;
        o1[t + 64*m] = a[m].y;
    }
}

extern "C" void kernel_launch(void* const* d_in, const int* in_sizes, int n_in,
                              void* d_out, int out_size) {
    const float* x      = (const float*)d_in[0];
    const float* w_real = (const float*)d_in[1];
    const float* w_imag = (const float*)d_in[2];
    const float* b_real = (const float*)d_in[3];
    const float* b_imag = (const float*)d_in[4];
    float* out = (float*)d_out;

    cudaFuncSetAttribute(kC_conv_mma, cudaFuncAttributeMaxDynamicSharedMemorySize, KC_SMEM);

    kW_buildB<<<(B_U32 + 511) / 512, 512>>>(w_real, w_imag);

    kA_rfft_rows<<<IMGS * 32, 512>>>(x);

    dim3 gB((NU + 7) / 8, IMGS);
    kBD_fft_cols<-1><<<gB, 512>>>(0, 1.0f);

    dim3 gC(9, HH / 16, NBATCH);
    kC_conv_mma<<<gC, 512, KC_SMEM>>>(b_real, b_imag);

    kBD_fft_cols<+1><<<gB, 512>>>(1, 1.0f / (512.0f * 512.0f));

    kE_irfft_rows<<<IMGS * 32, 512>>>(out);
}

// round 9
// speedup vs baseline: 1.5404x; 1.0018x over previous
#include <cuda_runtime.h>
#include <cuda_bf16.h>
#include <cstdint>

#define HH 512
#define WW 512
#define NU 257
#define SU 260
#define NCH 16
#define NBATCH 8
#define IMGS (NBATCH*NCH)
#define GSTR 578

__device__ float2 g_X[(size_t)IMGS * HH * SU];
__device__ float2 g_Y[(size_t)IMGS * HH * SU];

#define B_U32 (9 * 6 * 4 * 2 * 32)     // 13824
__device__ uint32_t g_Bfrag[B_U32];

__device__ __forceinline__ float2 cmul(float2 a, float2 b) {
    return make_float2(a.x*b.x - a.y*b.y, a.x*b.y + a.y*b.x);
}
__device__ __forceinline__ float2 cadd(float2 a, float2 b) { return make_float2(a.x+b.x, a.y+b.y); }
__device__ __forceinline__ float2 csub(float2 a, float2 b) { return make_float2(a.x-b.x, a.y-b.y); }

// ---------------- radix-8 register FFT ----------------
template<int S>
__device__ __forceinline__ void fft8(float2 a[8]) {
    const float r = 0.7071067811865476f;
    const float sf = (float)S;
    float2 d, u;
    u=a[0]; d=csub(u,a[4]); a[0]=cadd(u,a[4]); a[4]=d;
    u=a[1]; d=csub(u,a[5]); a[1]=cadd(u,a[5]); a[5]=make_float2(r*(d.x - sf*d.y), r*(sf*d.x + d.y));
    u=a[2]; d=csub(u,a[6]); a[2]=cadd(u,a[6]); a[6]=make_float2(-sf*d.y, sf*d.x);
    u=a[3]; d=csub(u,a[7]); a[3]=cadd(u,a[7]); a[7]=make_float2(r*(-d.x - sf*d.y), r*(sf*d.x - d.y));
    u=a[0]; d=csub(u,a[2]); a[0]=cadd(u,a[2]); a[2]=d;
    u=a[1]; d=csub(u,a[3]); a[1]=cadd(u,a[3]); a[3]=make_float2(-sf*d.y, sf*d.x);
    u=a[4]; d=csub(u,a[6]); a[4]=cadd(u,a[6]); a[6]=d;
    u=a[5]; d=csub(u,a[7]); a[5]=cadd(u,a[7]); a[7]=make_float2(-sf*d.y, sf*d.x);
    u=a[0]; a[0]=cadd(u,a[1]); a[1]=csub(u,a[1]);
    u=a[2]; a[2]=cadd(u,a[3]); a[3]=csub(u,a[3]);
    u=a[4]; a[4]=cadd(u,a[5]); a[5]=csub(u,a[5]);
    u=a[6]; a[6]=cadd(u,a[7]); a[7]=csub(u,a[7]);
    d=a[1]; a[1]=a[4]; a[4]=d;
    d=a[3]; a[3]=a[6]; a[6]=d;
}

template<int S>
__device__ __forceinline__ void fft512_regs(float2 a[8], int t, float2* s) {
    const float TWO_PI = 6.283185307179586f;
    const int n2 = t & 7;
    const int n1 = t >> 3;
    fft8<S>(a);
    const float c1 = (float)S * TWO_PI / 64.0f * (float)n1;
    #pragma unroll
    for (int k0 = 1; k0 < 8; ++k0) {
        float sn, cs; __sincosf(c1 * (float)k0, &sn, &cs);
        a[k0] = cmul(a[k0], make_float2(cs, sn));
    }
    #pragma unroll
    for (int k0 = 0; k0 < 8; ++k0) s[t + 72*k0] = a[k0];
    __syncthreads();
    const int k0r = t >> 3;
    #pragma unroll
    for (int j = 0; j < 8; ++j) a[j] = s[n2 + 8*j + 72*k0r];
    __syncthreads();
    fft8<S>(a);
    const float c2 = (float)S * TWO_PI / 512.0f * (float)n2;
    #pragma unroll
    for (int k1 = 0; k1 < 8; ++k1) {
        float sn, cs; __sincosf(c2 * (float)(k0r + 8*k1), &sn, &cs);
        a[k1] = cmul(a[k1], make_float2(cs, sn));
    }
    #pragma unroll
    for (int k1 = 0; k1 < 8; ++k1) s[72*k1 + 8*k0r + (n2 ^ k0r)] = a[k1];
    __syncthreads();
    const int k0b = t & 7, k1r = t >> 3;
    #pragma unroll
    for (int j = 0; j < 8; ++j) a[j] = s[72*k1r + 8*k0b + (j ^ k0b)];
    fft8<S>(a);
}

__global__ __launch_bounds__(512) void kA_rfft_rows(const float* __restrict__ x) {
    __shared__ float2 s[8 * GSTR];
    const int t = threadIdx.x & 63;
    const int g = threadIdx.x >> 6;
    const int img = blockIdx.x >> 5;
    const int pr = (blockIdx.x & 31) * 8 + g;
    const float* r0 = x + ((size_t)img * HH + 2 * pr) * WW;
    const float* r1 = r0 + WW;
    float2 a[8];
    #pragma unroll
    for (int m = 0; m < 8; ++m) a[m] = make_float2(r0[t + 64*m], r1[t + 64*m]);
    float2* z = s + g * GSTR;
    fft512_regs<-1>(a, t, z);
    __syncthreads();
    #pragma unroll
    for (int m = 0; m < 8; ++m) z[t + 64*m] = a[m];
    __syncthreads();
    float2* X0 = g_X + ((size_t)img * HH + 2 * pr) * SU;
    float2* X1 = X0 + SU;
    #pragma unroll
    for (int m = 0; m < 5; ++m) {
        const int u = t + 64*m;
        if (u < NU) {
            const float2 zk = z[u];
            const float2 zm = z[(512 - u) & 511];
            X0[u] = make_float2(0.5f*(zk.x + zm.x),  0.5f*(zk.y - zm.y));
            X1[u] = make_float2(0.5f*(zk.y + zm.y), -0.5f*(zk.x - zm.x));
        }
    }
}

template<int S>
__global__ __launch_bounds__(512) void kBD_fft_cols(int useY, float scale) {
    __shared__ float2 s[8 * GSTR];
    const int g = threadIdx.x & 7;
    const int t = threadIdx.x >> 3;
    const int img = blockIdx.y;
    const int u = blockIdx.x * 8 + g;
    const bool ok = (u < NU);
    float2* data = useY ? g_Y : g_X;
    float2* base = data + (size_t)img * HH * SU + u;
    float2 a[8];
    #pragma unroll
    for (int m = 0; m < 8; ++m)
        a[m] = ok ? base[(size_t)(t + 64*m) * SU] : make_float2(0.f, 0.f);
    fft512_regs<S>(a, t, s + g * GSTR);
    if (ok) {
        #pragma unroll
        for (int m = 0; m < 8; ++m)
            base[(size_t)(t + 64*m) * SU] = make_float2(a[m].x * scale, a[m].y * scale);
    }
}

// ===================== kC machinery =====================
#define APITCH 52
#define HALO_PTS (18 * 34)
#define A_U32 (HALO_PTS * APITCH)
#define KC_SMEM ((A_U32 + B_U32) * 4)

__device__ __forceinline__ uint32_t packbf(float x, float y) {
    __nv_bfloat162 h;
    h.x = __float2bfloat16_rn(x);
    h.y = __float2bfloat16_rn(y);
    uint32_t r;
    *(__nv_bfloat162*)&r = h;
    return r;
}

__device__ __forceinline__ uint32_t smem_u32(const void* p) {
    uint32_t a;
    asm("{ .reg .u64 t; cvta.to.shared.u64 t, %1; cvt.u32.u64 %0, t; }" : "=r"(a) : "l"(p));
    return a;
}

__device__ __forceinline__ void ldmA(uint32_t addr, uint32_t& a0, uint32_t& a1,
                                     uint32_t& a2, uint32_t& a3) {
    asm volatile("ldmatrix.sync.aligned.m8n8.x4.shared.b16 {%0,%1,%2,%3}, [%4];"
                 : "=r"(a0), "=r"(a1), "=r"(a2), "=r"(a3) : "r"(addr));
}

__device__ __forceinline__ void mma16816(float* d, uint32_t a0, uint32_t a1,
                                         uint32_t a2, uint32_t a3,
                                         uint32_t b0, uint32_t b1) {
    asm volatile(
        "mma.sync.aligned.m16n8k16.row.col.f32.bf16.bf16.f32 "
        "{%0,%1,%2,%3}, {%4,%5,%6,%7}, {%8,%9}, {%0,%1,%2,%3};"
        : "+f"(d[0]), "+f"(d[1]), "+f"(d[2]), "+f"(d[3])
        : "r"(a0), "r"(a1), "r"(a2), "r"(a3), "r"(b0), "r"(b1));
}

__global__ __launch_bounds__(512) void kW_buildB(
    const float* __restrict__ w_real, const float* __restrict__ w_imag)
{
    const int e = blockIdx.x * 512 + threadIdx.x;
    if (e >= B_U32) return;
    const int ln = e & 31;
    const int rr = (e >> 5) & 1;
    const int nt = (e >> 6) & 3;
    const int rem = e >> 8;
    const int ks = rem % 6;
    const int tap = rem / 6;
    const int a = tap / 3, b = tap % 3;
    const int gg = ln >> 2, tt = ln & 3;
    const int n_idx = nt * 8 + gg;
    const int o = n_idx >> 1, cout = n_idx & 1;
    float vals[2];
    #pragma unroll
    for (int q = 0; q < 2; ++q) {
        const int k = ks * 16 + tt * 2 + rr * 8 + q;
        const int half = k >> 5;
        const int i = (k & 31) >> 1;
        const int cin = k & 1;
        const float wr_ = w_real[(i * 16 + o) * 9 + a * 3 + b];
        const float wi_ = w_imag[(i * 16 + o) * 9 + a * 3 + b];
        const float coef = cout ? (cin ? wr_ : wi_) : (cin ? -wi_ : wr_);
        const float chi = __bfloat162float(__float2bfloat16_rn(coef));
        vals[q] = (half < 2) ? chi : (coef - chi);
    }
    g_Bfrag[(tap * 6 + ks) * 256 + nt * 64 + ln * 2 + rr] = packbf(vals[0], vals[1]);
}

__global__ __launch_bounds__(512, 1) void kC_conv_mma(
    const float* __restrict__ b_real, const float* __restrict__ b_imag)
{
    extern __shared__ uint32_t smc[];
    uint32_t* sA = smc;
    uint32_t* sB = smc + A_U32;

    const int t = threadIdx.x;
    const int w = t >> 5;
    const int lane = t & 31;
    const int g = lane >> 2;
    const int th = lane & 3;
    const int ubase = blockIdx.x * 32;
    const int h0 = blockIdx.y * 16;
    const int n = blockIdx.z;

    // B stage (coalesced copy)
    {
        const uint4* src = (const uint4*)g_Bfrag;
        uint4* dst = (uint4*)sB;
        #pragma unroll
        for (int e = t; e < B_U32 / 4; e += 512) dst[e] = src[e];
    }

    // A halo fill
    for (int e = t; e < HALO_PTS * NCH; e += 512) {
        const int i = e / HALO_PTS;
        const int p = e - i * HALO_PTS;
        const int hr = p / 34;
        const int c = p - hr * 34;
        const int h = h0 - 1 + hr;
        const int u = ubase - 1 + c;
        float2 v = make_float2(0.f, 0.f);
        if (h >= 0 && h < HH && u >= 0 && u < NU)
            v = g_X[(((size_t)n * NCH + i) * HH + h) * SU + u];
        const float hr_ = __bfloat162float(__float2bfloat16_rn(v.x));
        const float hi_ = __bfloat162float(__float2bfloat16_rn(v.y));
        const uint32_t hp = packbf(v.x, v.y);
        const uint32_t lp = packbf(v.x - hr_, v.y - hi_);
        const int base = p * APITCH;
        sA[base + i] = hp;
        sA[base + 16 + i] = lp;
        sA[base + 32 + i] = hp;
    }
    __syncthreads();

    const uint32_t sAb = smem_u32(sA);

    float acc[2][4][4];
    #pragma unroll
    for (int mt = 0; mt < 2; ++mt)
        #pragma unroll
        for (int nt = 0; nt < 4; ++nt)
            #pragma unroll
            for (int q = 0; q < 4; ++q) acc[mt][nt][q] = 0.f;

    const int lrow = (lane & 7) + ((lane >> 3) & 1) * 8;
    const int lkof = (lane >> 4) * 4;

    // Software-pipelined mainloop: 54 iterations, double-buffered fragments.
    uint2 bb[2][4];
    uint32_t af[2][2][4];

    #define LOAD_IT(IT, BUF)                                                       \
    do {                                                                           \
        const int _tap = (IT) / 6, _ks = (IT) % 6;                                 \
        const int _a = _tap / 3, _b = _tap % 3;                                    \
        const int _prow = (w + 2 - _a) * 34 + (2 - _b);                            \
        const int _bbase = (IT) * 256 + lane * 2;                                  \
        bb[BUF][0] = *(const uint2*)(sB + _bbase);                                 \
        bb[BUF][1] = *(const uint2*)(sB + _bbase + 64);                            \
        bb[BUF][2] = *(const uint2*)(sB + _bbase + 128);                           \
        bb[BUF][3] = *(const uint2*)(sB + _bbase + 192);                           \
        const uint32_t _ab = sAb +                                                 \
            (uint32_t)(((_prow + lrow) * APITCH) + lkof + _ks * 8) * 4u;           \
        ldmA(_ab, af[BUF][0][0], af[BUF][0][1], af[BUF][0][2], af[BUF][0][3]);     \
        ldmA(_ab + 16u * APITCH * 4u,                                              \
             af[BUF][1][0], af[BUF][1][1], af[BUF][1][2], af[BUF][1][3]);          \
    } while (0)

    LOAD_IT(0, 0);
    #pragma unroll
    for (int it = 0; it < 54; ++it) {
        const int cb = it & 1;
        const int nb = cb ^ 1;
        if (it < 53) LOAD_IT(it + 1, nb);
        #pragma unroll
        for (int mt = 0; mt < 2; ++mt)
            #pragma unroll
            for (int nt = 0; nt < 4; ++nt)
                mma16816(acc[mt][nt], af[cb][mt][0], af[cb][mt][1],
                         af[cb][mt][2], af[cb][mt][3], bb[cb][nt].x, bb[cb][nt].y);
    }
    #undef LOAD_IT

    // epilogue
    const int h = h0 + w;
    #pragma unroll
    for (int nt = 0; nt < 4; ++nt) {
        const int o = nt * 4 + th;
        const float br_ = __ldg(b_real + o);
        const float bi_ = __ldg(b_imag + o);
        float2* Yrow = g_Y + (((size_t)n * NCH + o) * HH + h) * SU;
        #pragma unroll
        for (int mt = 0; mt < 2; ++mt) {
            const int u0 = ubase + mt * 16 + g;
            const int u1 = u0 + 8;
            if (u0 < NU)
                Yrow[u0] = make_float2(acc[mt][nt][0] + br_, acc[mt][nt][1] + bi_);
            if (u1 < NU)
                Yrow[u1] = make_float2(acc[mt][nt][2] + br_, acc[mt][nt][3] + bi_);
        }
    }
}

__global__ __launch_bounds__(512) void kE_irfft_rows(float* __restrict__ out) {
    __shared__ float2 s[8 * GSTR];
    const int t = threadIdx.x & 63;
    const int g = threadIdx.x >> 6;
    const int img = blockIdx.x >> 5;
    const int pr = (blockIdx.x & 31) * 8 + g;
    const float2* G0 = g_Y + ((size_t)img * HH + 2 * pr) * SU;
    const float2* G1 = G0 + SU;
    float2* z = s + g * GSTR;
    #pragma unroll
    for (int m = 0; m < 5; ++m) {
        const int u = t + 64*m;
        if (u < NU) {
            float2 A = G0[u];
            float2 B = G1[u];
            if (u == 0 || u == 256) { A.y = 0.f; B.y = 0.f; }
            z[u] = make_float2(A.x - B.y, A.y + B.x);
            if (u >= 1 && u <= 255)
                z[512 - u] = make_float2(A.x + B.y, B.x - A.y);
        }
    }
    __syncthreads();
    float2 a[8];
    #pragma unroll
    for (int m = 0; m < 8; ++m) a[m] = z[t + 64*m];
    __syncthreads();
    fft512_regs<+1>(a, t, z);
    float* o0 = out + ((size_t)img * HH + 2 * pr) * WW;
    float* o1 = o0 + WW;
    #pragma unroll
    for (int m = 0; m < 8; ++m) {
        o0[t + 64*m] = a[m].x;
        o1[t + 64*m] = a[m].y;
    }
}

extern "C" void kernel_launch(void* const* d_in, const int* in_sizes, int n_in,
                              void* d_out, int out_size) {
    const float* x      = (const float*)d_in[0];
    const float* w_real = (const float*)d_in[1];
    const float* w_imag = (const float*)d_in[2];
    const float* b_real = (const float*)d_in[3];
    const float* b_imag = (const float*)d_in[4];
    float* out = (float*)d_out;

    cudaFuncSetAttribute(kC_conv_mma, cudaFuncAttributeMaxDynamicSharedMemorySize, KC_SMEM);

    kW_buildB<<<(B_U32 + 511) / 512, 512>>>(w_real, w_imag);

    kA_rfft_rows<<<IMGS * 32, 512>>>(x);

    dim3 gB((NU + 7) / 8, IMGS);
    kBD_fft_cols<-1><<<gB, 512>>>(0, 1.0f);

    dim3 gC(9, HH / 16, NBATCH);
    kC_conv_mma<<<gC, 512, KC_SMEM>>>(b_real, b_imag);

    kBD_fft_cols<+1><<<gB, 512>>>(1, 1.0f / (512.0f * 512.0f));

    kE_irfft_rows<<<IMGS * 32, 512>>>(out);
}

// round 10
// speedup vs baseline: 1.6673x; 1.0824x over previous
#include <cuda_runtime.h>
#include <cuda_bf16.h>
#include <cstdint>

#define HH 512
#define WW 512
#define NU 257
#define SU 260
#define NCH 16
#define NBATCH 8
#define IMGS (NBATCH*NCH)
#define GSTR 578

__device__ float2 g_X[(size_t)IMGS * HH * SU];
__device__ float2 g_Y[(size_t)IMGS * HH * SU];

#define B_U32 (9 * 6 * 4 * 2 * 32)     // 13824
__device__ uint32_t g_Bfrag[B_U32];

__device__ __forceinline__ float2 cmul(float2 a, float2 b) {
    return make_float2(a.x*b.x - a.y*b.y, a.x*b.y + a.y*b.x);
}
__device__ __forceinline__ float2 cadd(float2 a, float2 b) { return make_float2(a.x+b.x, a.y+b.y); }
__device__ __forceinline__ float2 csub(float2 a, float2 b) { return make_float2(a.x-b.x, a.y-b.y); }

// ---------------- radix-8 register FFT ----------------
template<int S>
__device__ __forceinline__ void fft8(float2 a[8]) {
    const float r = 0.7071067811865476f;
    const float sf = (float)S;
    float2 d, u;
    u=a[0]; d=csub(u,a[4]); a[0]=cadd(u,a[4]); a[4]=d;
    u=a[1]; d=csub(u,a[5]); a[1]=cadd(u,a[5]); a[5]=make_float2(r*(d.x - sf*d.y), r*(sf*d.x + d.y));
    u=a[2]; d=csub(u,a[6]); a[2]=cadd(u,a[6]); a[6]=make_float2(-sf*d.y, sf*d.x);
    u=a[3]; d=csub(u,a[7]); a[3]=cadd(u,a[7]); a[7]=make_float2(r*(-d.x - sf*d.y), r*(sf*d.x - d.y));
    u=a[0]; d=csub(u,a[2]); a[0]=cadd(u,a[2]); a[2]=d;
    u=a[1]; d=csub(u,a[3]); a[1]=cadd(u,a[3]); a[3]=make_float2(-sf*d.y, sf*d.x);
    u=a[4]; d=csub(u,a[6]); a[4]=cadd(u,a[6]); a[6]=d;
    u=a[5]; d=csub(u,a[7]); a[5]=cadd(u,a[7]); a[7]=make_float2(-sf*d.y, sf*d.x);
    u=a[0]; a[0]=cadd(u,a[1]); a[1]=csub(u,a[1]);
    u=a[2]; a[2]=cadd(u,a[3]); a[3]=csub(u,a[3]);
    u=a[4]; a[4]=cadd(u,a[5]); a[5]=csub(u,a[5]);
    u=a[6]; a[6]=cadd(u,a[7]); a[7]=csub(u,a[7]);
    d=a[1]; a[1]=a[4]; a[4]=d;
    d=a[3]; a[3]=a[6]; a[6]=d;
}

template<int S>
__device__ __forceinline__ void fft512_regs(float2 a[8], int t, float2* s) {
    const float TWO_PI = 6.283185307179586f;
    const int n2 = t & 7;
    const int n1 = t >> 3;
    fft8<S>(a);
    const float c1 = (float)S * TWO_PI / 64.0f * (float)n1;
    #pragma unroll
    for (int k0 = 1; k0 < 8; ++k0) {
        float sn, cs; __sincosf(c1 * (float)k0, &sn, &cs);
        a[k0] = cmul(a[k0], make_float2(cs, sn));
    }
    #pragma unroll
    for (int k0 = 0; k0 < 8; ++k0) s[t + 72*k0] = a[k0];
    __syncthreads();
    const int k0r = t >> 3;
    #pragma unroll
    for (int j = 0; j < 8; ++j) a[j] = s[n2 + 8*j + 72*k0r];
    __syncthreads();
    fft8<S>(a);
    const float c2 = (float)S * TWO_PI / 512.0f * (float)n2;
    #pragma unroll
    for (int k1 = 0; k1 < 8; ++k1) {
        float sn, cs; __sincosf(c2 * (float)(k0r + 8*k1), &sn, &cs);
        a[k1] = cmul(a[k1], make_float2(cs, sn));
    }
    #pragma unroll
    for (int k1 = 0; k1 < 8; ++k1) s[72*k1 + 8*k0r + (n2 ^ k0r)] = a[k1];
    __syncthreads();
    const int k0b = t & 7, k1r = t >> 3;
    #pragma unroll
    for (int j = 0; j < 8; ++j) a[j] = s[72*k1r + 8*k0b + (j ^ k0b)];
    fft8<S>(a);
}

__global__ __launch_bounds__(512) void kA_rfft_rows(const float* __restrict__ x) {
    __shared__ float2 s[8 * GSTR];
    const int t = threadIdx.x & 63;
    const int g = threadIdx.x >> 6;
    const int img = blockIdx.x >> 5;
    const int pr = (blockIdx.x & 31) * 8 + g;
    const float* r0 = x + ((size_t)img * HH + 2 * pr) * WW;
    const float* r1 = r0 + WW;
    float2 a[8];
    #pragma unroll
    for (int m = 0; m < 8; ++m) a[m] = make_float2(r0[t + 64*m], r1[t + 64*m]);
    float2* z = s + g * GSTR;
    fft512_regs<-1>(a, t, z);
    __syncthreads();
    #pragma unroll
    for (int m = 0; m < 8; ++m) z[t + 64*m] = a[m];
    __syncthreads();
    float2* X0 = g_X + ((size_t)img * HH + 2 * pr) * SU;
    float2* X1 = X0 + SU;
    #pragma unroll
    for (int m = 0; m < 5; ++m) {
        const int u = t + 64*m;
        if (u < NU) {
            const float2 zk = z[u];
            const float2 zm = z[(512 - u) & 511];
            X0[u] = make_float2(0.5f*(zk.x + zm.x),  0.5f*(zk.y - zm.y));
            X1[u] = make_float2(0.5f*(zk.y + zm.y), -0.5f*(zk.x - zm.x));
        }
    }
}

template<int S>
__global__ __launch_bounds__(512) void kBD_fft_cols(int useY, float scale) {
    __shared__ float2 s[8 * GSTR];
    const int g = threadIdx.x & 7;
    const int t = threadIdx.x >> 3;
    const int img = blockIdx.y;
    const int u = blockIdx.x * 8 + g;
    const bool ok = (u < NU);
    float2* data = useY ? g_Y : g_X;
    float2* base = data + (size_t)img * HH * SU + u;
    float2 a[8];
    #pragma unroll
    for (int m = 0; m < 8; ++m)
        a[m] = ok ? base[(size_t)(t + 64*m) * SU] : make_float2(0.f, 0.f);
    fft512_regs<S>(a, t, s + g * GSTR);
    if (ok) {
        #pragma unroll
        for (int m = 0; m < 8; ++m)
            base[(size_t)(t + 64*m) * SU] = make_float2(a[m].x * scale, a[m].y * scale);
    }
}

// ===================== kC machinery =====================
#define APITCH 36                      // u32 per point: [hi(16)|lo(16)] + 4 pad
#define HALO_ROWS 10                   // 8 payload h-lines + 2 halo
#define HALO_PTS (HALO_ROWS * 34)      // 340
#define A_U32 (HALO_PTS * APITCH)      // 12240
#define KC_SMEM ((A_U32 + B_U32) * 4)  // 104256 B -> 2 CTAs/SM

__device__ __forceinline__ uint32_t packbf(float x, float y) {
    __nv_bfloat162 h;
    h.x = __float2bfloat16_rn(x);
    h.y = __float2bfloat16_rn(y);
    uint32_t r;
    *(__nv_bfloat162*)&r = h;
    return r;
}

__device__ __forceinline__ uint32_t smem_u32(const void* p) {
    uint32_t a;
    asm("{ .reg .u64 t; cvta.to.shared.u64 t, %1; cvt.u32.u64 %0, t; }" : "=r"(a) : "l"(p));
    return a;
}

__device__ __forceinline__ void ldmA(uint32_t addr, uint32_t& a0, uint32_t& a1,
                                     uint32_t& a2, uint32_t& a3) {
    asm volatile("ldmatrix.sync.aligned.m8n8.x4.shared.b16 {%0,%1,%2,%3}, [%4];"
                 : "=r"(a0), "=r"(a1), "=r"(a2), "=r"(a3) : "r"(addr));
}

__device__ __forceinline__ void mma16816(float* d, uint32_t a0, uint32_t a1,
                                         uint32_t a2, uint32_t a3,
                                         uint32_t b0, uint32_t b1) {
    asm volatile(
        "mma.sync.aligned.m16n8k16.row.col.f32.bf16.bf16.f32 "
        "{%0,%1,%2,%3}, {%4,%5,%6,%7}, {%8,%9}, {%0,%1,%2,%3};"
        : "+f"(d[0]), "+f"(d[1]), "+f"(d[2]), "+f"(d[3])
        : "r"(a0), "r"(a1), "r"(a2), "r"(a3), "r"(b0), "r"(b1));
}

__global__ __launch_bounds__(512) void kW_buildB(
    const float* __restrict__ w_real, const float* __restrict__ w_imag)
{
    const int e = blockIdx.x * 512 + threadIdx.x;
    if (e >= B_U32) return;
    const int ln = e & 31;
    const int rr = (e >> 5) & 1;
    const int nt = (e >> 6) & 3;
    const int rem = e >> 8;
    const int ks = rem % 6;
    const int tap = rem / 6;
    const int a = tap / 3, b = tap % 3;
    const int gg = ln >> 2, tt = ln & 3;
    const int n_idx = nt * 8 + gg;
    const int o = n_idx >> 1, cout = n_idx & 1;
    float vals[2];
    #pragma unroll
    for (int q = 0; q < 2; ++q) {
        const int k = ks * 16 + tt * 2 + rr * 8 + q;
        const int half = k >> 5;
        const int i = (k & 31) >> 1;
        const int cin = k & 1;
        const float wr_ = w_real[(i * 16 + o) * 9 + a * 3 + b];
        const float wi_ = w_imag[(i * 16 + o) * 9 + a * 3 + b];
        const float coef = cout ? (cin ? wr_ : wi_) : (cin ? -wi_ : wr_);
        const float chi = __bfloat162float(__float2bfloat16_rn(coef));
        vals[q] = (half < 2) ? chi : (coef - chi);
    }
    g_Bfrag[(tap * 6 + ks) * 256 + nt * 64 + ln * 2 + rr] = packbf(vals[0], vals[1]);
}

__global__ __launch_bounds__(512, 2) void kC_conv_mma(
    const float* __restrict__ b_real, const float* __restrict__ b_imag)
{
    extern __shared__ uint32_t smc[];
    uint32_t* sA = smc;
    uint32_t* sB = smc + A_U32;

    const int t = threadIdx.x;
    const int w = t >> 5;
    const int lane = t & 31;
    const int g = lane >> 2;
    const int th = lane & 3;
    const int ubase = blockIdx.x * 32;
    const int h0 = blockIdx.y * 8;
    const int n = blockIdx.z;
    const int l = w >> 1;          // h-line within tile (0..7)
    const int usub = w & 1;        // which 16-u half of the line

    // B stage (coalesced copy; table is L2-resident)
    {
        const uint4* src = (const uint4*)g_Bfrag;
        uint4* dst = (uint4*)sB;
        #pragma unroll
        for (int e = t; e < B_U32 / 4; e += 512) dst[e] = src[e];
    }

    // A halo fill: [hi(16)|lo(16)] u32 per point
    for (int e = t; e < HALO_PTS * NCH; e += 512) {
        const int i = e / HALO_PTS;
        const int p = e - i * HALO_PTS;
        const int hr = p / 34;
        const int c = p - hr * 34;
        const int h = h0 - 1 + hr;
        const int u = ubase - 1 + c;
        float2 v = make_float2(0.f, 0.f);
        if (h >= 0 && h < HH && u >= 0 && u < NU)
            v = g_X[(((size_t)n * NCH + i) * HH + h) * SU + u];
        const float hr_ = __bfloat162float(__float2bfloat16_rn(v.x));
        const float hi_ = __bfloat162float(__float2bfloat16_rn(v.y));
        const int base = p * APITCH;
        sA[base + i] = packbf(v.x, v.y);
        sA[base + 16 + i] = packbf(v.x - hr_, v.y - hi_);
    }
    __syncthreads();

    const uint32_t sAb = smem_u32(sA);

    float acc[4][4];
    #pragma unroll
    for (int nt = 0; nt < 4; ++nt)
        #pragma unroll
        for (int q = 0; q < 4; ++q) acc[nt][q] = 0.f;

    const int lrow = (lane & 7) + ((lane >> 3) & 1) * 8;
    const int lkof = (lane >> 4) * 4;

    // Pipelined mainloop: 54 iterations (tap*6+ks), double-buffered.
    uint2 bb[2][4];
    uint32_t af[2][4];

    #define LOAD_IT(IT, BUF)                                                       \
    do {                                                                           \
        const int _tap = (IT) / 6, _ks = (IT) % 6;                                 \
        const int _a = _tap / 3, _b = _tap % 3;                                    \
        const int _prow = (l + 2 - _a) * 34 + (2 - _b) + usub * 16;                \
        const int _bbase = (IT) * 256 + lane * 2;                                  \
        bb[BUF][0] = *(const uint2*)(sB + _bbase);                                 \
        bb[BUF][1] = *(const uint2*)(sB + _bbase + 64);                            \
        bb[BUF][2] = *(const uint2*)(sB + _bbase + 128);                           \
        bb[BUF][3] = *(const uint2*)(sB + _bbase + 192);                           \
        const int _aoff = (_ks < 4) ? _ks * 8 : (_ks - 4) * 8;                     \
        const uint32_t _ab = sAb +                                                 \
            (uint32_t)(((_prow + lrow) * APITCH) + lkof + _aoff) * 4u;             \
        ldmA(_ab, af[BUF][0], af[BUF][1], af[BUF][2], af[BUF][3]);                 \
    } while (0)

    LOAD_IT(0, 0);
    #pragma unroll
    for (int it = 0; it < 54; ++it) {
        const int cb = it & 1;
        const int nb = cb ^ 1;
        if (it < 53) LOAD_IT(it + 1, nb);
        #pragma unroll
        for (int nt = 0; nt < 4; ++nt)
            mma16816(acc[nt], af[cb][0], af[cb][1], af[cb][2], af[cb][3],
                     bb[cb][nt].x, bb[cb][nt].y);
    }
    #undef LOAD_IT

    // epilogue: lane owns (re,im) for outch o = nt*4+th at u0, u0+8
    const int h = h0 + l;
    #pragma unroll
    for (int nt = 0; nt < 4; ++nt) {
        const int o = nt * 4 + th;
        const float br_ = __ldg(b_real + o);
        const float bi_ = __ldg(b_imag + o);
        float2* Yrow = g_Y + (((size_t)n * NCH + o) * HH + h) * SU;
        const int u0 = ubase + usub * 16 + g;
        const int u1 = u0 + 8;
        if (u0 < NU)
            Yrow[u0] = make_float2(acc[nt][0] + br_, acc[nt][1] + bi_);
        if (u1 < NU)
            Yrow[u1] = make_float2(acc[nt][2] + br_, acc[nt][3] + bi_);
    }
}

__global__ __launch_bounds__(512) void kE_irfft_rows(float* __restrict__ out) {
    __shared__ float2 s[8 * GSTR];
    const int t = threadIdx.x & 63;
    const int g = threadIdx.x >> 6;
    const int img = blockIdx.x >> 5;
    const int pr = (blockIdx.x & 31) * 8 + g;
    const float2* G0 = g_Y + ((size_t)img * HH + 2 * pr) * SU;
    const float2* G1 = G0 + SU;
    float2* z = s + g * GSTR;
    #pragma unroll
    for (int m = 0; m < 5; ++m) {
        const int u = t + 64*m;
        if (u < NU) {
            float2 A = G0[u];
            float2 B = G1[u];
            if (u == 0 || u == 256) { A.y = 0.f; B.y = 0.f; }
            z[u] = make_float2(A.x - B.y, A.y + B.x);
            if (u >= 1 && u <= 255)
                z[512 - u] = make_float2(A.x + B.y, B.x - A.y);
        }
    }
    __syncthreads();
    float2 a[8];
    #pragma unroll
    for (int m = 0; m < 8; ++m) a[m] = z[t + 64*m];
    __syncthreads();
    fft512_regs<+1>(a, t, z);
    float* o0 = out + ((size_t)img * HH + 2 * pr) * WW;
    float* o1 = o0 + WW;
    #pragma unroll
    for (int m = 0; m < 8; ++m) {
        o0[t + 64*m] = a[m].x;
        o1[t + 64*m] = a[m].y;
    }
}

extern "C" void kernel_launch(void* const* d_in, const int* in_sizes, int n_in,
                              void* d_out, int out_size) {
    const float* x      = (const float*)d_in[0];
    const float* w_real = (const float*)d_in[1];
    const float* w_imag = (const float*)d_in[2];
    const float* b_real = (const float*)d_in[3];
    const float* b_imag = (const float*)d_in[4];
    float* out = (float*)d_out;

    cudaFuncSetAttribute(kC_conv_mma, cudaFuncAttributeMaxDynamicSharedMemorySize, KC_SMEM);

    kW_buildB<<<(B_U32 + 511) / 512, 512>>>(w_real, w_imag);

    kA_rfft_rows<<<IMGS * 32, 512>>>(x);

    dim3 gB((NU + 7) / 8, IMGS);
    kBD_fft_cols<-1><<<gB, 512>>>(0, 1.0f);

    dim3 gC(9, HH / 8, NBATCH);
    kC_conv_mma<<<gC, 512, KC_SMEM>>>(b_real, b_imag);

    kBD_fft_cols<+1><<<gB, 512>>>(1, 1.0f / (512.0f * 512.0f));

    kE_irfft_rows<<<IMGS * 32, 512>>>(out);
}

// round 12
// speedup vs baseline: 2.0387x; 1.2228x over previous
#include <cuda_runtime.h>
#include <cuda_fp16.h>
#include <cstdint>

#define HH 512
#define WW 512
#define NU 257
#define SU 260
#define NCH 16
#define NBATCH 8
#define IMGS (NBATCH*NCH)
#define GSTR 578

__device__ float2 g_X[(size_t)IMGS * HH * SU];
__device__ float2 g_Y[(size_t)IMGS * HH * SU];

#define B_U32 (9 * 2 * 4 * 2 * 32)     // 4608: [tap][chunk][nt][ln*2+rr]
__device__ uint32_t g_Bfrag[B_U32];

__device__ __forceinline__ float2 cmul(float2 a, float2 b) {
    return make_float2(a.x*b.x - a.y*b.y, a.x*b.y + a.y*b.x);
}
__device__ __forceinline__ float2 cadd(float2 a, float2 b) { return make_float2(a.x+b.x, a.y+b.y); }
__device__ __forceinline__ float2 csub(float2 a, float2 b) { return make_float2(a.x-b.x, a.y-b.y); }

// ---------------- radix-8 register FFT ----------------
template<int S>
__device__ __forceinline__ void fft8(float2 a[8]) {
    const float r = 0.7071067811865476f;
    const float sf = (float)S;
    float2 d, u;
    u=a[0]; d=csub(u,a[4]); a[0]=cadd(u,a[4]); a[4]=d;
    u=a[1]; d=csub(u,a[5]); a[1]=cadd(u,a[5]); a[5]=make_float2(r*(d.x - sf*d.y), r*(sf*d.x + d.y));
    u=a[2]; d=csub(u,a[6]); a[2]=cadd(u,a[6]); a[6]=make_float2(-sf*d.y, sf*d.x);
    u=a[3]; d=csub(u,a[7]); a[3]=cadd(u,a[7]); a[7]=make_float2(r*(-d.x - sf*d.y), r*(sf*d.x - d.y));
    u=a[0]; d=csub(u,a[2]); a[0]=cadd(u,a[2]); a[2]=d;
    u=a[1]; d=csub(u,a[3]); a[1]=cadd(u,a[3]); a[3]=make_float2(-sf*d.y, sf*d.x);
    u=a[4]; d=csub(u,a[6]); a[4]=cadd(u,a[6]); a[6]=d;
    u=a[5]; d=csub(u,a[7]); a[5]=cadd(u,a[7]); a[7]=make_float2(-sf*d.y, sf*d.x);
    u=a[0]; a[0]=cadd(u,a[1]); a[1]=csub(u,a[1]);
    u=a[2]; a[2]=cadd(u,a[3]); a[3]=csub(u,a[3]);
    u=a[4]; a[4]=cadd(u,a[5]); a[5]=csub(u,a[5]);
    u=a[6]; a[6]=cadd(u,a[7]); a[7]=csub(u,a[7]);
    d=a[1]; a[1]=a[4]; a[4]=d;
    d=a[3]; a[3]=a[6]; a[6]=d;
}

template<int S>
__device__ __forceinline__ void fft512_regs(float2 a[8], int t, float2* s) {
    const float TWO_PI = 6.283185307179586f;
    const int n2 = t & 7;
    const int n1 = t >> 3;
    fft8<S>(a);
    const float c1 = (float)S * TWO_PI / 64.0f * (float)n1;
    #pragma unroll
    for (int k0 = 1; k0 < 8; ++k0) {
        float sn, cs; __sincosf(c1 * (float)k0, &sn, &cs);
        a[k0] = cmul(a[k0], make_float2(cs, sn));
    }
    #pragma unroll
    for (int k0 = 0; k0 < 8; ++k0) s[t + 72*k0] = a[k0];
    __syncthreads();
    const int k0r = t >> 3;
    #pragma unroll
    for (int j = 0; j < 8; ++j) a[j] = s[n2 + 8*j + 72*k0r];
    __syncthreads();
    fft8<S>(a);
    const float c2 = (float)S * TWO_PI / 512.0f * (float)n2;
    #pragma unroll
    for (int k1 = 0; k1 < 8; ++k1) {
        float sn, cs; __sincosf(c2 * (float)(k0r + 8*k1), &sn, &cs);
        a[k1] = cmul(a[k1], make_float2(cs, sn));
    }
    #pragma unroll
    for (int k1 = 0; k1 < 8; ++k1) s[72*k1 + 8*k0r + (n2 ^ k0r)] = a[k1];
    __syncthreads();
    const int k0b = t & 7, k1r = t >> 3;
    #pragma unroll
    for (int j = 0; j < 8; ++j) a[j] = s[72*k1r + 8*k0b + (j ^ k0b)];
    fft8<S>(a);
}

__global__ __launch_bounds__(512) void kA_rfft_rows(const float* __restrict__ x) {
    __shared__ float2 s[8 * GSTR];
    const int t = threadIdx.x & 63;
    const int g = threadIdx.x >> 6;
    const int img = blockIdx.x >> 5;
    const int pr = (blockIdx.x & 31) * 8 + g;
    const float* r0 = x + ((size_t)img * HH + 2 * pr) * WW;
    const float* r1 = r0 + WW;
    float2 a[8];
    #pragma unroll
    for (int m = 0; m < 8; ++m) a[m] = make_float2(r0[t + 64*m], r1[t + 64*m]);
    float2* z = s + g * GSTR;
    fft512_regs<-1>(a, t, z);
    __syncthreads();
    #pragma unroll
    for (int m = 0; m < 8; ++m) z[t + 64*m] = a[m];
    __syncthreads();
    float2* X0 = g_X + ((size_t)img * HH + 2 * pr) * SU;
    float2* X1 = X0 + SU;
    #pragma unroll
    for (int m = 0; m < 5; ++m) {
        const int u = t + 64*m;
        if (u < NU) {
            const float2 zk = z[u];
            const float2 zm = z[(512 - u) & 511];
            X0[u] = make_float2(0.5f*(zk.x + zm.x),  0.5f*(zk.y - zm.y));
            X1[u] = make_float2(0.5f*(zk.y + zm.y), -0.5f*(zk.x - zm.x));
        }
    }
}

template<int S>
__global__ __launch_bounds__(512) void kBD_fft_cols(int useY, float scale) {
    __shared__ float2 s[8 * GSTR];
    const int g = threadIdx.x & 7;
    const int t = threadIdx.x >> 3;
    const int img = blockIdx.y;
    const int u = blockIdx.x * 8 + g;
    const bool ok = (u < NU);
    float2* data = useY ? g_Y : g_X;
    float2* base = data + (size_t)img * HH * SU + u;
    float2 a[8];
    #pragma unroll
    for (int m = 0; m < 8; ++m)
        a[m] = ok ? base[(size_t)(t + 64*m) * SU] : make_float2(0.f, 0.f);
    fft512_regs<S>(a, t, s + g * GSTR);
    if (ok) {
        #pragma unroll
        for (int m = 0; m < 8; ++m)
            base[(size_t)(t + 64*m) * SU] = make_float2(a[m].x * scale, a[m].y * scale);
    }
}

// ===================== kC machinery (fp16 split, K=64) =====================
#define APITCH 36                      // u32 per point: [hi(16)|lo(16)] + 4 pad
#define HALO_ROWS 10
#define HALO_PTS (HALO_ROWS * 34)      // 340
#define A_U32 (HALO_PTS * APITCH)      // 12240
#define KC_SMEM ((A_U32 + B_U32) * 4)  // 67392 B -> 2 CTAs/SM

__device__ __forceinline__ uint32_t packh(float x, float y) {
    __half2 h = __floats2half2_rn(x, y);
    uint32_t r;
    *(__half2*)&r = h;
    return r;
}

__device__ __forceinline__ uint32_t smem_u32(const void* p) {
    uint32_t a;
    asm("{ .reg .u64 t; cvta.to.shared.u64 t, %1; cvt.u32.u64 %0, t; }" : "=r"(a) : "l"(p));
    return a;
}

__device__ __forceinline__ void ldmA(uint32_t addr, uint32_t* a) {
    asm volatile("ldmatrix.sync.aligned.m8n8.x4.shared.b16 {%0,%1,%2,%3}, [%4];"
                 : "=r"(a[0]), "=r"(a[1]), "=r"(a[2]), "=r"(a[3]) : "r"(addr));
}

__device__ __forceinline__ void mma16816(float* d, const uint32_t* a,
                                         uint32_t b0, uint32_t b1) {
    asm volatile(
        "mma.sync.aligned.m16n8k16.row.col.f32.f16.f16.f32 "
        "{%0,%1,%2,%3}, {%4,%5,%6,%7}, {%8,%9}, {%0,%1,%2,%3};"
        : "+f"(d[0]), "+f"(d[1]), "+f"(d[2]), "+f"(d[3])
        : "r"(a[0]), "r"(a[1]), "r"(a[2]), "r"(a[3]), "r"(b0), "r"(b1));
}

__global__ __launch_bounds__(512) void kW_buildB(
    const float* __restrict__ w_real, const float* __restrict__ w_imag)
{
    const int e = blockIdx.x * 512 + threadIdx.x;
    if (e >= B_U32) return;
    const int ln = e & 31;
    const int rr = (e >> 5) & 1;
    const int nt = (e >> 6) & 3;
    const int rem = e >> 8;
    const int chunk = rem & 1;
    const int tap = rem >> 1;
    const int a = tap / 3, b = tap % 3;
    const int gg = ln >> 2, tt = ln & 3;
    const int n_idx = nt * 8 + gg;
    const int o = n_idx >> 1, cout = n_idx & 1;
    float vals[2];
    #pragma unroll
    for (int q = 0; q < 2; ++q) {
        const int k = chunk * 16 + tt * 2 + rr * 8 + q;   // k in [0,32)
        const int i = k >> 1;
        const int cin = k & 1;
        const float wr_ = w_real[(i * 16 + o) * 9 + a * 3 + b];
        const float wi_ = w_imag[(i * 16 + o) * 9 + a * 3 + b];
        vals[q] = cout ? (cin ? wr_ : wi_) : (cin ? -wi_ : wr_);
    }
    // Interleaved fragment layout matching the consumer: pairs (rr=0, rr=1)
    // adjacent per lane.
    g_Bfrag[(tap * 2 + chunk) * 256 + nt * 64 + ln * 2 + rr] = packh(vals[0], vals[1]);
}

__global__ __launch_bounds__(512, 2) void kC_conv_mma(
    const float* __restrict__ b_real, const float* __restrict__ b_imag)
{
    extern __shared__ uint32_t smc[];
    uint32_t* sA = smc;
    uint32_t* sB = smc + A_U32;

    const int t = threadIdx.x;
    const int w = t >> 5;
    const int lane = t & 31;
    const int g = lane >> 2;
    const int th = lane & 3;
    const int ubase = blockIdx.x * 32;
    const int h0 = blockIdx.y * 8;
    const int n = blockIdx.z;
    const int l = w >> 1;
    const int usub = w & 1;

    // B stage (small table, coalesced)
    {
        const uint4* src = (const uint4*)g_Bfrag;
        uint4* dst = (uint4*)sB;
        #pragma unroll
        for (int e = t; e < B_U32 / 4; e += 512) dst[e] = src[e];
    }

    // A halo fill: [hi(16)|lo(16)] fp16x2 per point
    for (int e = t; e < HALO_PTS * NCH; e += 512) {
        const int i = e / HALO_PTS;
        const int p = e - i * HALO_PTS;
        const int hr = p / 34;
        const int c = p - hr * 34;
        const int h = h0 - 1 + hr;
        const int u = ubase - 1 + c;
        float2 v = make_float2(0.f, 0.f);
        if (h >= 0 && h < HH && u >= 0 && u < NU)
            v = g_X[(((size_t)n * NCH + i) * HH + h) * SU + u];
        const __half hx = __float2half_rn(v.x);
        const __half hy = __float2half_rn(v.y);
        const int base = p * APITCH;
        sA[base + i] = packh(v.x, v.y);
        sA[base + 16 + i] = packh(v.x - __half2float(hx), v.y - __half2float(hy));
    }
    __syncthreads();

    const uint32_t sAb = smem_u32(sA);

    float acc[4][4];
    #pragma unroll
    for (int nt = 0; nt < 4; ++nt)
        #pragma unroll
        for (int q = 0; q < 4; ++q) acc[nt][q] = 0.f;

    const int lrow = (lane & 7) + ((lane >> 3) & 1) * 8;
    const int lkof = (lane >> 4) * 4;

    // mainloop: 9 taps; per tap load B once (2 chunks), A hi0/hi1/lo0/lo1.
    #pragma unroll
    for (int tap = 0; tap < 9; ++tap) {
        const int a = tap / 3, b = tap % 3;
        const int prow = (l + 2 - a) * 34 + (2 - b) + usub * 16;
        const int bbase = tap * 512 + lane * 2;
        uint2 bb0[4], bb1[4];
        #pragma unroll
        for (int nt = 0; nt < 4; ++nt) {
            bb0[nt] = *(const uint2*)(sB + bbase + nt * 64);
            bb1[nt] = *(const uint2*)(sB + bbase + 256 + nt * 64);
        }
        const uint32_t ab = sAb + (uint32_t)(((prow + lrow) * APITCH) + lkof) * 4u;
        uint32_t hi0[4], hi1[4], lo0[4], lo1[4];
        ldmA(ab, hi0);
        ldmA(ab + 32, hi1);       // +8 u32
        ldmA(ab + 64, lo0);       // +16 u32
        ldmA(ab + 96, lo1);       // +24 u32
        #pragma unroll
        for (int nt = 0; nt < 4; ++nt) {
            mma16816(acc[nt], hi0, bb0[nt].x, bb0[nt].y);
            mma16816(acc[nt], hi1, bb1[nt].x, bb1[nt].y);
            mma16816(acc[nt], lo0, bb0[nt].x, bb0[nt].y);
            mma16816(acc[nt], lo1, bb1[nt].x, bb1[nt].y);
        }
    }

    // epilogue
    const int h = h0 + l;
    #pragma unroll
    for (int nt = 0; nt < 4; ++nt) {
        const int o = nt * 4 + th;
        const float br_ = __ldg(b_real + o);
        const float bi_ = __ldg(b_imag + o);
        float2* Yrow = g_Y + (((size_t)n * NCH + o) * HH + h) * SU;
        const int u0 = ubase + usub * 16 + g;
        const int u1 = u0 + 8;
        if (u0 < NU)
            Yrow[u0] = make_float2(acc[nt][0] + br_, acc[nt][1] + bi_);
        if (u1 < NU)
            Yrow[u1] = make_float2(acc[nt][2] + br_, acc[nt][3] + bi_);
    }
}

__global__ __launch_bounds__(512) void kE_irfft_rows(float* __restrict__ out) {
    __shared__ float2 s[8 * GSTR];
    const int t = threadIdx.x & 63;
    const int g = threadIdx.x >> 6;
    const int img = blockIdx.x >> 5;
    const int pr = (blockIdx.x & 31) * 8 + g;
    const float2* G0 = g_Y + ((size_t)img * HH + 2 * pr) * SU;
    const float2* G1 = G0 + SU;
    float2* z = s + g * GSTR;
    #pragma unroll
    for (int m = 0; m < 5; ++m) {
        const int u = t + 64*m;
        if (u < NU) {
            float2 A = G0[u];
            float2 B = G1[u];
            if (u == 0 || u == 256) { A.y = 0.f; B.y = 0.f; }
            z[u] = make_float2(A.x - B.y, A.y + B.x);
            if (u >= 1 && u <= 255)
                z[512 - u] = make_float2(A.x + B.y, B.x - A.y);
        }
    }
    __syncthreads();
    float2 a[8];
    #pragma unroll
    for (int m = 0; m < 8; ++m) a[m] = z[t + 64*m];
    __syncthreads();
    fft512_regs<+1>(a, t, z);
    float* o0 = out + ((size_t)img * HH + 2 * pr) * WW;
    float* o1 = o0 + WW;
    #pragma unroll
    for (int m = 0; m < 8; ++m) {
        o0[t + 64*m] = a[m].x;
        o1[t + 64*m] = a[m].y;
    }
}

extern "C" void kernel_launch(void* const* d_in, const int* in_sizes, int n_in,
                              void* d_out, int out_size) {
    const float* x      = (const float*)d_in[0];
    const float* w_real = (const float*)d_in[1];
    const float* w_imag = (const float*)d_in[2];
    const float* b_real = (const float*)d_in[3];
    const float* b_imag = (const float*)d_in[4];
    float* out = (float*)d_out;

    cudaFuncSetAttribute(kC_conv_mma, cudaFuncAttributeMaxDynamicSharedMemorySize, KC_SMEM);

    kW_buildB<<<(B_U32 + 511) / 512, 512>>>(w_real, w_imag);

    kA_rfft_rows<<<IMGS * 32, 512>>>(x);

    dim3 gB((NU + 7) / 8, IMGS);
    kBD_fft_cols<-1><<<gB, 512>>>(0, 1.0f);

    dim3 gC(9, HH / 8, NBATCH);
    kC_conv_mma<<<gC, 512, KC_SMEM>>>(b_real, b_imag);

    kBD_fft_cols<+1><<<gB, 512>>>(1, 1.0f / (512.0f * 512.0f));

    kE_irfft_rows<<<IMGS * 32, 512>>>(out);
}

// round 13
// speedup vs baseline: 2.1366x; 1.0480x over previous
#include <cuda_runtime.h>
#include <cuda_fp16.h>
#include <cstdint>

#define HH 512
#define WW 512
#define NU 257
#define SU 260
#define NCH 16
#define NBATCH 8
#define IMGS (NBATCH*NCH)
#define GSTR 578

__device__ float2 g_X[(size_t)IMGS * HH * SU];
__device__ float2 g_Y[(size_t)IMGS * HH * SU];

#define B_U32 (9 * 2 * 4 * 2 * 32)     // 4608: [tap][chunk][nt][ln*2+rr]
__device__ uint32_t g_Bfrag[B_U32];

__device__ __forceinline__ float2 cmul(float2 a, float2 b) {
    return make_float2(a.x*b.x - a.y*b.y, a.x*b.y + a.y*b.x);
}
__device__ __forceinline__ float2 cadd(float2 a, float2 b) { return make_float2(a.x+b.x, a.y+b.y); }
__device__ __forceinline__ float2 csub(float2 a, float2 b) { return make_float2(a.x-b.x, a.y-b.y); }

// ---------------- radix-8 register FFT ----------------
template<int S>
__device__ __forceinline__ void fft8(float2 a[8]) {
    const float r = 0.7071067811865476f;
    const float sf = (float)S;
    float2 d, u;
    u=a[0]; d=csub(u,a[4]); a[0]=cadd(u,a[4]); a[4]=d;
    u=a[1]; d=csub(u,a[5]); a[1]=cadd(u,a[5]); a[5]=make_float2(r*(d.x - sf*d.y), r*(sf*d.x + d.y));
    u=a[2]; d=csub(u,a[6]); a[2]=cadd(u,a[6]); a[6]=make_float2(-sf*d.y, sf*d.x);
    u=a[3]; d=csub(u,a[7]); a[3]=cadd(u,a[7]); a[7]=make_float2(r*(-d.x - sf*d.y), r*(sf*d.x - d.y));
    u=a[0]; d=csub(u,a[2]); a[0]=cadd(u,a[2]); a[2]=d;
    u=a[1]; d=csub(u,a[3]); a[1]=cadd(u,a[3]); a[3]=make_float2(-sf*d.y, sf*d.x);
    u=a[4]; d=csub(u,a[6]); a[4]=cadd(u,a[6]); a[6]=d;
    u=a[5]; d=csub(u,a[7]); a[5]=cadd(u,a[7]); a[7]=make_float2(-sf*d.y, sf*d.x);
    u=a[0]; a[0]=cadd(u,a[1]); a[1]=csub(u,a[1]);
    u=a[2]; a[2]=cadd(u,a[3]); a[3]=csub(u,a[3]);
    u=a[4]; a[4]=cadd(u,a[5]); a[5]=csub(u,a[5]);
    u=a[6]; a[6]=cadd(u,a[7]); a[7]=csub(u,a[7]);
    d=a[1]; a[1]=a[4]; a[4]=d;
    d=a[3]; a[3]=a[6]; a[6]=d;
}

template<int S>
__device__ __forceinline__ void fft512_regs(float2 a[8], int t, float2* s) {
    const float TWO_PI = 6.283185307179586f;
    const int n2 = t & 7;
    const int n1 = t >> 3;
    fft8<S>(a);
    const float c1 = (float)S * TWO_PI / 64.0f * (float)n1;
    #pragma unroll
    for (int k0 = 1; k0 < 8; ++k0) {
        float sn, cs; __sincosf(c1 * (float)k0, &sn, &cs);
        a[k0] = cmul(a[k0], make_float2(cs, sn));
    }
    #pragma unroll
    for (int k0 = 0; k0 < 8; ++k0) s[t + 72*k0] = a[k0];
    __syncthreads();
    const int k0r = t >> 3;
    #pragma unroll
    for (int j = 0; j < 8; ++j) a[j] = s[n2 + 8*j + 72*k0r];
    __syncthreads();
    fft8<S>(a);
    const float c2 = (float)S * TWO_PI / 512.0f * (float)n2;
    #pragma unroll
    for (int k1 = 0; k1 < 8; ++k1) {
        float sn, cs; __sincosf(c2 * (float)(k0r + 8*k1), &sn, &cs);
        a[k1] = cmul(a[k1], make_float2(cs, sn));
    }
    #pragma unroll
    for (int k1 = 0; k1 < 8; ++k1) s[72*k1 + 8*k0r + (n2 ^ k0r)] = a[k1];
    __syncthreads();
    const int k0b = t & 7, k1r = t >> 3;
    #pragma unroll
    for (int j = 0; j < 8; ++j) a[j] = s[72*k1r + 8*k0b + (j ^ k0b)];
    fft8<S>(a);
}

__global__ __launch_bounds__(512) void kA_rfft_rows(const float* __restrict__ x) {
    __shared__ float2 s[8 * GSTR];
    const int t = threadIdx.x & 63;
    const int g = threadIdx.x >> 6;
    const int img = blockIdx.x >> 5;
    const int pr = (blockIdx.x & 31) * 8 + g;
    const float* r0 = x + ((size_t)img * HH + 2 * pr) * WW;
    const float* r1 = r0 + WW;
    float2 a[8];
    #pragma unroll
    for (int m = 0; m < 8; ++m) a[m] = make_float2(r0[t + 64*m], r1[t + 64*m]);
    float2* z = s + g * GSTR;
    fft512_regs<-1>(a, t, z);
    __syncthreads();
    #pragma unroll
    for (int m = 0; m < 8; ++m) z[t + 64*m] = a[m];
    __syncthreads();
    float2* X0 = g_X + ((size_t)img * HH + 2 * pr) * SU;
    float2* X1 = X0 + SU;
    #pragma unroll
    for (int m = 0; m < 5; ++m) {
        const int u = t + 64*m;
        if (u < NU) {
            const float2 zk = z[u];
            const float2 zm = z[(512 - u) & 511];
            X0[u] = make_float2(0.5f*(zk.x + zm.x),  0.5f*(zk.y - zm.y));
            X1[u] = make_float2(0.5f*(zk.y + zm.y), -0.5f*(zk.x - zm.x));
        }
    }
}

template<int S>
__global__ __launch_bounds__(512) void kBD_fft_cols(int useY, float scale) {
    __shared__ float2 s[8 * GSTR];
    const int g = threadIdx.x & 7;
    const int t = threadIdx.x >> 3;
    const int img = blockIdx.y;
    const int u = blockIdx.x * 8 + g;
    const bool ok = (u < NU);
    float2* data = useY ? g_Y : g_X;
    float2* base = data + (size_t)img * HH * SU + u;
    float2 a[8];
    #pragma unroll
    for (int m = 0; m < 8; ++m)
        a[m] = ok ? base[(size_t)(t + 64*m) * SU] : make_float2(0.f, 0.f);
    fft512_regs<S>(a, t, s + g * GSTR);
    if (ok) {
        #pragma unroll
        for (int m = 0; m < 8; ++m)
            base[(size_t)(t + 64*m) * SU] = make_float2(a[m].x * scale, a[m].y * scale);
    }
}

// ===================== kC machinery (fp16 single, K=32) =====================
#define APITCH 20                      // u32 per point: hi(16) + 4 pad
#define HALO_ROWS 10
#define HALO_PTS (HALO_ROWS * 34)      // 340
#define A_U32 (HALO_PTS * APITCH)      // 6800
#define KC_SMEM ((A_U32 + B_U32) * 4)  // 45632 B

__device__ __forceinline__ uint32_t packh(float x, float y) {
    __half2 h = __floats2half2_rn(x, y);
    uint32_t r;
    *(__half2*)&r = h;
    return r;
}

__device__ __forceinline__ uint32_t smem_u32(const void* p) {
    uint32_t a;
    asm("{ .reg .u64 t; cvta.to.shared.u64 t, %1; cvt.u32.u64 %0, t; }" : "=r"(a) : "l"(p));
    return a;
}

__device__ __forceinline__ void ldmA(uint32_t addr, uint32_t* a) {
    asm volatile("ldmatrix.sync.aligned.m8n8.x4.shared.b16 {%0,%1,%2,%3}, [%4];"
                 : "=r"(a[0]), "=r"(a[1]), "=r"(a[2]), "=r"(a[3]) : "r"(addr));
}

__device__ __forceinline__ void mma16816(float* d, const uint32_t* a,
                                         uint32_t b0, uint32_t b1) {
    asm volatile(
        "mma.sync.aligned.m16n8k16.row.col.f32.f16.f16.f32 "
        "{%0,%1,%2,%3}, {%4,%5,%6,%7}, {%8,%9}, {%0,%1,%2,%3};"
        : "+f"(d[0]), "+f"(d[1]), "+f"(d[2]), "+f"(d[3])
        : "r"(a[0]), "r"(a[1]), "r"(a[2]), "r"(a[3]), "r"(b0), "r"(b1));
}

__global__ __launch_bounds__(512) void kW_buildB(
    const float* __restrict__ w_real, const float* __restrict__ w_imag)
{
    const int e = blockIdx.x * 512 + threadIdx.x;
    if (e >= B_U32) return;
    const int ln = e & 31;
    const int rr = (e >> 5) & 1;
    const int nt = (e >> 6) & 3;
    const int rem = e >> 8;
    const int chunk = rem & 1;
    const int tap = rem >> 1;
    const int a = tap / 3, b = tap % 3;
    const int gg = ln >> 2, tt = ln & 3;
    const int n_idx = nt * 8 + gg;
    const int o = n_idx >> 1, cout = n_idx & 1;
    float vals[2];
    #pragma unroll
    for (int q = 0; q < 2; ++q) {
        const int k = chunk * 16 + tt * 2 + rr * 8 + q;   // k in [0,32)
        const int i = k >> 1;
        const int cin = k & 1;
        const float wr_ = w_real[(i * 16 + o) * 9 + a * 3 + b];
        const float wi_ = w_imag[(i * 16 + o) * 9 + a * 3 + b];
        vals[q] = cout ? (cin ? wr_ : wi_) : (cin ? -wi_ : wr_);
    }
    g_Bfrag[(tap * 2 + chunk) * 256 + nt * 64 + ln * 2 + rr] = packh(vals[0], vals[1]);
}

__global__ __launch_bounds__(512, 2) void kC_conv_mma(
    const float* __restrict__ b_real, const float* __restrict__ b_imag)
{
    extern __shared__ uint32_t smc[];
    uint32_t* sA = smc;
    uint32_t* sB = smc + A_U32;

    const int t = threadIdx.x;
    const int w = t >> 5;
    const int lane = t & 31;
    const int g = lane >> 2;
    const int th = lane & 3;
    const int ubase = blockIdx.x * 32;
    const int h0 = blockIdx.y * 8;
    const int n = blockIdx.z;
    const int l = w >> 1;
    const int usub = w & 1;

    // B stage (small table, coalesced)
    {
        const uint4* src = (const uint4*)g_Bfrag;
        uint4* dst = (uint4*)sB;
        #pragma unroll
        for (int e = t; e < B_U32 / 4; e += 512) dst[e] = src[e];
    }

    // A halo fill: single fp16x2 per (point, channel)
    for (int e = t; e < HALO_PTS * NCH; e += 512) {
        const int i = e / HALO_PTS;
        const int p = e - i * HALO_PTS;
        const int hr = p / 34;
        const int c = p - hr * 34;
        const int h = h0 - 1 + hr;
        const int u = ubase - 1 + c;
        float2 v = make_float2(0.f, 0.f);
        if (h >= 0 && h < HH && u >= 0 && u < NU)
            v = g_X[(((size_t)n * NCH + i) * HH + h) * SU + u];
        sA[p * APITCH + i] = packh(v.x, v.y);
    }
    __syncthreads();

    const uint32_t sAb = smem_u32(sA);

    float acc[4][4];
    #pragma unroll
    for (int nt = 0; nt < 4; ++nt)
        #pragma unroll
        for (int q = 0; q < 4; ++q) acc[nt][q] = 0.f;

    const int lrow = (lane & 7) + ((lane >> 3) & 1) * 8;
    const int lkof = (lane >> 4) * 4;

    // mainloop: 9 taps; per tap: 2 ldmatrix (K=32) + 8 B uint2 + 8 MMAs
    #pragma unroll
    for (int tap = 0; tap < 9; ++tap) {
        const int a = tap / 3, b = tap % 3;
        const int prow = (l + 2 - a) * 34 + (2 - b) + usub * 16;
        const int bbase = tap * 512 + lane * 2;
        uint2 bb0[4], bb1[4];
        #pragma unroll
        for (int nt = 0; nt < 4; ++nt) {
            bb0[nt] = *(const uint2*)(sB + bbase + nt * 64);
            bb1[nt] = *(const uint2*)(sB + bbase + 256 + nt * 64);
        }
        const uint32_t ab = sAb + (uint32_t)(((prow + lrow) * APITCH) + lkof) * 4u;
        uint32_t hi0[4], hi1[4];
        ldmA(ab, hi0);
        ldmA(ab + 32, hi1);       // +8 u32 -> K 16..31
        #pragma unroll
        for (int nt = 0; nt < 4; ++nt) {
            mma16816(acc[nt], hi0, bb0[nt].x, bb0[nt].y);
            mma16816(acc[nt], hi1, bb1[nt].x, bb1[nt].y);
        }
    }

    // epilogue
    const int h = h0 + l;
    #pragma unroll
    for (int nt = 0; nt < 4; ++nt) {
        const int o = nt * 4 + th;
        const float br_ = __ldg(b_real + o);
        const float bi_ = __ldg(b_imag + o);
        float2* Yrow = g_Y + (((size_t)n * NCH + o) * HH + h) * SU;
        const int u0 = ubase + usub * 16 + g;
        const int u1 = u0 + 8;
        if (u0 < NU)
            Yrow[u0] = make_float2(acc[nt][0] + br_, acc[nt][1] + bi_);
        if (u1 < NU)
            Yrow[u1] = make_float2(acc[nt][2] + br_, acc[nt][3] + bi_);
    }
}

__global__ __launch_bounds__(512) void kE_irfft_rows(float* __restrict__ out) {
    __shared__ float2 s[8 * GSTR];
    const int t = threadIdx.x & 63;
    const int g = threadIdx.x >> 6;
    const int img = blockIdx.x >> 5;
    const int pr = (blockIdx.x & 31) * 8 + g;
    const float2* G0 = g_Y + ((size_t)img * HH + 2 * pr) * SU;
    const float2* G1 = G0 + SU;
    float2* z = s + g * GSTR;
    #pragma unroll
    for (int m = 0; m < 5; ++m) {
        const int u = t + 64*m;
        if (u < NU) {
            float2 A = G0[u];
            float2 B = G1[u];
            if (u == 0 || u == 256) { A.y = 0.f; B.y = 0.f; }
            z[u] = make_float2(A.x - B.y, A.y + B.x);
            if (u >= 1 && u <= 255)
                z[512 - u] = make_float2(A.x + B.y, B.x - A.y);
        }
    }
    __syncthreads();
    float2 a[8];
    #pragma unroll
    for (int m = 0; m < 8; ++m) a[m] = z[t + 64*m];
    __syncthreads();
    fft512_regs<+1>(a, t, z);
    float* o0 = out + ((size_t)img * HH + 2 * pr) * WW;
    float* o1 = o0 + WW;
    #pragma unroll
    for (int m = 0; m < 8; ++m) {
        o0[t + 64*m] = a[m].x;
        o1[t + 64*m] = a[m].y;
    }
}

extern "C" void kernel_launch(void* const* d_in, const int* in_sizes, int n_in,
                              void* d_out, int out_size) {
    const float* x      = (const float*)d_in[0];
    const float* w_real = (const float*)d_in[1];
    const float* w_imag = (const float*)d_in[2];
    const float* b_real = (const float*)d_in[3];
    const float* b_imag = (const float*)d_in[4];
    float* out = (float*)d_out;

    cudaFuncSetAttribute(kC_conv_mma, cudaFuncAttributeMaxDynamicSharedMemorySize, KC_SMEM);

    kW_buildB<<<(B_U32 + 511) / 512, 512>>>(w_real, w_imag);

    kA_rfft_rows<<<IMGS * 32, 512>>>(x);

    dim3 gB((NU + 7) / 8, IMGS);
    kBD_fft_cols<-1><<<gB, 512>>>(0, 1.0f);

    dim3 gC(9, HH / 8, NBATCH);
    kC_conv_mma<<<gC, 512, KC_SMEM>>>(b_real, b_imag);

    kBD_fft_cols<+1><<<gB, 512>>>(1, 1.0f / (512.0f * 512.0f));

    kE_irfft_rows<<<IMGS * 32, 512>>>(out);
}

// round 14
// speedup vs baseline: 2.4257x; 1.1353x over previous
#include <cuda_runtime.h>
#include <cuda_fp16.h>
#include <cstdint>

#define HH 512
#define WW 512
#define NU 257
#define SU 260
#define NCH 16
#define NBATCH 8
#define IMGS (NBATCH*NCH)
#define GSTR 578

__device__ float2 g_X[(size_t)IMGS * HH * SU];
__device__ float2 g_Y[(size_t)IMGS * HH * SU];

// h-reduction vectors and edge-correction tables
__device__ float2 g_R0[IMGS * NU];     // X_f[k=0]   = sum_h X[h]
__device__ float2 g_R511[IMGS * NU];   // X_f[k=511] = sum_h X[h] e^{+i 2pi h/512}
__device__ float2 g_D0[IMGS * NU];     // correction at k=0   (per n,o,u)
__device__ float2 g_D511[IMGS * NU];   // correction at k=511

#define B_U32 (3 * 2 * 12 * 64)        // 4608: [(b*2+chunk)*12+nt][64]
__device__ uint32_t g_Bfrag[B_U32];

__device__ __forceinline__ float2 cmul(float2 a, float2 b) {
    return make_float2(a.x*b.x - a.y*b.y, a.x*b.y + a.y*b.x);
}
__device__ __forceinline__ float2 cadd(float2 a, float2 b) { return make_float2(a.x+b.x, a.y+b.y); }
__device__ __forceinline__ float2 csub(float2 a, float2 b) { return make_float2(a.x-b.x, a.y-b.y); }

// ---------------- radix-8 register FFT ----------------
template<int S>
__device__ __forceinline__ void fft8(float2 a[8]) {
    const float r = 0.7071067811865476f;
    const float sf = (float)S;
    float2 d, u;
    u=a[0]; d=csub(u,a[4]); a[0]=cadd(u,a[4]); a[4]=d;
    u=a[1]; d=csub(u,a[5]); a[1]=cadd(u,a[5]); a[5]=make_float2(r*(d.x - sf*d.y), r*(sf*d.x + d.y));
    u=a[2]; d=csub(u,a[6]); a[2]=cadd(u,a[6]); a[6]=make_float2(-sf*d.y, sf*d.x);
    u=a[3]; d=csub(u,a[7]); a[3]=cadd(u,a[7]); a[7]=make_float2(r*(-d.x - sf*d.y), r*(sf*d.x - d.y));
    u=a[0]; d=csub(u,a[2]); a[0]=cadd(u,a[2]); a[2]=d;
    u=a[1]; d=csub(u,a[3]); a[1]=cadd(u,a[3]); a[3]=make_float2(-sf*d.y, sf*d.x);
    u=a[4]; d=csub(u,a[6]); a[4]=cadd(u,a[6]); a[6]=d;
    u=a[5]; d=csub(u,a[7]); a[5]=cadd(u,a[7]); a[7]=make_float2(-sf*d.y, sf*d.x);
    u=a[0]; a[0]=cadd(u,a[1]); a[1]=csub(u,a[1]);
    u=a[2]; a[2]=cadd(u,a[3]); a[3]=csub(u,a[3]);
    u=a[4]; a[4]=cadd(u,a[5]); a[5]=csub(u,a[5]);
    u=a[6]; a[6]=cadd(u,a[7]); a[7]=csub(u,a[7]);
    d=a[1]; a[1]=a[4]; a[4]=d;
    d=a[3]; a[3]=a[6]; a[6]=d;
}

template<int S>
__device__ __forceinline__ void fft512_regs(float2 a[8], int t, float2* s) {
    const float TWO_PI = 6.283185307179586f;
    const int n2 = t & 7;
    const int n1 = t >> 3;
    fft8<S>(a);
    const float c1 = (float)S * TWO_PI / 64.0f * (float)n1;
    #pragma unroll
    for (int k0 = 1; k0 < 8; ++k0) {
        float sn, cs; __sincosf(c1 * (float)k0, &sn, &cs);
        a[k0] = cmul(a[k0], make_float2(cs, sn));
    }
    #pragma unroll
    for (int k0 = 0; k0 < 8; ++k0) s[t + 72*k0] = a[k0];
    __syncthreads();
    const int k0r = t >> 3;
    #pragma unroll
    for (int j = 0; j < 8; ++j) a[j] = s[n2 + 8*j + 72*k0r];
    __syncthreads();
    fft8<S>(a);
    const float c2 = (float)S * TWO_PI / 512.0f * (float)n2;
    #pragma unroll
    for (int k1 = 0; k1 < 8; ++k1) {
        float sn, cs; __sincosf(c2 * (float)(k0r + 8*k1), &sn, &cs);
        a[k1] = cmul(a[k1], make_float2(cs, sn));
    }
    #pragma unroll
    for (int k1 = 0; k1 < 8; ++k1) s[72*k1 + 8*k0r + (n2 ^ k0r)] = a[k1];
    __syncthreads();
    const int k0b = t & 7, k1r = t >> 3;
    #pragma unroll
    for (int j = 0; j < 8; ++j) a[j] = s[72*k1r + 8*k0b + (j ^ k0b)];
    fft8<S>(a);
}

// ---------------- kZeroR ----------------
__global__ __launch_bounds__(512) void kZeroR() {
    const int i = blockIdx.x * 512 + threadIdx.x;
    if (i < IMGS * NU) {
        g_R0[i] = make_float2(0.f, 0.f);
        g_R511[i] = make_float2(0.f, 0.f);
    }
}

// ---------------- kA: row rfft + R reductions ----------------
__global__ __launch_bounds__(512) void kA_rfft_rows(const float* __restrict__ x) {
    __shared__ float2 s[8 * GSTR];
    const int t = threadIdx.x & 63;
    const int g = threadIdx.x >> 6;
    const int img = blockIdx.x >> 5;
    const int pr = (blockIdx.x & 31) * 8 + g;
    const float* r0 = x + ((size_t)img * HH + 2 * pr) * WW;
    const float* r1 = r0 + WW;
    float2 a[8];
    #pragma unroll
    for (int m = 0; m < 8; ++m) a[m] = make_float2(r0[t + 64*m], r1[t + 64*m]);
    float2* z = s + g * GSTR;
    fft512_regs<-1>(a, t, z);
    __syncthreads();
    #pragma unroll
    for (int m = 0; m < 8; ++m) z[t + 64*m] = a[m];
    __syncthreads();

    // row phases for R511: e^{+i 2pi h /512}, h = 2pr, 2pr+1
    float c0, s0, c1, s1;
    sincosf(6.283185307179586f * (float)(2 * pr) / 512.0f, &s0, &c0);
    sincosf(6.283185307179586f * (float)(2 * pr + 1) / 512.0f, &s1, &c1);

    float2* X0 = g_X + ((size_t)img * HH + 2 * pr) * SU;
    float2* X1 = X0 + SU;
    float2 rc0[5], rc5[5];
    #pragma unroll
    for (int m = 0; m < 5; ++m) {
        const int u = t + 64*m;
        if (u < NU) {
            const float2 zk = z[u];
            const float2 zm = z[(512 - u) & 511];
            const float2 A = make_float2(0.5f*(zk.x + zm.x),  0.5f*(zk.y - zm.y));
            const float2 B = make_float2(0.5f*(zk.y + zm.y), -0.5f*(zk.x - zm.x));
            X0[u] = A;
            X1[u] = B;
            rc0[m] = cadd(A, B);
            rc5[m] = make_float2(A.x*c0 - A.y*s0 + B.x*c1 - B.y*s1,
                                 A.x*s0 + A.y*c0 + B.x*s1 + B.y*c1);
        }
    }
    __syncthreads();   // all reads of z done
    #pragma unroll
    for (int m = 0; m < 5; ++m) {
        const int u = t + 64*m;
        if (u < NU) {
            z[u] = rc0[m];
            z[NU + u] = rc5[m];
        }
    }
    __syncthreads();
    // cross-group reduction + global atomics
    for (int e = threadIdx.x; e < 2 * NU; e += 512) {
        float2 acc = make_float2(0.f, 0.f);
        #pragma unroll
        for (int gg = 0; gg < 8; ++gg) acc = cadd(acc, s[gg * GSTR + e]);
        if (e < NU) {
            atomicAdd(&g_R0[img * NU + e].x, acc.x);
            atomicAdd(&g_R0[img * NU + e].y, acc.y);
        } else {
            atomicAdd(&g_R511[img * NU + (e - NU)].x, acc.x);
            atomicAdd(&g_R511[img * NU + (e - NU)].y, acc.y);
        }
    }
}

// ---------------- kD0: edge-correction tables ----------------
// D0[n,o,u]   = - sum_{i,b} w[i,o,a=2,b] * R511[n,i,u+1-b]
// D511[n,o,u] = - sum_{i,b} w[i,o,a=0,b] * R0  [n,i,u+1-b]
__global__ __launch_bounds__(288) void kD0_corr(
    const float* __restrict__ w_real, const float* __restrict__ w_imag)
{
    const int no = blockIdx.x;       // n*16 + o
    const int n = no >> 4, o = no & 15;
    const int u = threadIdx.x;
    if (u >= NU) return;
    float2 d0 = make_float2(0.f, 0.f), d5 = make_float2(0.f, 0.f);
    for (int i = 0; i < NCH; ++i) {
        const int wb = (i * 16 + o) * 9;
        #pragma unroll
        for (int b = 0; b < 3; ++b) {
            const int up = u + 1 - b;
            if (up < 0 || up >= NU) continue;
            const float2 r5 = g_R511[(n * 16 + i) * NU + up];
            const float2 r0 = g_R0[(n * 16 + i) * NU + up];
            const float2 w2 = make_float2(__ldg(w_real + wb + 6 + b), __ldg(w_imag + wb + 6 + b));
            const float2 w0 = make_float2(__ldg(w_real + wb + b), __ldg(w_imag + wb + b));
            d0 = csub(d0, cmul(w2, r5));
            d5 = csub(d5, cmul(w0, r0));
        }
    }
    g_D0[no * NU + u] = d0;
    g_D511[no * NU + u] = d5;
}

// ===================== kC machinery =====================
#define APITCH 20
#define HALO_PTS (4 * 34)              // 4 payload h-lines, u halo only
#define A_U32 (HALO_PTS * APITCH)      // 2720
#define KC_SMEM ((A_U32 + B_U32) * 4)  // 29312 B

__device__ __forceinline__ uint32_t packh(float x, float y) {
    __half2 h = __floats2half2_rn(x, y);
    uint32_t r;
    *(__half2*)&r = h;
    return r;
}
__device__ __forceinline__ uint32_t smem_u32(const void* p) {
    uint32_t a;
    asm("{ .reg .u64 t; cvta.to.shared.u64 t, %1; cvt.u32.u64 %0, t; }" : "=r"(a) : "l"(p));
    return a;
}
__device__ __forceinline__ void ldmA(uint32_t addr, uint32_t* a) {
    asm volatile("ldmatrix.sync.aligned.m8n8.x4.shared.b16 {%0,%1,%2,%3}, [%4];"
                 : "=r"(a[0]), "=r"(a[1]), "=r"(a[2]), "=r"(a[3]) : "r"(addr));
}
__device__ __forceinline__ void mma16816(float* d, const uint32_t* a,
                                         uint32_t b0, uint32_t b1) {
    asm volatile(
        "mma.sync.aligned.m16n8k16.row.col.f32.f16.f16.f32 "
        "{%0,%1,%2,%3}, {%4,%5,%6,%7}, {%8,%9}, {%0,%1,%2,%3};"
        : "+f"(d[0]), "+f"(d[1]), "+f"(d[2]), "+f"(d[3])
        : "r"(a[0]), "r"(a[1]), "r"(a[2]), "r"(a[3]), "r"(b0), "r"(b1));
}

// B fragments: n_idx = a*32 + o*2 + cout ; layout tile=(b*2+chunk)*12+nt
__global__ __launch_bounds__(512) void kW_buildB(
    const float* __restrict__ w_real, const float* __restrict__ w_imag)
{
    const int e = blockIdx.x * 512 + threadIdx.x;
    if (e >= B_U32) return;
    const int within = e & 63;
    const int ln = within >> 1, rr = within & 1;
    const int tile = e >> 6;
    const int nt = tile % 12;
    const int bc = tile / 12;
    const int chunk = bc & 1, b = bc >> 1;
    const int a = nt >> 2;
    const int gg = ln >> 2, tt = ln & 3;
    const int n_idx = nt * 8 + gg;
    const int oc = n_idx & 31;
    const int o = oc >> 1, cout = oc & 1;
    float vals[2];
    #pragma unroll
    for (int q = 0; q < 2; ++q) {
        const int k = chunk * 16 + tt * 2 + rr * 8 + q;   // k in [0,32)
        const int i = k >> 1;
        const int cin = k & 1;
        const float wr_ = w_real[(i * 16 + o) * 9 + a * 3 + b];
        const float wi_ = w_imag[(i * 16 + o) * 9 + a * 3 + b];
        vals[q] = cout ? (cin ? wr_ : wi_) : (cin ? -wi_ : wr_);
    }
    g_Bfrag[e] = packh(vals[0], vals[1]);
}

__global__ __launch_bounds__(512, 2) void kC_conv_mma(
    const float* __restrict__ b_real, const float* __restrict__ b_imag)
{
    extern __shared__ uint32_t smc[];
    uint32_t* sA = smc;
    uint32_t* sB = smc + A_U32;

    const int t = threadIdx.x;
    const int w = t >> 5;
    const int lane = t & 31;
    const int g = lane >> 2;
    const int th = lane & 3;
    const int ubase = blockIdx.x * 32;
    const int h0 = blockIdx.y * 4;
    const int n = blockIdx.z;
    const int l = w >> 2;          // h-line (0..3)
    const int usub = (w >> 1) & 1; // u half
    const int oh = w & 1;          // o half

    // B stage
    {
        const uint4* src = (const uint4*)g_Bfrag;
        uint4* dst = (uint4*)sB;
        #pragma unroll
        for (int e = t; e < B_U32 / 4; e += 512) dst[e] = src[e];
    }
    // A fill: 4 lines x 34 u x 16 ch, h-spatial (no h halo)
    for (int e = t; e < HALO_PTS * NCH; e += 512) {
        const int i = e / HALO_PTS;
        const int p = e - i * HALO_PTS;
        const int hr = p / 34;
        const int c = p - hr * 34;
        const int h = h0 + hr;
        const int u = ubase - 1 + c;
        float2 v = make_float2(0.f, 0.f);
        if (u >= 0 && u < NU)
            v = g_X[(((size_t)n * NCH + i) * HH + h) * SU + u];
        sA[p * APITCH + i] = packh(v.x, v.y);
    }
    __syncthreads();

    const uint32_t sAb = smem_u32(sA);

    float acc[6][4];   // ntl = a*2 + og2
    #pragma unroll
    for (int q = 0; q < 6; ++q)
        #pragma unroll
        for (int j = 0; j < 4; ++j) acc[q][j] = 0.f;

    const int lrow = (lane & 7) + ((lane >> 3) & 1) * 8;
    const int lkof = (lane >> 4) * 4;

    #pragma unroll
    for (int b = 0; b < 3; ++b) {
        const int prow = l * 34 + (2 - b) + usub * 16;
        const uint32_t ab = sAb + (uint32_t)(((prow + lrow) * APITCH) + lkof) * 4u;
        uint32_t A0[4], A1[4];
        ldmA(ab, A0);
        ldmA(ab + 32, A1);
        #pragma unroll
        for (int chunk = 0; chunk < 2; ++chunk) {
            const uint32_t* Af = chunk ? A1 : A0;
            const int cb = (b * 2 + chunk) * 768 + lane * 2;
            #pragma unroll
            for (int ntl = 0; ntl < 6; ++ntl) {
                const int a = ntl >> 1, og2 = ntl & 1;
                const int ntg = a * 4 + oh * 2 + og2;
                const uint2 bv = *(const uint2*)(sB + cb + ntg * 64);
                mma16816(acc[ntl], Af, bv.x, bv.y);
            }
        }
    }

    // epilogue: Y = q0*Z0 + Z1 + conj(q0)*Z2 + (D0 + q0*D511)/512 (+bias at h=0)
    const int h = h0 + l;
    float sn, cs;
    sincosf(6.283185307179586f * (float)h / 512.0f, &sn, &cs);
    const float inv512 = 1.0f / 512.0f;

    #pragma unroll
    for (int og2 = 0; og2 < 2; ++og2) {
        const int o = oh * 8 + og2 * 4 + th;
        const float br_ = __ldg(b_real + o);
        const float bi_ = __ldg(b_imag + o);
        float2* Yrow = g_Y + (((size_t)n * NCH + o) * HH + h) * SU;
        const float2* Dr0 = g_D0 + (n * 16 + o) * NU;
        const float2* Dr5 = g_D511 + (n * 16 + o) * NU;
        #pragma unroll
        for (int q2 = 0; q2 < 2; ++q2) {
            const int u = ubase + usub * 16 + g + q2 * 8;
            if (u < NU) {
                const float Z0re = acc[0 + og2][q2*2], Z0im = acc[0 + og2][q2*2+1];
                const float Z1re = acc[2 + og2][q2*2], Z1im = acc[2 + og2][q2*2+1];
                const float Z2re = acc[4 + og2][q2*2], Z2im = acc[4 + og2][q2*2+1];
                float Yre = Z1re + (cs*Z0re + sn*Z0im) + (cs*Z2re - sn*Z2im);
                float Yim = Z1im + (cs*Z0im - sn*Z0re) + (cs*Z2im + sn*Z2re);
                const float2 d0 = Dr0[u];
                const float2 d5 = Dr5[u];
                Yre += inv512 * (d0.x + cs*d5.x + sn*d5.y);
                Yim += inv512 * (d0.y + cs*d5.y - sn*d5.x);
                if (h == 0) { Yre += br_; Yim += bi_; }
                Yrow[u] = make_float2(Yre, Yim);
            }
        }
    }
}

// ---------------- kE: row irfft (scale 1/512) ----------------
__global__ __launch_bounds__(512) void kE_irfft_rows(float* __restrict__ out) {
    __shared__ float2 s[8 * GSTR];
    const int t = threadIdx.x & 63;
    const int g = threadIdx.x >> 6;
    const int img = blockIdx.x >> 5;
    const int pr = (blockIdx.x & 31) * 8 + g;
    const float sc = 1.0f / 512.0f;
    const float2* G0 = g_Y + ((size_t)img * HH + 2 * pr) * SU;
    const float2* G1 = G0 + SU;
    float2* z = s + g * GSTR;
    #pragma unroll
    for (int m = 0; m < 5; ++m) {
        const int u = t + 64*m;
        if (u < NU) {
            float2 A = G0[u];
            float2 B = G1[u];
            A.x *= sc; A.y *= sc; B.x *= sc; B.y *= sc;
            if (u == 0 || u == 256) { A.y = 0.f; B.y = 0.f; }
            z[u] = make_float2(A.x - B.y, A.y + B.x);
            if (u >= 1 && u <= 255)
                z[512 - u] = make_float2(A.x + B.y, B.x - A.y);
        }
    }
    __syncthreads();
    float2 a[8];
    #pragma unroll
    for (int m = 0; m < 8; ++m) a[m] = z[t + 64*m];
    __syncthreads();
    fft512_regs<+1>(a, t, z);
    float* o0 = out + ((size_t)img * HH + 2 * pr) * WW;
    float* o1 = o0 + WW;
    #pragma unroll
    for (int m = 0; m < 8; ++m) {
        o0[t + 64*m] = a[m].x;
        o1[t + 64*m] = a[m].y;
    }
}

extern "C" void kernel_launch(void* const* d_in, const int* in_sizes, int n_in,
                              void* d_out, int out_size) {
    const float* x      = (const float*)d_in[0];
    const float* w_real = (const float*)d_in[1];
    const float* w_imag = (const float*)d_in[2];
    const float* b_real = (const float*)d_in[3];
    const float* b_imag = (const float*)d_in[4];
    float* out = (float*)d_out;

    cudaFuncSetAttribute(kC_conv_mma, cudaFuncAttributeMaxDynamicSharedMemorySize, KC_SMEM);

    kZeroR<<<(IMGS * NU + 511) / 512, 512>>>();
    kW_buildB<<<(B_U32 + 511) / 512, 512>>>(w_real, w_imag);

    kA_rfft_rows<<<IMGS * 32, 512>>>(x);

    kD0_corr<<<IMGS, 288>>>(w_real, w_imag);

    dim3 gC(9, HH / 4, NBATCH);
    kC_conv_mma<<<gC, 512, KC_SMEM>>>(b_real, b_imag);

    kE_irfft_rows<<<IMGS * 32, 512>>>(out);
}

// round 15
// speedup vs baseline: 2.7212x; 1.1218x over previous
#include <cuda_runtime.h>
#include <cuda_fp16.h>
#include <cstdint>

#define HH 512
#define WW 512
#define NU 257
#define SU 260
#define NCH 16
#define NBATCH 8
#define IMGS (NBATCH*NCH)
#define GSTR 578

// Spectra stored as fp16x2 (re,im) packed in u32
__device__ uint32_t g_X[(size_t)IMGS * HH * SU];
__device__ uint32_t g_Y[(size_t)IMGS * HH * SU];

// h-reduction vectors and edge-correction tables (f32 — exact corrections)
__device__ float2 g_R0[IMGS * NU];
__device__ float2 g_R511[IMGS * NU];
__device__ float2 g_D0[IMGS * NU];
__device__ float2 g_D511[IMGS * NU];

#define B_U32 (3 * 2 * 12 * 64)        // 4608
__device__ uint32_t g_Bfrag[B_U32];

__device__ __forceinline__ float2 cmul(float2 a, float2 b) {
    return make_float2(a.x*b.x - a.y*b.y, a.x*b.y + a.y*b.x);
}
__device__ __forceinline__ float2 cadd(float2 a, float2 b) { return make_float2(a.x+b.x, a.y+b.y); }
__device__ __forceinline__ float2 csub(float2 a, float2 b) { return make_float2(a.x-b.x, a.y-b.y); }

__device__ __forceinline__ uint32_t packh(float x, float y) {
    __half2 h = __floats2half2_rn(x, y);
    uint32_t r;
    *(__half2*)&r = h;
    return r;
}
__device__ __forceinline__ float2 unpackh(uint32_t v) {
    __half2 h = *(__half2*)&v;
    return make_float2(__half2float(h.x), __half2float(h.y));
}

// ---------------- radix-8 register FFT ----------------
template<int S>
__device__ __forceinline__ void fft8(float2 a[8]) {
    const float r = 0.7071067811865476f;
    const float sf = (float)S;
    float2 d, u;
    u=a[0]; d=csub(u,a[4]); a[0]=cadd(u,a[4]); a[4]=d;
    u=a[1]; d=csub(u,a[5]); a[1]=cadd(u,a[5]); a[5]=make_float2(r*(d.x - sf*d.y), r*(sf*d.x + d.y));
    u=a[2]; d=csub(u,a[6]); a[2]=cadd(u,a[6]); a[6]=make_float2(-sf*d.y, sf*d.x);
    u=a[3]; d=csub(u,a[7]); a[3]=cadd(u,a[7]); a[7]=make_float2(r*(-d.x - sf*d.y), r*(sf*d.x - d.y));
    u=a[0]; d=csub(u,a[2]); a[0]=cadd(u,a[2]); a[2]=d;
    u=a[1]; d=csub(u,a[3]); a[1]=cadd(u,a[3]); a[3]=make_float2(-sf*d.y, sf*d.x);
    u=a[4]; d=csub(u,a[6]); a[4]=cadd(u,a[6]); a[6]=d;
    u=a[5]; d=csub(u,a[7]); a[5]=cadd(u,a[7]); a[7]=make_float2(-sf*d.y, sf*d.x);
    u=a[0]; a[0]=cadd(u,a[1]); a[1]=csub(u,a[1]);
    u=a[2]; a[2]=cadd(u,a[3]); a[3]=csub(u,a[3]);
    u=a[4]; a[4]=cadd(u,a[5]); a[5]=csub(u,a[5]);
    u=a[6]; a[6]=cadd(u,a[7]); a[7]=csub(u,a[7]);
    d=a[1]; a[1]=a[4]; a[4]=d;
    d=a[3]; a[3]=a[6]; a[6]=d;
}

template<int S>
__device__ __forceinline__ void fft512_regs(float2 a[8], int t, float2* s) {
    const float TWO_PI = 6.283185307179586f;
    const int n2 = t & 7;
    const int n1 = t >> 3;
    fft8<S>(a);
    const float c1 = (float)S * TWO_PI / 64.0f * (float)n1;
    #pragma unroll
    for (int k0 = 1; k0 < 8; ++k0) {
        float sn, cs; __sincosf(c1 * (float)k0, &sn, &cs);
        a[k0] = cmul(a[k0], make_float2(cs, sn));
    }
    #pragma unroll
    for (int k0 = 0; k0 < 8; ++k0) s[t + 72*k0] = a[k0];
    __syncthreads();
    const int k0r = t >> 3;
    #pragma unroll
    for (int j = 0; j < 8; ++j) a[j] = s[n2 + 8*j + 72*k0r];
    __syncthreads();
    fft8<S>(a);
    const float c2 = (float)S * TWO_PI / 512.0f * (float)n2;
    #pragma unroll
    for (int k1 = 0; k1 < 8; ++k1) {
        float sn, cs; __sincosf(c2 * (float)(k0r + 8*k1), &sn, &cs);
        a[k1] = cmul(a[k1], make_float2(cs, sn));
    }
    #pragma unroll
    for (int k1 = 0; k1 < 8; ++k1) s[72*k1 + 8*k0r + (n2 ^ k0r)] = a[k1];
    __syncthreads();
    const int k0b = t & 7, k1r = t >> 3;
    #pragma unroll
    for (int j = 0; j < 8; ++j) a[j] = s[72*k1r + 8*k0b + (j ^ k0b)];
    fft8<S>(a);
}

// ---------------- kZeroR ----------------
__global__ __launch_bounds__(512) void kZeroR() {
    const int i = blockIdx.x * 512 + threadIdx.x;
    if (i < IMGS * NU) {
        g_R0[i] = make_float2(0.f, 0.f);
        g_R511[i] = make_float2(0.f, 0.f);
    }
}

// ---------------- kA: row rfft + R reductions ----------------
__global__ __launch_bounds__(512) void kA_rfft_rows(const float* __restrict__ x) {
    __shared__ float2 s[8 * GSTR];
    const int t = threadIdx.x & 63;
    const int g = threadIdx.x >> 6;
    const int img = blockIdx.x >> 5;
    const int pr = (blockIdx.x & 31) * 8 + g;
    const float* r0 = x + ((size_t)img * HH + 2 * pr) * WW;
    const float* r1 = r0 + WW;
    float2 a[8];
    #pragma unroll
    for (int m = 0; m < 8; ++m) a[m] = make_float2(r0[t + 64*m], r1[t + 64*m]);
    float2* z = s + g * GSTR;
    fft512_regs<-1>(a, t, z);
    __syncthreads();
    #pragma unroll
    for (int m = 0; m < 8; ++m) z[t + 64*m] = a[m];
    __syncthreads();

    float c0, s0, c1, s1;
    sincosf(6.283185307179586f * (float)(2 * pr) / 512.0f, &s0, &c0);
    sincosf(6.283185307179586f * (float)(2 * pr + 1) / 512.0f, &s1, &c1);

    uint32_t* X0 = g_X + ((size_t)img * HH + 2 * pr) * SU;
    uint32_t* X1 = X0 + SU;
    float2 rc0[5], rc5[5];
    #pragma unroll
    for (int m = 0; m < 5; ++m) {
        const int u = t + 64*m;
        if (u < NU) {
            const float2 zk = z[u];
            const float2 zm = z[(512 - u) & 511];
            const float2 A = make_float2(0.5f*(zk.x + zm.x),  0.5f*(zk.y - zm.y));
            const float2 B = make_float2(0.5f*(zk.y + zm.y), -0.5f*(zk.x - zm.x));
            X0[u] = packh(A.x, A.y);
            X1[u] = packh(B.x, B.y);
            rc0[m] = cadd(A, B);
            rc5[m] = make_float2(A.x*c0 - A.y*s0 + B.x*c1 - B.y*s1,
                                 A.x*s0 + A.y*c0 + B.x*s1 + B.y*c1);
        }
    }
    __syncthreads();
    #pragma unroll
    for (int m = 0; m < 5; ++m) {
        const int u = t + 64*m;
        if (u < NU) {
            z[u] = rc0[m];
            z[NU + u] = rc5[m];
        }
    }
    __syncthreads();
    for (int e = threadIdx.x; e < 2 * NU; e += 512) {
        float2 acc = make_float2(0.f, 0.f);
        #pragma unroll
        for (int gg = 0; gg < 8; ++gg) acc = cadd(acc, s[gg * GSTR + e]);
        if (e < NU) {
            atomicAdd(&g_R0[img * NU + e].x, acc.x);
            atomicAdd(&g_R0[img * NU + e].y, acc.y);
        } else {
            atomicAdd(&g_R511[img * NU + (e - NU)].x, acc.x);
            atomicAdd(&g_R511[img * NU + (e - NU)].y, acc.y);
        }
    }
}

// ---------------- kD0: edge-correction tables (smem-staged) ----------------
// D0[n,o,u]   = - sum_{i,b} w[i,o,a=2,b] * R511[n,i,u+1-b]
// D511[n,o,u] = - sum_{i,b} w[i,o,a=0,b] * R0  [n,i,u+1-b]
#define D0_CH 33     // u per chunk
#define D0_JW 35     // staged up-entries per channel (u0-1 .. u0+33)
__global__ __launch_bounds__(512) void kD0_corr(
    const float* __restrict__ w_real, const float* __restrict__ w_imag)
{
    __shared__ float2 sR0[NCH][D0_JW + 1];
    __shared__ float2 sR5[NCH][D0_JW + 1];
    __shared__ float2 sW0[NCH * NCH * 3];   // [i][o][b], a=0
    __shared__ float2 sW2[NCH * NCH * 3];   // a=2

    const int n = blockIdx.x;
    const int u0 = blockIdx.y * D0_CH;
    const int t = threadIdx.x;

    for (int e = t; e < NCH * D0_JW; e += 512) {
        const int i = e / D0_JW;
        const int j = e - i * D0_JW;
        const int up = u0 - 1 + j;
        float2 r0v = make_float2(0.f, 0.f), r5v = make_float2(0.f, 0.f);
        if (up >= 0 && up < NU) {
            r0v = g_R0[(n * NCH + i) * NU + up];
            r5v = g_R511[(n * NCH + i) * NU + up];
        }
        sR0[i][j] = r0v;
        sR5[i][j] = r5v;
    }
    for (int e = t; e < NCH * NCH * 3; e += 512) {
        const int b = e % 3;
        const int io = e / 3;        // i*16 + o
        const int wb = io * 9;
        sW0[e] = make_float2(w_real[wb + b], w_imag[wb + b]);
        sW2[e] = make_float2(w_real[wb + 6 + b], w_imag[wb + 6 + b]);
    }
    __syncthreads();

    const int o = t & 15;
    const int us = t >> 4;            // 0..31
    for (int ui = us; ui < D0_CH; ui += 32) {
        const int u = u0 + ui;
        if (u >= NU) continue;
        float2 d0 = make_float2(0.f, 0.f), d5 = make_float2(0.f, 0.f);
        #pragma unroll
        for (int i = 0; i < NCH; ++i) {
            #pragma unroll
            for (int b = 0; b < 3; ++b) {
                const int j = ui + 2 - b;          // up - (u0-1)
                const float2 r5 = sR5[i][j];
                const float2 r0 = sR0[i][j];
                const float2 w2 = sW2[(i * 16 + o) * 3 + b];
                const float2 w0 = sW0[(i * 16 + o) * 3 + b];
                d0 = csub(d0, cmul(w2, r5));
                d5 = csub(d5, cmul(w0, r0));
            }
        }
        g_D0[(n * NCH + o) * NU + u] = d0;
        g_D511[(n * NCH + o) * NU + u] = d5;
    }
}

// ===================== kC machinery =====================
#define APITCH 20
#define HALO_PTS (4 * 34)
#define A_U32 (HALO_PTS * APITCH)      // 2720
#define KC_SMEM ((A_U32 + B_U32) * 4)  // 29312 B

__device__ __forceinline__ uint32_t smem_u32(const void* p) {
    uint32_t a;
    asm("{ .reg .u64 t; cvta.to.shared.u64 t, %1; cvt.u32.u64 %0, t; }" : "=r"(a) : "l"(p));
    return a;
}
__device__ __forceinline__ void ldmA(uint32_t addr, uint32_t* a) {
    asm volatile("ldmatrix.sync.aligned.m8n8.x4.shared.b16 {%0,%1,%2,%3}, [%4];"
                 : "=r"(a[0]), "=r"(a[1]), "=r"(a[2]), "=r"(a[3]) : "r"(addr));
}
__device__ __forceinline__ void mma16816(float* d, const uint32_t* a,
                                         uint32_t b0, uint32_t b1) {
    asm volatile(
        "mma.sync.aligned.m16n8k16.row.col.f32.f16.f16.f32 "
        "{%0,%1,%2,%3}, {%4,%5,%6,%7}, {%8,%9}, {%0,%1,%2,%3};"
        : "+f"(d[0]), "+f"(d[1]), "+f"(d[2]), "+f"(d[3])
        : "r"(a[0]), "r"(a[1]), "r"(a[2]), "r"(a[3]), "r"(b0), "r"(b1));
}

__global__ __launch_bounds__(512) void kW_buildB(
    const float* __restrict__ w_real, const float* __restrict__ w_imag)
{
    const int e = blockIdx.x * 512 + threadIdx.x;
    if (e >= B_U32) return;
    const int within = e & 63;
    const int ln = within >> 1, rr = within & 1;
    const int tile = e >> 6;
    const int nt = tile % 12;
    const int bc = tile / 12;
    const int chunk = bc & 1, b = bc >> 1;
    const int a = nt >> 2;
    const int gg = ln >> 2, tt = ln & 3;
    const int n_idx = nt * 8 + gg;
    const int oc = n_idx & 31;
    const int o = oc >> 1, cout = oc & 1;
    float vals[2];
    #pragma unroll
    for (int q = 0; q < 2; ++q) {
        const int k = chunk * 16 + tt * 2 + rr * 8 + q;
        const int i = k >> 1;
        const int cin = k & 1;
        const float wr_ = w_real[(i * 16 + o) * 9 + a * 3 + b];
        const float wi_ = w_imag[(i * 16 + o) * 9 + a * 3 + b];
        vals[q] = cout ? (cin ? wr_ : wi_) : (cin ? -wi_ : wr_);
    }
    g_Bfrag[e] = packh(vals[0], vals[1]);
}

__global__ __launch_bounds__(512, 2) void kC_conv_mma(
    const float* __restrict__ b_real, const float* __restrict__ b_imag)
{
    extern __shared__ uint32_t smc[];
    uint32_t* sA = smc;
    uint32_t* sB = smc + A_U32;

    const int t = threadIdx.x;
    const int w = t >> 5;
    const int lane = t & 31;
    const int g = lane >> 2;
    const int th = lane & 3;
    const int ubase = blockIdx.x * 32;
    const int h0 = blockIdx.y * 4;
    const int n = blockIdx.z;
    const int l = w >> 2;
    const int usub = (w >> 1) & 1;
    const int oh = w & 1;

    // B stage
    {
        const uint4* src = (const uint4*)g_Bfrag;
        uint4* dst = (uint4*)sB;
        #pragma unroll
        for (int e = t; e < B_U32 / 4; e += 512) dst[e] = src[e];
    }
    // A fill: direct fp16x2 copy
    for (int e = t; e < HALO_PTS * NCH; e += 512) {
        const int i = e / HALO_PTS;
        const int p = e - i * HALO_PTS;
        const int hr = p / 34;
        const int c = p - hr * 34;
        const int h = h0 + hr;
        const int u = ubase - 1 + c;
        uint32_t v = 0;
        if (u >= 0 && u < NU)
            v = g_X[(((size_t)n * NCH + i) * HH + h) * SU + u];
        sA[p * APITCH + i] = v;
    }
    __syncthreads();

    const uint32_t sAb = smem_u32(sA);

    float acc[6][4];
    #pragma unroll
    for (int q = 0; q < 6; ++q)
        #pragma unroll
        for (int j = 0; j < 4; ++j) acc[q][j] = 0.f;

    const int lrow = (lane & 7) + ((lane >> 3) & 1) * 8;
    const int lkof = (lane >> 4) * 4;

    #pragma unroll
    for (int b = 0; b < 3; ++b) {
        const int prow = l * 34 + (2 - b) + usub * 16;
        const uint32_t ab = sAb + (uint32_t)(((prow + lrow) * APITCH) + lkof) * 4u;
        uint32_t A0[4], A1[4];
        ldmA(ab, A0);
        ldmA(ab + 32, A1);
        #pragma unroll
        for (int chunk = 0; chunk < 2; ++chunk) {
            const uint32_t* Af = chunk ? A1 : A0;
            const int cb = (b * 2 + chunk) * 768 + lane * 2;
            #pragma unroll
            for (int ntl = 0; ntl < 6; ++ntl) {
                const int a = ntl >> 1, og2 = ntl & 1;
                const int ntg = a * 4 + oh * 2 + og2;
                const uint2 bv = *(const uint2*)(sB + cb + ntg * 64);
                mma16816(acc[ntl], Af, bv.x, bv.y);
            }
        }
    }

    // epilogue
    const int h = h0 + l;
    float sn, cs;
    sincosf(6.283185307179586f * (float)h / 512.0f, &sn, &cs);
    const float inv512 = 1.0f / 512.0f;

    #pragma unroll
    for (int og2 = 0; og2 < 2; ++og2) {
        const int o = oh * 8 + og2 * 4 + th;
        const float br_ = __ldg(b_real + o);
        const float bi_ = __ldg(b_imag + o);
        uint32_t* Yrow = g_Y + (((size_t)n * NCH + o) * HH + h) * SU;
        const float2* Dr0 = g_D0 + (n * 16 + o) * NU;
        const float2* Dr5 = g_D511 + (n * 16 + o) * NU;
        #pragma unroll
        for (int q2 = 0; q2 < 2; ++q2) {
            const int u = ubase + usub * 16 + g + q2 * 8;
            if (u < NU) {
                const float Z0re = acc[0 + og2][q2*2], Z0im = acc[0 + og2][q2*2+1];
                const float Z1re = acc[2 + og2][q2*2], Z1im = acc[2 + og2][q2*2+1];
                const float Z2re = acc[4 + og2][q2*2], Z2im = acc[4 + og2][q2*2+1];
                float Yre = Z1re + (cs*Z0re + sn*Z0im) + (cs*Z2re - sn*Z2im);
                float Yim = Z1im + (cs*Z0im - sn*Z0re) + (cs*Z2im + sn*Z2re);
                const float2 d0 = Dr0[u];
                const float2 d5 = Dr5[u];
                Yre += inv512 * (d0.x + cs*d5.x + sn*d5.y);
                Yim += inv512 * (d0.y + cs*d5.y - sn*d5.x);
                if (h == 0) { Yre += br_; Yim += bi_; }
                Yrow[u] = packh(Yre, Yim);
            }
        }
    }
}

// ---------------- kE: row irfft (fp16 in, scale 1/512) ----------------
__global__ __launch_bounds__(512) void kE_irfft_rows(float* __restrict__ out) {
    __shared__ float2 s[8 * GSTR];
    const int t = threadIdx.x & 63;
    const int g = threadIdx.x >> 6;
    const int img = blockIdx.x >> 5;
    const int pr = (blockIdx.x & 31) * 8 + g;
    const float sc = 1.0f / 512.0f;
    const uint32_t* G0 = g_Y + ((size_t)img * HH + 2 * pr) * SU;
    const uint32_t* G1 = G0 + SU;
    float2* z = s + g * GSTR;
    #pragma unroll
    for (int m = 0; m < 5; ++m) {
        const int u = t + 64*m;
        if (u < NU) {
            float2 A = unpackh(G0[u]);
            float2 B = unpackh(G1[u]);
            A.x *= sc; A.y *= sc; B.x *= sc; B.y *= sc;
            if (u == 0 || u == 256) { A.y = 0.f; B.y = 0.f; }
            z[u] = make_float2(A.x - B.y, A.y + B.x);
            if (u >= 1 && u <= 255)
                z[512 - u] = make_float2(A.x + B.y, B.x - A.y);
        }
    }
    __syncthreads();
    float2 a[8];
    #pragma unroll
    for (int m = 0; m < 8; ++m) a[m] = z[t + 64*m];
    __syncthreads();
    fft512_regs<+1>(a, t, z);
    float* o0 = out + ((size_t)img * HH + 2 * pr) * WW;
    float* o1 = o0 + WW;
    #pragma unroll
    for (int m = 0; m < 8; ++m) {
        o0[t + 64*m] = a[m].x;
        o1[t + 64*m] = a[m].y;
    }
}

extern "C" void kernel_launch(void* const* d_in, const int* in_sizes, int n_in,
                              void* d_out, int out_size) {
    const float* x      = (const float*)d_in[0];
    const float* w_real = (const float*)d_in[1];
    const float* w_imag = (const float*)d_in[2];
    const float* b_real = (const float*)d_in[3];
    const float* b_imag = (const float*)d_in[4];
    float* out = (float*)d_out;

    cudaFuncSetAttribute(kC_conv_mma, cudaFuncAttributeMaxDynamicSharedMemorySize, KC_SMEM);

    kZeroR<<<(IMGS * NU + 511) / 512, 512>>>();
    kW_buildB<<<(B_U32 + 511) / 512, 512>>>(w_real, w_imag);

    kA_rfft_rows<<<IMGS * 32, 512>>>(x);

    dim3 gD(NBATCH, (NU + D0_CH - 1) / D0_CH);
    kD0_corr<<<gD, 512>>>(w_real, w_imag);

    dim3 gC(9, HH / 4, NBATCH);
    kC_conv_mma<<<gC, 512, KC_SMEM>>>(b_real, b_imag);

    kE_irfft_rows<<<IMGS * 32, 512>>>(out);
}

// round 16
// speedup vs baseline: 2.8856x; 1.0604x over previous
#include <cuda_runtime.h>
#include <cuda_fp16.h>
#include <cstdint>

#define HH 512
#define WW 512
#define NU 257
#define SU 260
#define NCH 16
#define NBATCH 8
#define IMGS (NBATCH*NCH)
#define GSTR 578

// Spectra stored as fp16x2 (re,im) packed in u32
__device__ uint32_t g_X[(size_t)IMGS * HH * SU];
__device__ uint32_t g_Y[(size_t)IMGS * HH * SU];

// h-reduction vectors and edge-correction tables (f32 — exact corrections)
__device__ float2 g_R0[IMGS * NU];
__device__ float2 g_R511[IMGS * NU];
__device__ float2 g_D0[IMGS * NU];
__device__ float2 g_D511[IMGS * NU];

#define B_U32 (3 * 2 * 12 * 64)        // 4608
__device__ uint32_t g_Bfrag[B_U32];

__device__ __forceinline__ float2 cmul(float2 a, float2 b) {
    return make_float2(a.x*b.x - a.y*b.y, a.x*b.y + a.y*b.x);
}
__device__ __forceinline__ float2 cadd(float2 a, float2 b) { return make_float2(a.x+b.x, a.y+b.y); }
__device__ __forceinline__ float2 csub(float2 a, float2 b) { return make_float2(a.x-b.x, a.y-b.y); }

__device__ __forceinline__ uint32_t packh(float x, float y) {
    __half2 h = __floats2half2_rn(x, y);
    uint32_t r;
    *(__half2*)&r = h;
    return r;
}
__device__ __forceinline__ float2 unpackh(uint32_t v) {
    __half2 h = *(__half2*)&v;
    return make_float2(__half2float(h.x), __half2float(h.y));
}

// ---------------- radix-8 register FFT ----------------
template<int S>
__device__ __forceinline__ void fft8(float2 a[8]) {
    const float r = 0.7071067811865476f;
    const float sf = (float)S;
    float2 d, u;
    u=a[0]; d=csub(u,a[4]); a[0]=cadd(u,a[4]); a[4]=d;
    u=a[1]; d=csub(u,a[5]); a[1]=cadd(u,a[5]); a[5]=make_float2(r*(d.x - sf*d.y), r*(sf*d.x + d.y));
    u=a[2]; d=csub(u,a[6]); a[2]=cadd(u,a[6]); a[6]=make_float2(-sf*d.y, sf*d.x);
    u=a[3]; d=csub(u,a[7]); a[3]=cadd(u,a[7]); a[7]=make_float2(r*(-d.x - sf*d.y), r*(sf*d.x - d.y));
    u=a[0]; d=csub(u,a[2]); a[0]=cadd(u,a[2]); a[2]=d;
    u=a[1]; d=csub(u,a[3]); a[1]=cadd(u,a[3]); a[3]=make_float2(-sf*d.y, sf*d.x);
    u=a[4]; d=csub(u,a[6]); a[4]=cadd(u,a[6]); a[6]=d;
    u=a[5]; d=csub(u,a[7]); a[5]=cadd(u,a[7]); a[7]=make_float2(-sf*d.y, sf*d.x);
    u=a[0]; a[0]=cadd(u,a[1]); a[1]=csub(u,a[1]);
    u=a[2]; a[2]=cadd(u,a[3]); a[3]=csub(u,a[3]);
    u=a[4]; a[4]=cadd(u,a[5]); a[5]=csub(u,a[5]);
    u=a[6]; a[6]=cadd(u,a[7]); a[7]=csub(u,a[7]);
    d=a[1]; a[1]=a[4]; a[4]=d;
    d=a[3]; a[3]=a[6]; a[6]=d;
}

template<int S>
__device__ __forceinline__ void fft512_regs(float2 a[8], int t, float2* s) {
    const float TWO_PI = 6.283185307179586f;
    const int n2 = t & 7;
    const int n1 = t >> 3;
    fft8<S>(a);
    const float c1 = (float)S * TWO_PI / 64.0f * (float)n1;
    #pragma unroll
    for (int k0 = 1; k0 < 8; ++k0) {
        float sn, cs; __sincosf(c1 * (float)k0, &sn, &cs);
        a[k0] = cmul(a[k0], make_float2(cs, sn));
    }
    #pragma unroll
    for (int k0 = 0; k0 < 8; ++k0) s[t + 72*k0] = a[k0];
    __syncthreads();
    const int k0r = t >> 3;
    #pragma unroll
    for (int j = 0; j < 8; ++j) a[j] = s[n2 + 8*j + 72*k0r];
    __syncthreads();
    fft8<S>(a);
    const float c2 = (float)S * TWO_PI / 512.0f * (float)n2;
    #pragma unroll
    for (int k1 = 0; k1 < 8; ++k1) {
        float sn, cs; __sincosf(c2 * (float)(k0r + 8*k1), &sn, &cs);
        a[k1] = cmul(a[k1], make_float2(cs, sn));
    }
    #pragma unroll
    for (int k1 = 0; k1 < 8; ++k1) s[72*k1 + 8*k0r + (n2 ^ k0r)] = a[k1];
    __syncthreads();
    const int k0b = t & 7, k1r = t >> 3;
    #pragma unroll
    for (int j = 0; j < 8; ++j) a[j] = s[72*k1r + 8*k0b + (j ^ k0b)];
    fft8<S>(a);
}

// ---------------- kSetup: zero R + build B fragments ----------------
__global__ __launch_bounds__(512) void kSetup(
    const float* __restrict__ w_real, const float* __restrict__ w_imag)
{
    const int e = blockIdx.x * 512 + threadIdx.x;
    if (e < IMGS * NU) {
        g_R0[e] = make_float2(0.f, 0.f);
        g_R511[e] = make_float2(0.f, 0.f);
    }
    if (e < B_U32) {
        const int within = e & 63;
        const int ln = within >> 1, rr = within & 1;
        const int tile = e >> 6;
        const int nt = tile % 12;
        const int bc = tile / 12;
        const int chunk = bc & 1, b = bc >> 1;
        const int a = nt >> 2;
        const int gg = ln >> 2, tt = ln & 3;
        const int n_idx = nt * 8 + gg;
        const int oc = n_idx & 31;
        const int o = oc >> 1, cout = oc & 1;
        float vals[2];
        #pragma unroll
        for (int q = 0; q < 2; ++q) {
            const int k = chunk * 16 + tt * 2 + rr * 8 + q;
            const int i = k >> 1;
            const int cin = k & 1;
            const float wr_ = w_real[(i * 16 + o) * 9 + a * 3 + b];
            const float wi_ = w_imag[(i * 16 + o) * 9 + a * 3 + b];
            vals[q] = cout ? (cin ? wr_ : wi_) : (cin ? -wi_ : wr_);
        }
        g_Bfrag[e] = packh(vals[0], vals[1]);
    }
}

// ---------------- kA: row rfft + R reductions ----------------
__global__ __launch_bounds__(512) void kA_rfft_rows(const float* __restrict__ x) {
    __shared__ float2 s[8 * GSTR];
    const int t = threadIdx.x & 63;
    const int g = threadIdx.x >> 6;
    const int img = blockIdx.x >> 5;
    const int pr = (blockIdx.x & 31) * 8 + g;
    const float* r0 = x + ((size_t)img * HH + 2 * pr) * WW;
    const float* r1 = r0 + WW;
    float2 a[8];
    #pragma unroll
    for (int m = 0; m < 8; ++m) a[m] = make_float2(r0[t + 64*m], r1[t + 64*m]);
    float2* z = s + g * GSTR;
    fft512_regs<-1>(a, t, z);
    __syncthreads();
    #pragma unroll
    for (int m = 0; m < 8; ++m) z[t + 64*m] = a[m];
    __syncthreads();

    float c0, s0, c1, s1;
    __sincosf(6.283185307179586f * (float)(2 * pr) / 512.0f, &s0, &c0);
    __sincosf(6.283185307179586f * (float)(2 * pr + 1) / 512.0f, &s1, &c1);

    uint32_t* X0 = g_X + ((size_t)img * HH + 2 * pr) * SU;
    uint32_t* X1 = X0 + SU;
    float2 rc0[5], rc5[5];
    #pragma unroll
    for (int m = 0; m < 5; ++m) {
        const int u = t + 64*m;
        if (u < NU) {
            const float2 zk = z[u];
            const float2 zm = z[(512 - u) & 511];
            const float2 A = make_float2(0.5f*(zk.x + zm.x),  0.5f*(zk.y - zm.y));
            const float2 B = make_float2(0.5f*(zk.y + zm.y), -0.5f*(zk.x - zm.x));
            X0[u] = packh(A.x, A.y);
            X1[u] = packh(B.x, B.y);
            rc0[m] = cadd(A, B);
            rc5[m] = make_float2(A.x*c0 - A.y*s0 + B.x*c1 - B.y*s1,
                                 A.x*s0 + A.y*c0 + B.x*s1 + B.y*c1);
        }
    }
    __syncthreads();
    #pragma unroll
    for (int m = 0; m < 5; ++m) {
        const int u = t + 64*m;
        if (u < NU) {
            z[u] = rc0[m];
            z[NU + u] = rc5[m];
        }
    }
    __syncthreads();
    for (int e = threadIdx.x; e < 2 * NU; e += 512) {
        float2 acc = make_float2(0.f, 0.f);
        #pragma unroll
        for (int gg = 0; gg < 8; ++gg) acc = cadd(acc, s[gg * GSTR + e]);
        if (e < NU) {
            atomicAdd(&g_R0[img * NU + e].x, acc.x);
            atomicAdd(&g_R0[img * NU + e].y, acc.y);
        } else {
            atomicAdd(&g_R511[img * NU + (e - NU)].x, acc.x);
            atomicAdd(&g_R511[img * NU + (e - NU)].y, acc.y);
        }
    }
}

// ---------------- kD0: edge-correction tables (smem-staged) ----------------
#define D0_CH 17     // u per chunk
#define D0_JW 19     // staged up-entries per channel
__global__ __launch_bounds__(512) void kD0_corr(
    const float* __restrict__ w_real, const float* __restrict__ w_imag)
{
    __shared__ float2 sR0[NCH][D0_JW + 1];
    __shared__ float2 sR5[NCH][D0_JW + 1];
    __shared__ float2 sW0[NCH * NCH * 3];
    __shared__ float2 sW2[NCH * NCH * 3];

    const int n = blockIdx.x;
    const int u0 = blockIdx.y * D0_CH;
    const int t = threadIdx.x;

    for (int e = t; e < NCH * D0_JW; e += 512) {
        const int i = e / D0_JW;
        const int j = e - i * D0_JW;
        const int up = u0 - 1 + j;
        float2 r0v = make_float2(0.f, 0.f), r5v = make_float2(0.f, 0.f);
        if (up >= 0 && up < NU) {
            r0v = g_R0[(n * NCH + i) * NU + up];
            r5v = g_R511[(n * NCH + i) * NU + up];
        }
        sR0[i][j] = r0v;
        sR5[i][j] = r5v;
    }
    for (int e = t; e < NCH * NCH * 3; e += 512) {
        const int b = e % 3;
        const int io = e / 3;
        const int wb = io * 9;
        sW0[e] = make_float2(w_real[wb + b], w_imag[wb + b]);
        sW2[e] = make_float2(w_real[wb + 6 + b], w_imag[wb + 6 + b]);
    }
    __syncthreads();

    const int o = t & 15;
    const int ui = t >> 4;            // 0..31 (only ui<17 useful)
    const int u = u0 + ui;
    if (ui < D0_CH && u < NU) {
        float2 d0 = make_float2(0.f, 0.f), d5 = make_float2(0.f, 0.f);
        #pragma unroll
        for (int i = 0; i < NCH; ++i) {
            #pragma unroll
            for (int b = 0; b < 3; ++b) {
                const int j = ui + 2 - b;
                const float2 r5 = sR5[i][j];
                const float2 r0 = sR0[i][j];
                const float2 w2 = sW2[(i * 16 + o) * 3 + b];
                const float2 w0 = sW0[(i * 16 + o) * 3 + b];
                d0 = csub(d0, cmul(w2, r5));
                d5 = csub(d5, cmul(w0, r0));
            }
        }
        g_D0[(n * NCH + o) * NU + u] = d0;
        g_D511[(n * NCH + o) * NU + u] = d5;
    }
}

// ===================== kC machinery =====================
#define APITCH 20
#define HALO_PTS (4 * 34)
#define A_U32 (HALO_PTS * APITCH)      // 2720
#define KC_SMEM ((A_U32 + B_U32) * 4)  // 29312 B

__device__ __forceinline__ uint32_t smem_u32(const void* p) {
    uint32_t a;
    asm("{ .reg .u64 t; cvta.to.shared.u64 t, %1; cvt.u32.u64 %0, t; }" : "=r"(a) : "l"(p));
    return a;
}
__device__ __forceinline__ void ldmA(uint32_t addr, uint32_t* a) {
    asm volatile("ldmatrix.sync.aligned.m8n8.x4.shared.b16 {%0,%1,%2,%3}, [%4];"
                 : "=r"(a[0]), "=r"(a[1]), "=r"(a[2]), "=r"(a[3]) : "r"(addr));
}
__device__ __forceinline__ void mma16816(float* d, const uint32_t* a,
                                         uint32_t b0, uint32_t b1) {
    asm volatile(
        "mma.sync.aligned.m16n8k16.row.col.f32.f16.f16.f32 "
        "{%0,%1,%2,%3}, {%4,%5,%6,%7}, {%8,%9}, {%0,%1,%2,%3};"
        : "+f"(d[0]), "+f"(d[1]), "+f"(d[2]), "+f"(d[3])
        : "r"(a[0]), "r"(a[1]), "r"(a[2]), "r"(a[3]), "r"(b0), "r"(b1));
}

__global__ __launch_bounds__(512, 2) void kC_conv_mma(
    const float* __restrict__ b_real, const float* __restrict__ b_imag)
{
    extern __shared__ uint32_t smc[];
    uint32_t* sA = smc;
    uint32_t* sB = smc + A_U32;

    const int t = threadIdx.x;
    const int w = t >> 5;
    const int lane = t & 31;
    const int g = lane >> 2;
    const int th = lane & 3;
    const int ubase = blockIdx.x * 32;
    const int h0 = blockIdx.y * 4;
    const int n = blockIdx.z;
    const int l = w >> 2;
    const int usub = (w >> 1) & 1;
    const int oh = w & 1;

    // B stage
    {
        const uint4* src = (const uint4*)g_Bfrag;
        uint4* dst = (uint4*)sB;
        #pragma unroll
        for (int e = t; e < B_U32 / 4; e += 512) dst[e] = src[e];
    }
    // A fill: direct fp16x2 copy
    for (int e = t; e < HALO_PTS * NCH; e += 512) {
        const int i = e / HALO_PTS;
        const int p = e - i * HALO_PTS;
        const int hr = p / 34;
        const int c = p - hr * 34;
        const int h = h0 + hr;
        const int u = ubase - 1 + c;
        uint32_t v = 0;
        if (u >= 0 && u < NU)
            v = g_X[(((size_t)n * NCH + i) * HH + h) * SU + u];
        sA[p * APITCH + i] = v;
    }
    __syncthreads();

    const uint32_t sAb = smem_u32(sA);

    float acc[6][4];
    #pragma unroll
    for (int q = 0; q < 6; ++q)
        #pragma unroll
        for (int j = 0; j < 4; ++j) acc[q][j] = 0.f;

    const int lrow = (lane & 7) + ((lane >> 3) & 1) * 8;
    const int lkof = (lane >> 4) * 4;

    #pragma unroll
    for (int b = 0; b < 3; ++b) {
        const int prow = l * 34 + (2 - b) + usub * 16;
        const uint32_t ab = sAb + (uint32_t)(((prow + lrow) * APITCH) + lkof) * 4u;
        uint32_t A0[4], A1[4];
        ldmA(ab, A0);
        ldmA(ab + 32, A1);
        #pragma unroll
        for (int chunk = 0; chunk < 2; ++chunk) {
            const uint32_t* Af = chunk ? A1 : A0;
            const int cb = (b * 2 + chunk) * 768 + lane * 2;
            #pragma unroll
            for (int ntl = 0; ntl < 6; ++ntl) {
                const int a = ntl >> 1, og2 = ntl & 1;
                const int ntg = a * 4 + oh * 2 + og2;
                const uint2 bv = *(const uint2*)(sB + cb + ntg * 64);
                mma16816(acc[ntl], Af, bv.x, bv.y);
            }
        }
    }

    // epilogue: phase-combine a-taps + bias at h==0; corrections moved to kE
    const int h = h0 + l;
    float sn, cs;
    __sincosf(6.283185307179586f * (float)h / 512.0f, &sn, &cs);

    #pragma unroll
    for (int og2 = 0; og2 < 2; ++og2) {
        const int o = oh * 8 + og2 * 4 + th;
        uint32_t* Yrow = g_Y + (((size_t)n * NCH + o) * HH + h) * SU;
        #pragma unroll
        for (int q2 = 0; q2 < 2; ++q2) {
            const int u = ubase + usub * 16 + g + q2 * 8;
            if (u < NU) {
                const float Z0re = acc[0 + og2][q2*2], Z0im = acc[0 + og2][q2*2+1];
                const float Z1re = acc[2 + og2][q2*2], Z1im = acc[2 + og2][q2*2+1];
                const float Z2re = acc[4 + og2][q2*2], Z2im = acc[4 + og2][q2*2+1];
                float Yre = Z1re + (cs*Z0re + sn*Z0im) + (cs*Z2re - sn*Z2im);
                float Yim = Z1im + (cs*Z0im - sn*Z0re) + (cs*Z2im + sn*Z2re);
                if (h == 0) {
                    Yre += __ldg(b_real + o);
                    Yim += __ldg(b_imag + o);
                }
                Yrow[u] = packh(Yre, Yim);
            }
        }
    }
}

// ---------------- kE: row irfft with edge corrections ----------------
__global__ __launch_bounds__(512) void kE_irfft_rows(float* __restrict__ out) {
    __shared__ float2 s[8 * GSTR];
    const int t = threadIdx.x & 63;
    const int g = threadIdx.x >> 6;
    const int img = blockIdx.x >> 5;
    const int pr = (blockIdx.x & 31) * 8 + g;
    const float sc = 1.0f / 512.0f;
    const float inv512 = 1.0f / 512.0f;
    const uint32_t* G0 = g_Y + ((size_t)img * HH + 2 * pr) * SU;
    const uint32_t* G1 = G0 + SU;
    const float2* Dr0 = g_D0 + img * NU;
    const float2* Dr5 = g_D511 + img * NU;

    // correction phases e^{-i 2pi h/512} for h = 2pr, 2pr+1
    float c0, s0, c1, s1;
    __sincosf(6.283185307179586f * (float)(2 * pr) / 512.0f, &s0, &c0);
    __sincosf(6.283185307179586f * (float)(2 * pr + 1) / 512.0f, &s1, &c1);

    float2* z = s + g * GSTR;
    #pragma unroll
    for (int m = 0; m < 5; ++m) {
        const int u = t + 64*m;
        if (u < NU) {
            float2 A = unpackh(G0[u]);
            float2 B = unpackh(G1[u]);
            const float2 d0 = Dr0[u];
            const float2 d5 = Dr5[u];
            A.x += inv512 * (d0.x + c0*d5.x + s0*d5.y);
            A.y += inv512 * (d0.y + c0*d5.y - s0*d5.x);
            B.x += inv512 * (d0.x + c1*d5.x + s1*d5.y);
            B.y += inv512 * (d0.y + c1*d5.y - s1*d5.x);
            A.x *= sc; A.y *= sc; B.x *= sc; B.y *= sc;
            if (u == 0 || u == 256) { A.y = 0.f; B.y = 0.f; }
            z[u] = make_float2(A.x - B.y, A.y + B.x);
            if (u >= 1 && u <= 255)
                z[512 - u] = make_float2(A.x + B.y, B.x - A.y);
        }
    }
    __syncthreads();
    float2 a[8];
    #pragma unroll
    for (int m = 0; m < 8; ++m) a[m] = z[t + 64*m];
    __syncthreads();
    fft512_regs<+1>(a, t, z);
    float* o0 = out + ((size_t)img * HH + 2 * pr) * WW;
    float* o1 = o0 + WW;
    #pragma unroll
    for (int m = 0; m < 8; ++m) {
        o0[t + 64*m] = a[m].x;
        o1[t + 64*m] = a[m].y;
    }
}

extern "C" void kernel_launch(void* const* d_in, const int* in_sizes, int n_in,
                              void* d_out, int out_size) {
    const float* x      = (const float*)d_in[0];
    const float* w_real = (const float*)d_in[1];
    const float* w_imag = (const float*)d_in[2];
    const float* b_real = (const float*)d_in[3];
    const float* b_imag = (const float*)d_in[4];
    float* out = (float*)d_out;

    cudaFuncSetAttribute(kC_conv_mma, cudaFuncAttributeMaxDynamicSharedMemorySize, KC_SMEM);

    kSetup<<<(IMGS * NU + 511) / 512, 512>>>(w_real, w_imag);

    kA_rfft_rows<<<IMGS * 32, 512>>>(x);

    dim3 gD(NBATCH, (NU + D0_CH - 1) / D0_CH);
    kD0_corr<<<gD, 512>>>(w_real, w_imag);

    dim3 gC(9, HH / 4, NBATCH);
    kC_conv_mma<<<gC, 512, KC_SMEM>>>(b_real, b_imag);

    kE_irfft_rows<<<IMGS * 32, 512>>>(out);
}

// round 17
// speedup vs baseline: 2.9071x; 1.0075x over previous
#include <cuda_runtime.h>
#include <cuda_fp16.h>
#include <cstdint>

#define HH 512
#define WW 512
#define NU 257
#define SU 260
#define NCH 16
#define NBATCH 8
#define IMGS (NBATCH*NCH)
#define GSTR 578

// Spectra stored as fp16x2 (re,im) packed in u32
__device__ uint32_t g_X[(size_t)IMGS * HH * SU];
__device__ uint32_t g_Y[(size_t)IMGS * HH * SU];

// h-reduction vectors and edge-correction tables (f32 — exact corrections)
__device__ float2 g_R0[IMGS * NU];
__device__ float2 g_R511[IMGS * NU];
__device__ float2 g_D0[IMGS * NU];
__device__ float2 g_D511[IMGS * NU];

#define B_U32 (3 * 2 * 12 * 64)        // 4608
__device__ uint32_t g_Bfrag[B_U32];

__device__ __forceinline__ float2 cmul(float2 a, float2 b) {
    return make_float2(a.x*b.x - a.y*b.y, a.x*b.y + a.y*b.x);
}
__device__ __forceinline__ float2 cadd(float2 a, float2 b) { return make_float2(a.x+b.x, a.y+b.y); }
__device__ __forceinline__ float2 csub(float2 a, float2 b) { return make_float2(a.x-b.x, a.y-b.y); }

__device__ __forceinline__ uint32_t packh(float x, float y) {
    __half2 h = __floats2half2_rn(x, y);
    uint32_t r;
    *(__half2*)&r = h;
    return r;
}
__device__ __forceinline__ float2 unpackh(uint32_t v) {
    __half2 h = *(__half2*)&v;
    return make_float2(__half2float(h.x), __half2float(h.y));
}

// ---------------- radix-8 register FFT ----------------
template<int S>
__device__ __forceinline__ void fft8(float2 a[8]) {
    const float r = 0.7071067811865476f;
    const float sf = (float)S;
    float2 d, u;
    u=a[0]; d=csub(u,a[4]); a[0]=cadd(u,a[4]); a[4]=d;
    u=a[1]; d=csub(u,a[5]); a[1]=cadd(u,a[5]); a[5]=make_float2(r*(d.x - sf*d.y), r*(sf*d.x + d.y));
    u=a[2]; d=csub(u,a[6]); a[2]=cadd(u,a[6]); a[6]=make_float2(-sf*d.y, sf*d.x);
    u=a[3]; d=csub(u,a[7]); a[3]=cadd(u,a[7]); a[7]=make_float2(r*(-d.x - sf*d.y), r*(sf*d.x - d.y));
    u=a[0]; d=csub(u,a[2]); a[0]=cadd(u,a[2]); a[2]=d;
    u=a[1]; d=csub(u,a[3]); a[1]=cadd(u,a[3]); a[3]=make_float2(-sf*d.y, sf*d.x);
    u=a[4]; d=csub(u,a[6]); a[4]=cadd(u,a[6]); a[6]=d;
    u=a[5]; d=csub(u,a[7]); a[5]=cadd(u,a[7]); a[7]=make_float2(-sf*d.y, sf*d.x);
    u=a[0]; a[0]=cadd(u,a[1]); a[1]=csub(u,a[1]);
    u=a[2]; a[2]=cadd(u,a[3]); a[3]=csub(u,a[3]);
    u=a[4]; a[4]=cadd(u,a[5]); a[5]=csub(u,a[5]);
    u=a[6]; a[6]=cadd(u,a[7]); a[7]=csub(u,a[7]);
    d=a[1]; a[1]=a[4]; a[4]=d;
    d=a[3]; a[3]=a[6]; a[6]=d;
}

template<int S>
__device__ __forceinline__ void fft512_regs(float2 a[8], int t, float2* s) {
    const float TWO_PI = 6.283185307179586f;
    const int n2 = t & 7;
    const int n1 = t >> 3;
    fft8<S>(a);
    const float c1 = (float)S * TWO_PI / 64.0f * (float)n1;
    #pragma unroll
    for (int k0 = 1; k0 < 8; ++k0) {
        float sn, cs; __sincosf(c1 * (float)k0, &sn, &cs);
        a[k0] = cmul(a[k0], make_float2(cs, sn));
    }
    #pragma unroll
    for (int k0 = 0; k0 < 8; ++k0) s[t + 72*k0] = a[k0];
    __syncthreads();
    const int k0r = t >> 3;
    #pragma unroll
    for (int j = 0; j < 8; ++j) a[j] = s[n2 + 8*j + 72*k0r];
    __syncthreads();
    fft8<S>(a);
    const float c2 = (float)S * TWO_PI / 512.0f * (float)n2;
    #pragma unroll
    for (int k1 = 0; k1 < 8; ++k1) {
        float sn, cs; __sincosf(c2 * (float)(k0r + 8*k1), &sn, &cs);
        a[k1] = cmul(a[k1], make_float2(cs, sn));
    }
    #pragma unroll
    for (int k1 = 0; k1 < 8; ++k1) s[72*k1 + 8*k0r + (n2 ^ k0r)] = a[k1];
    __syncthreads();
    const int k0b = t & 7, k1r = t >> 3;
    #pragma unroll
    for (int j = 0; j < 8; ++j) a[j] = s[72*k1r + 8*k0b + (j ^ k0b)];
    fft8<S>(a);
}

// ---------------- kSetup: zero R + build B fragments ----------------
__global__ __launch_bounds__(512) void kSetup(
    const float* __restrict__ w_real, const float* __restrict__ w_imag)
{
    const int e = blockIdx.x * 512 + threadIdx.x;
    if (e < IMGS * NU) {
        g_R0[e] = make_float2(0.f, 0.f);
        g_R511[e] = make_float2(0.f, 0.f);
    }
    if (e < B_U32) {
        const int within = e & 63;
        const int ln = within >> 1, rr = within & 1;
        const int tile = e >> 6;
        const int nt = tile % 12;
        const int bc = tile / 12;
        const int chunk = bc & 1, b = bc >> 1;
        const int a = nt >> 2;
        const int gg = ln >> 2, tt = ln & 3;
        const int n_idx = nt * 8 + gg;
        const int oc = n_idx & 31;
        const int o = oc >> 1, cout = oc & 1;
        float vals[2];
        #pragma unroll
        for (int q = 0; q < 2; ++q) {
            const int k = chunk * 16 + tt * 2 + rr * 8 + q;
            const int i = k >> 1;
            const int cin = k & 1;
            const float wr_ = w_real[(i * 16 + o) * 9 + a * 3 + b];
            const float wi_ = w_imag[(i * 16 + o) * 9 + a * 3 + b];
            vals[q] = cout ? (cin ? wr_ : wi_) : (cin ? -wi_ : wr_);
        }
        g_Bfrag[e] = packh(vals[0], vals[1]);
    }
}

// ---------------- kA: row rfft + R reductions ----------------
__global__ __launch_bounds__(512) void kA_rfft_rows(const float* __restrict__ x) {
    __shared__ float2 s[8 * GSTR];
    const int t = threadIdx.x & 63;
    const int g = threadIdx.x >> 6;
    const int img = blockIdx.x >> 5;
    const int pr = (blockIdx.x & 31) * 8 + g;
    const float* r0 = x + ((size_t)img * HH + 2 * pr) * WW;
    const float* r1 = r0 + WW;
    float2 a[8];
    #pragma unroll
    for (int m = 0; m < 8; ++m) a[m] = make_float2(r0[t + 64*m], r1[t + 64*m]);
    float2* z = s + g * GSTR;
    fft512_regs<-1>(a, t, z);
    __syncthreads();
    #pragma unroll
    for (int m = 0; m < 8; ++m) z[t + 64*m] = a[m];
    __syncthreads();

    float c0, s0, c1, s1;
    __sincosf(6.283185307179586f * (float)(2 * pr) / 512.0f, &s0, &c0);
    __sincosf(6.283185307179586f * (float)(2 * pr + 1) / 512.0f, &s1, &c1);

    uint32_t* X0 = g_X + ((size_t)img * HH + 2 * pr) * SU;
    uint32_t* X1 = X0 + SU;
    float2 rc0[5], rc5[5];
    #pragma unroll
    for (int m = 0; m < 5; ++m) {
        const int u = t + 64*m;
        if (u < NU) {
            const float2 zk = z[u];
            const float2 zm = z[(512 - u) & 511];
            const float2 A = make_float2(0.5f*(zk.x + zm.x),  0.5f*(zk.y - zm.y));
            const float2 B = make_float2(0.5f*(zk.y + zm.y), -0.5f*(zk.x - zm.x));
            X0[u] = packh(A.x, A.y);
            X1[u] = packh(B.x, B.y);
            rc0[m] = cadd(A, B);
            rc5[m] = make_float2(A.x*c0 - A.y*s0 + B.x*c1 - B.y*s1,
                                 A.x*s0 + A.y*c0 + B.x*s1 + B.y*c1);
        }
    }
    __syncthreads();
    #pragma unroll
    for (int m = 0; m < 5; ++m) {
        const int u = t + 64*m;
        if (u < NU) {
            z[u] = rc0[m];
            z[NU + u] = rc5[m];
        }
    }
    __syncthreads();
    for (int e = threadIdx.x; e < 2 * NU; e += 512) {
        float2 acc = make_float2(0.f, 0.f);
        #pragma unroll
        for (int gg = 0; gg < 8; ++gg) acc = cadd(acc, s[gg * GSTR + e]);
        if (e < NU) {
            atomicAdd(&g_R0[img * NU + e].x, acc.x);
            atomicAdd(&g_R0[img * NU + e].y, acc.y);
        } else {
            atomicAdd(&g_R511[img * NU + (e - NU)].x, acc.x);
            atomicAdd(&g_R511[img * NU + (e - NU)].y, acc.y);
        }
    }
}

// ---------------- kD0: edge-correction tables (smem-staged) ----------------
#define D0_CH 17
#define D0_JW 19
__global__ __launch_bounds__(512) void kD0_corr(
    const float* __restrict__ w_real, const float* __restrict__ w_imag)
{
    __shared__ float2 sR0[NCH][D0_JW + 1];
    __shared__ float2 sR5[NCH][D0_JW + 1];
    __shared__ float2 sW0[NCH * NCH * 3];
    __shared__ float2 sW2[NCH * NCH * 3];

    const int n = blockIdx.x;
    const int u0 = blockIdx.y * D0_CH;
    const int t = threadIdx.x;

    for (int e = t; e < NCH * D0_JW; e += 512) {
        const int i = e / D0_JW;
        const int j = e - i * D0_JW;
        const int up = u0 - 1 + j;
        float2 r0v = make_float2(0.f, 0.f), r5v = make_float2(0.f, 0.f);
        if (up >= 0 && up < NU) {
            r0v = g_R0[(n * NCH + i) * NU + up];
            r5v = g_R511[(n * NCH + i) * NU + up];
        }
        sR0[i][j] = r0v;
        sR5[i][j] = r5v;
    }
    for (int e = t; e < NCH * NCH * 3; e += 512) {
        const int b = e % 3;
        const int io = e / 3;
        const int wb = io * 9;
        sW0[e] = make_float2(w_real[wb + b], w_imag[wb + b]);
        sW2[e] = make_float2(w_real[wb + 6 + b], w_imag[wb + 6 + b]);
    }
    __syncthreads();

    const int o = t & 15;
    const int ui = t >> 4;
    const int u = u0 + ui;
    if (ui < D0_CH && u < NU) {
        float2 d0 = make_float2(0.f, 0.f), d5 = make_float2(0.f, 0.f);
        #pragma unroll
        for (int i = 0; i < NCH; ++i) {
            #pragma unroll
            for (int b = 0; b < 3; ++b) {
                const int j = ui + 2 - b;
                const float2 r5 = sR5[i][j];
                const float2 r0 = sR0[i][j];
                const float2 w2 = sW2[(i * 16 + o) * 3 + b];
                const float2 w0 = sW0[(i * 16 + o) * 3 + b];
                d0 = csub(d0, cmul(w2, r5));
                d5 = csub(d5, cmul(w0, r0));
            }
        }
        g_D0[(n * NCH + o) * NU + u] = d0;
        g_D511[(n * NCH + o) * NU + u] = d5;
    }
}

// ===================== kC machinery =====================
#define APITCH 20
#define HALO_PTS (4 * 34)
#define A_U32 (HALO_PTS * APITCH)      // 2720
#define KC_SMEM ((A_U32 + B_U32) * 4)  // 29312 B

__device__ __forceinline__ uint32_t smem_u32(const void* p) {
    uint32_t a;
    asm("{ .reg .u64 t; cvta.to.shared.u64 t, %1; cvt.u32.u64 %0, t; }" : "=r"(a) : "l"(p));
    return a;
}
__device__ __forceinline__ void ldmA(uint32_t addr, uint32_t* a) {
    asm volatile("ldmatrix.sync.aligned.m8n8.x4.shared.b16 {%0,%1,%2,%3}, [%4];"
                 : "=r"(a[0]), "=r"(a[1]), "=r"(a[2]), "=r"(a[3]) : "r"(addr));
}
__device__ __forceinline__ void mma16816(float* d, const uint32_t* a,
                                         uint32_t b0, uint32_t b1) {
    asm volatile(
        "mma.sync.aligned.m16n8k16.row.col.f32.f16.f16.f32 "
        "{%0,%1,%2,%3}, {%4,%5,%6,%7}, {%8,%9}, {%0,%1,%2,%3};"
        : "+f"(d[0]), "+f"(d[1]), "+f"(d[2]), "+f"(d[3])
        : "r"(a[0]), "r"(a[1]), "r"(a[2]), "r"(a[3]), "r"(b0), "r"(b1));
}

// 256 threads = 8 warps: warp = (l, oh). Each warp owns BOTH usub M-tiles,
// reusing its B fragments across the two ldmatrix/MMA sets (B traffic /2).
__global__ __launch_bounds__(256) void kC_conv_mma(
    const float* __restrict__ b_real, const float* __restrict__ b_imag)
{
    extern __shared__ uint32_t smc[];
    uint32_t* sA = smc;
    uint32_t* sB = smc + A_U32;

    const int t = threadIdx.x;
    const int w = t >> 5;
    const int lane = t & 31;
    const int g = lane >> 2;
    const int th = lane & 3;
    const int ubase = blockIdx.x * 32;
    const int h0 = blockIdx.y * 4;
    const int n = blockIdx.z;
    const int l = w >> 1;          // h-line (0..3)
    const int oh = w & 1;          // out-channel half

    // B stage
    {
        const uint4* src = (const uint4*)g_Bfrag;
        uint4* dst = (uint4*)sB;
        #pragma unroll
        for (int e = t; e < B_U32 / 4; e += 256) dst[e] = src[e];
    }
    // A fill: direct fp16x2 copy
    for (int e = t; e < HALO_PTS * NCH; e += 256) {
        const int i = e / HALO_PTS;
        const int p = e - i * HALO_PTS;
        const int hr = p / 34;
        const int c = p - hr * 34;
        const int h = h0 + hr;
        const int u = ubase - 1 + c;
        uint32_t v = 0;
        if (u >= 0 && u < NU)
            v = g_X[(((size_t)n * NCH + i) * HH + h) * SU + u];
        sA[p * APITCH + i] = v;
    }
    __syncthreads();

    const uint32_t sAb = smem_u32(sA);

    float acc[2][6][4];    // [usub][ntl = a*2+og2][frag]
    #pragma unroll
    for (int us = 0; us < 2; ++us)
        #pragma unroll
        for (int q = 0; q < 6; ++q)
            #pragma unroll
            for (int j = 0; j < 4; ++j) acc[us][q][j] = 0.f;

    const int lrow = (lane & 7) + ((lane >> 3) & 1) * 8;
    const int lkof = (lane >> 4) * 4;

    #pragma unroll
    for (int b = 0; b < 3; ++b) {
        const int prow = l * 34 + (2 - b);
        const uint32_t ab0 = sAb + (uint32_t)(((prow + lrow) * APITCH) + lkof) * 4u;
        const uint32_t ab1 = ab0 + 16u * APITCH * 4u;   // usub=1 M-tile
        #pragma unroll
        for (int chunk = 0; chunk < 2; ++chunk) {
            uint2 bb[6];
            const int cb = (b * 2 + chunk) * 768 + lane * 2;
            #pragma unroll
            for (int ntl = 0; ntl < 6; ++ntl) {
                const int a = ntl >> 1, og2 = ntl & 1;
                const int ntg = a * 4 + oh * 2 + og2;
                bb[ntl] = *(const uint2*)(sB + cb + ntg * 64);
            }
            uint32_t Af[4];
            ldmA(ab0 + chunk * 32u, Af);
            #pragma unroll
            for (int ntl = 0; ntl < 6; ++ntl)
                mma16816(acc[0][ntl], Af, bb[ntl].x, bb[ntl].y);
            ldmA(ab1 + chunk * 32u, Af);
            #pragma unroll
            for (int ntl = 0; ntl < 6; ++ntl)
                mma16816(acc[1][ntl], Af, bb[ntl].x, bb[ntl].y);
        }
    }

    // epilogue: phase-combine a-taps + bias at h==0
    const int h = h0 + l;
    float sn, cs;
    __sincosf(6.283185307179586f * (float)h / 512.0f, &sn, &cs);

    #pragma unroll
    for (int us = 0; us < 2; ++us) {
        #pragma unroll
        for (int og2 = 0; og2 < 2; ++og2) {
            const int o = oh * 8 + og2 * 4 + th;
            uint32_t* Yrow = g_Y + (((size_t)n * NCH + o) * HH + h) * SU;
            #pragma unroll
            for (int q2 = 0; q2 < 2; ++q2) {
                const int u = ubase + us * 16 + g + q2 * 8;
                if (u < NU) {
                    const float Z0re = acc[us][0 + og2][q2*2], Z0im = acc[us][0 + og2][q2*2+1];
                    const float Z1re = acc[us][2 + og2][q2*2], Z1im = acc[us][2 + og2][q2*2+1];
                    const float Z2re = acc[us][4 + og2][q2*2], Z2im = acc[us][4 + og2][q2*2+1];
                    float Yre = Z1re + (cs*Z0re + sn*Z0im) + (cs*Z2re - sn*Z2im);
                    float Yim = Z1im + (cs*Z0im - sn*Z0re) + (cs*Z2im + sn*Z2re);
                    if (h == 0) {
                        Yre += __ldg(b_real + o);
                        Yim += __ldg(b_imag + o);
                    }
                    Yrow[u] = packh(Yre, Yim);
                }
            }
        }
    }
}

// ---------------- kE: row irfft with edge corrections ----------------
__global__ __launch_bounds__(512) void kE_irfft_rows(float* __restrict__ out) {
    __shared__ float2 s[8 * GSTR];
    const int t = threadIdx.x & 63;
    const int g = threadIdx.x >> 6;
    const int img = blockIdx.x >> 5;
    const int pr = (blockIdx.x & 31) * 8 + g;
    const float sc = 1.0f / 512.0f;
    const float inv512 = 1.0f / 512.0f;
    const uint32_t* G0 = g_Y + ((size_t)img * HH + 2 * pr) * SU;
    const uint32_t* G1 = G0 + SU;
    const float2* Dr0 = g_D0 + img * NU;
    const float2* Dr5 = g_D511 + img * NU;

    float c0, s0, c1, s1;
    __sincosf(6.283185307179586f * (float)(2 * pr) / 512.0f, &s0, &c0);
    __sincosf(6.283185307179586f * (float)(2 * pr + 1) / 512.0f, &s1, &c1);

    float2* z = s + g * GSTR;
    #pragma unroll
    for (int m = 0; m < 5; ++m) {
        const int u = t + 64*m;
        if (u < NU) {
            float2 A = unpackh(G0[u]);
            float2 B = unpackh(G1[u]);
            const float2 d0 = Dr0[u];
            const float2 d5 = Dr5[u];
            A.x += inv512 * (d0.x + c0*d5.x + s0*d5.y);
            A.y += inv512 * (d0.y + c0*d5.y - s0*d5.x);
            B.x += inv512 * (d0.x + c1*d5.x + s1*d5.y);
            B.y += inv512 * (d0.y + c1*d5.y - s1*d5.x);
            A.x *= sc; A.y *= sc; B.x *= sc; B.y *= sc;
            if (u == 0 || u == 256) { A.y = 0.f; B.y = 0.f; }
            z[u] = make_float2(A.x - B.y, A.y + B.x);
            if (u >= 1 && u <= 255)
                z[512 - u] = make_float2(A.x + B.y, B.x - A.y);
        }
    }
    __syncthreads();
    float2 a[8];
    #pragma unroll
    for (int m = 0; m < 8; ++m) a[m] = z[t + 64*m];
    __syncthreads();
    fft512_regs<+1>(a, t, z);
    float* o0 = out + ((size_t)img * HH + 2 * pr) * WW;
    float* o1 = o0 + WW;
    #pragma unroll
    for (int m = 0; m < 8; ++m) {
        o0[t + 64*m] = a[m].x;
        o1[t + 64*m] = a[m].y;
    }
}

extern "C" void kernel_launch(void* const* d_in, const int* in_sizes, int n_in,
                              void* d_out, int out_size) {
    const float* x      = (const float*)d_in[0];
    const float* w_real = (const float*)d_in[1];
    const float* w_imag = (const float*)d_in[2];
    const float* b_real = (const float*)d_in[3];
    const float* b_imag = (const float*)d_in[4];
    float* out = (float*)d_out;

    cudaFuncSetAttribute(kC_conv_mma, cudaFuncAttributeMaxDynamicSharedMemorySize, KC_SMEM);

    kSetup<<<(IMGS * NU + 511) / 512, 512>>>(w_real, w_imag);

    kA_rfft_rows<<<IMGS * 32, 512>>>(x);

    dim3 gD(NBATCH, (NU + D0_CH - 1) / D0_CH);
    kD0_corr<<<gD, 512>>>(w_real, w_imag);

    dim3 gC(9, HH / 4, NBATCH);
    kC_conv_mma<<<gC, 256, KC_SMEM>>>(b_real, b_imag);

    kE_irfft_rows<<<IMGS * 32, 512>>>(out);
}